// round 10
// baseline (speedup 1.0000x reference)
#include <cuda_runtime.h>
#include <cuda_bf16.h>
#include <cstdint>
#include <float.h>

// ---------------- problem constants ----------------
#define BDIM 4
#define SDIM 4096
#define HDIM 1024
#define PDIM 4096
#define DDIM 512
#define NTOK (BDIM * SDIM)          // 16384
#define INTER_DIM 1024
#define NDIL 3

// ---------------- scratch (device globals; no allocs allowed) ----------------
__device__ float g_inter[NTOK * INTER_DIM];         // near-exact fp32 (rescore)
__device__ __nv_bfloat16 g_logitsb[(size_t)NTOK * PDIM]; // bf16 screen logits
__device__ float g_concat[(size_t)NTOK * 3 * HDIM]; // tf32-rounded GELU out
__device__ float g_local[NTOK * HDIM];
__device__ float g_combined[NTOK * 2 * DDIM];       // tf32-rounded
__device__ float g_transf[NTOK * DDIM];             // tf32-rounded
__device__ float g_global[NTOK * HDIM];
__device__ float g_proj[NTOK * DDIM];
__device__ float g_convwt[NDIL * 3 * HDIM * HDIM];  // repacked + tf32-rounded
__device__ float g_usage[PDIM];
// pre-rounded tf32 operands (continuous paths)
__device__ float g_xt[NTOK * HDIM];                 // tf32(x)
__device__ float g_wprojt[DDIM * HDIM];
__device__ float g_woutt[HDIM * 3 * HDIM];
__device__ float g_wmapt[DDIM * 2 * DDIM];
__device__ float g_wrpt[HDIM * DDIM];
// bf16 router operands
__device__ __nv_bfloat16 g_xhb[NTOK * HDIM];        // hi(x) bf16
__device__ __nv_bfloat16 g_xlb[NTOK * HDIM];        // lo(x) bf16
__device__ __nv_bfloat16 g_w1hb[INTER_DIM * HDIM];
__device__ __nv_bfloat16 g_w1lb[INTER_DIM * HDIM];
__device__ __nv_bfloat16 g_w2b[(size_t)PDIM * INTER_DIM];
__device__ __nv_bfloat16 g_interb[NTOK * INTER_DIM];// bf16(inter) (logits A)

// ---------------- helpers ----------------
__device__ __forceinline__ float block_reduce_sum(float v, float* sh) {
    int tid = threadIdx.x;
    #pragma unroll
    for (int o = 16; o; o >>= 1) v += __shfl_xor_sync(0xffffffffu, v, o);
    if ((tid & 31) == 0) sh[tid >> 5] = v;
    __syncthreads();
    int nw = blockDim.x >> 5;
    float r = (tid < nw) ? sh[tid] : 0.f;
    if (tid < 32) {
        #pragma unroll
        for (int o = 16; o; o >>= 1) r += __shfl_xor_sync(0xffffffffu, r, o);
        if (tid == 0) sh[32] = r;
    }
    __syncthreads();
    float total = sh[32];
    __syncthreads();
    return total;
}

__device__ __forceinline__ unsigned cvt_tf32(float x) {
    unsigned r;
    asm("cvt.rna.tf32.f32 %0, %1;" : "=r"(r) : "f"(x));
    return r;
}
__device__ __forceinline__ float round_tf32f(float x) {
    return __uint_as_float(cvt_tf32(x));
}

__device__ __forceinline__ void mma_tf32(float* c, const unsigned* a, const unsigned* b) {
    asm volatile(
        "mma.sync.aligned.m16n8k8.row.col.f32.tf32.tf32.f32 "
        "{%0,%1,%2,%3}, {%4,%5,%6,%7}, {%8,%9}, {%0,%1,%2,%3};\n"
        : "+f"(c[0]), "+f"(c[1]), "+f"(c[2]), "+f"(c[3])
        : "r"(a[0]), "r"(a[1]), "r"(a[2]), "r"(a[3]), "r"(b[0]), "r"(b[1]));
}

__device__ __forceinline__ void mma_bf16(float* c, const unsigned* a, const unsigned* b) {
    asm volatile(
        "mma.sync.aligned.m16n8k16.row.col.f32.bf16.bf16.f32 "
        "{%0,%1,%2,%3}, {%4,%5,%6,%7}, {%8,%9}, {%0,%1,%2,%3};\n"
        : "+f"(c[0]), "+f"(c[1]), "+f"(c[2]), "+f"(c[3])
        : "r"(a[0]), "r"(a[1]), "r"(a[2]), "r"(a[3]), "r"(b[0]), "r"(b[1]));
}

__device__ __forceinline__ void ldsm_x4(unsigned addr, unsigned& r0, unsigned& r1,
                                        unsigned& r2, unsigned& r3) {
    asm volatile("ldmatrix.sync.aligned.m8n8.x4.shared.b16 {%0,%1,%2,%3}, [%4];"
                 : "=r"(r0), "=r"(r1), "=r"(r2), "=r"(r3) : "r"(addr));
}

__device__ __forceinline__ void cp16(void* dst_smem, const void* src, bool pred) {
    unsigned d = (unsigned)__cvta_generic_to_shared(dst_smem);
    int sz = pred ? 16 : 0;
    asm volatile("cp.async.cg.shared.global [%0], [%1], 16, %2;\n"
                 :: "r"(d), "l"(src), "r"(sz));
}
#define CP_COMMIT() asm volatile("cp.async.commit_group;\n" ::)
#define CP_WAIT1()  asm volatile("cp.async.wait_group 1;\n" ::)

// =====================================================================
// TF32 GEMM, BM=256 x BN=128, 512 threads (16 warps, 4x4, warp 64x32),
// BK=32, cp.async 3-stage, one __syncthreads per chunk.
// MODE 0: plain. MODE 1: conv virtual im2col, blockIdx.z = dilation idx.
// =====================================================================
#define TFPAD 36

template<int MODE>
__global__ void __launch_bounds__(512, 1) gemm_tf32(
    const float* __restrict__ A, const float* __restrict__ W,
    const float* __restrict__ bias, float* __restrict__ C,
    int K, int ldc, int coff, int act, int roundC)
{
    extern __shared__ float smem[];
    float* As = smem;                      // [3][256][TFPAD]
    float* Bs = smem + 3 * 256 * TFPAD;    // [3][128][TFPAD]

    int dil = 0;
    if (MODE == 1) {
        int z = blockIdx.z;
        dil = 1 << z;
        W += (size_t)z * 3 * HDIM * HDIM;
        bias += z * HDIM;
        coff += z * HDIM;
    }

    const int tid = threadIdx.x;
    const int lane = tid & 31;
    const int wid = tid >> 5;
    const int wm = wid >> 2;      // 0..3 -> 64-row slabs
    const int wn = wid & 3;       // 0..3 -> 32-col slabs
    const int g = lane >> 2;
    const int t = lane & 3;
    const int row0 = blockIdx.y * 256;
    const int col0 = blockIdx.x * 128;
    const int KT = K >> 5;

    const unsigned sA = (unsigned)__cvta_generic_to_shared(As);
    const unsigned sB = (unsigned)__cvta_generic_to_shared(Bs);
    const unsigned aBase = sA + (((wm * 64 + (lane & 15)) * TFPAD + ((lane >> 4) & 1) * 4) << 2);
    const unsigned bBase = sB + (((wn * 32 + (lane & 7) + ((lane >> 4) & 1) * 8) * TFPAD
                                  + ((lane >> 3) & 1) * 4) << 2);
    const unsigned ABUF = 256 * TFPAD * 4;
    const unsigned BBUF = 128 * TFPAD * 4;

    float acc[4][4][4];
    #pragma unroll
    for (int i = 0; i < 4; i++)
        #pragma unroll
        for (int j = 0; j < 4; j++)
            #pragma unroll
            for (int q = 0; q < 4; q++) acc[i][j][q] = 0.f;

    auto load_tile = [&](int kt, int buf) {
        int k0 = kt << 5;
        int ksl = 0, h0 = k0, shift = 0;
        if (MODE == 1) {
            ksl = k0 >> 10;
            h0 = k0 & (HDIM - 1);
            shift = (ksl - 1) * dil;
        }
        float* Ad = As + buf * 256 * TFPAD;
        float* Bd = Bs + buf * 128 * TFPAD;
        // A: 256 rows x 8 float4 = 2048 chunks, 4/thread
        #pragma unroll
        for (int i = 0; i < 4; i++) {
            int idx = tid + i * 512;
            int r = idx >> 3;
            int c4 = (idx & 7) << 2;
            const float* srcA;
            bool pred = true;
            if (MODE == 1) {
                int n = row0 + r;
                int s2 = (n & (SDIM - 1)) + shift;
                pred = ((unsigned)s2 < (unsigned)SDIM);
                srcA = pred ? (A + (size_t)(n + shift) * HDIM + h0 + c4) : A;
            } else {
                srcA = A + (size_t)(row0 + r) * K + k0 + c4;
            }
            cp16(Ad + r * TFPAD + c4, srcA, pred);
        }
        // B: 128 rows x 8 float4 = 1024 chunks, 2/thread
        #pragma unroll
        for (int i = 0; i < 2; i++) {
            int idx = tid + i * 512;
            int r = idx >> 3;
            int c4 = (idx & 7) << 2;
            const float* srcB;
            if (MODE == 1)
                srcB = W + ((size_t)ksl * HDIM + col0 + r) * HDIM + h0 + c4;
            else
                srcB = W + (size_t)(col0 + r) * K + k0 + c4;
            cp16(Bd + r * TFPAD + c4, srcB, true);
        }
    };

    load_tile(0, 0); CP_COMMIT();
    if (KT > 1) load_tile(1, 1);
    CP_COMMIT();

    int buf = 0;
    for (int kt = 0; kt < KT; kt++) {
        CP_WAIT1();
        __syncthreads();
        if (kt + 2 < KT) load_tile(kt + 2, (buf + 2 >= 3) ? buf - 1 : buf + 2);
        CP_COMMIT();

        const unsigned aB = aBase + buf * ABUF;
        const unsigned bB = bBase + buf * BBUF;
        #pragma unroll
        for (int kk = 0; kk < 4; kk++) {
            unsigned af[4][4], bf[4][2];
            #pragma unroll
            for (int p = 0; p < 2; p++)
                ldsm_x4(bB + p * (16 * TFPAD * 4) + kk * 32,
                        bf[2 * p][0], bf[2 * p][1], bf[2 * p + 1][0], bf[2 * p + 1][1]);
            #pragma unroll
            for (int mt = 0; mt < 4; mt++)
                ldsm_x4(aB + mt * (16 * TFPAD * 4) + kk * 32,
                        af[mt][0], af[mt][1], af[mt][2], af[mt][3]);
            #pragma unroll
            for (int mt = 0; mt < 4; mt++)
                #pragma unroll
                for (int nt = 0; nt < 4; nt++)
                    mma_tf32(acc[mt][nt], af[mt], bf[nt]);
        }
        buf = (buf + 1 == 3) ? 0 : buf + 1;
    }

    #pragma unroll
    for (int mt = 0; mt < 4; mt++) {
        int r0 = row0 + wm * 64 + mt * 16 + g;
        int r1 = r0 + 8;
        #pragma unroll
        for (int nt = 0; nt < 4; nt++) {
            int c = col0 + wn * 32 + nt * 8 + 2 * t;
            float b0v = bias ? bias[c] : 0.f;
            float b1v = bias ? bias[c + 1] : 0.f;
            float v[4] = {acc[mt][nt][0] + b0v, acc[mt][nt][1] + b1v,
                          acc[mt][nt][2] + b0v, acc[mt][nt][3] + b1v};
            if (act == 2) {
                #pragma unroll
                for (int q = 0; q < 4; q++)
                    v[q] = 0.5f * v[q] * (1.f + erff(v[q] * 0.70710678118654752f));
            } else if (act == 1) {
                #pragma unroll
                for (int q = 0; q < 4; q++) v[q] = fmaxf(v[q], 0.f);
            }
            if (roundC) {
                #pragma unroll
                for (int q = 0; q < 4; q++) v[q] = round_tf32f(v[q]);
            }
            *reinterpret_cast<float2*>(C + (size_t)r0 * ldc + coff + c) = make_float2(v[0], v[1]);
            *reinterpret_cast<float2*>(C + (size_t)r1 * ldc + coff + c) = make_float2(v[2], v[3]);
        }
    }
}

// =====================================================================
// BF16 GEMM (router), BM=256 x BN=128, 512 threads, BK=32 halves.
// MODE 0: plain. MODE 2: 3xBF16 virtual K=3072.
// =====================================================================
#define HPAD 40

template<int MODE>
__global__ void __launch_bounds__(512, 1) gemm_bf16k(
    const __nv_bfloat16* __restrict__ A, const __nv_bfloat16* __restrict__ Alo,
    const __nv_bfloat16* __restrict__ W, const __nv_bfloat16* __restrict__ Wlo,
    const float* __restrict__ bias, float* __restrict__ C, __nv_bfloat16* __restrict__ C2,
    int K, int ldc, int act)
{
    extern __shared__ __nv_bfloat16 hsm[];
    __nv_bfloat16* As = hsm;                   // [3][256][HPAD]
    __nv_bfloat16* Bs = hsm + 3 * 256 * HPAD;  // [3][128][HPAD]

    const int tid = threadIdx.x;
    const int lane = tid & 31;
    const int wid = tid >> 5;
    const int wm = wid >> 2;
    const int wn = wid & 3;
    const int g = lane >> 2;
    const int t = lane & 3;
    const int row0 = blockIdx.y * 256;
    const int col0 = blockIdx.x * 128;
    const int KT = K >> 5;

    const unsigned sA = (unsigned)__cvta_generic_to_shared(As);
    const unsigned sB = (unsigned)__cvta_generic_to_shared(Bs);
    const unsigned aBase = sA + (wm * 64 + (lane & 15)) * (HPAD * 2) + ((lane >> 4) & 1) * 16;
    const unsigned bBase = sB + (wn * 32 + (lane & 7) + ((lane >> 4) & 1) * 8) * (HPAD * 2)
                              + ((lane >> 3) & 1) * 16;
    const unsigned ABUF = 256 * HPAD * 2;
    const unsigned BBUF = 128 * HPAD * 2;

    float acc[4][4][4];
    #pragma unroll
    for (int i = 0; i < 4; i++)
        #pragma unroll
        for (int j = 0; j < 4; j++)
            #pragma unroll
            for (int q = 0; q < 4; q++) acc[i][j][q] = 0.f;

    auto load_tile = [&](int kt, int buf) {
        int k0 = kt << 5;
        int ksl = 0, h0 = k0;
        if (MODE == 2) { ksl = k0 >> 10; h0 = k0 & (HDIM - 1); }
        __nv_bfloat16* Ad = As + buf * 256 * HPAD;
        __nv_bfloat16* Bd = Bs + buf * 128 * HPAD;
        // A: 256 rows x 4 chunks(8 halves) = 1024, 2/thread
        #pragma unroll
        for (int i = 0; i < 2; i++) {
            int idx = tid + i * 512;
            int r = idx >> 2;
            int c8 = (idx & 3) << 3;
            const __nv_bfloat16* srcA;
            if (MODE == 2) {
                const __nv_bfloat16* Ab = (ksl == 2) ? Alo : A;
                srcA = Ab + (size_t)(row0 + r) * HDIM + h0 + c8;
            } else {
                srcA = A + (size_t)(row0 + r) * K + k0 + c8;
            }
            cp16(Ad + r * HPAD + c8, srcA, true);
        }
        // B: 128 rows x 4 chunks = 512, 1/thread
        {
            int r = tid >> 2;
            int c8 = (tid & 3) << 3;
            const __nv_bfloat16* srcB;
            if (MODE == 2) {
                const __nv_bfloat16* Wb = (ksl == 1) ? Wlo : W;
                srcB = Wb + (size_t)(col0 + r) * HDIM + h0 + c8;
            } else {
                srcB = W + (size_t)(col0 + r) * K + k0 + c8;
            }
            cp16(Bd + r * HPAD + c8, srcB, true);
        }
    };

    load_tile(0, 0); CP_COMMIT();
    if (KT > 1) load_tile(1, 1);
    CP_COMMIT();

    int buf = 0;
    for (int kt = 0; kt < KT; kt++) {
        CP_WAIT1();
        __syncthreads();
        if (kt + 2 < KT) load_tile(kt + 2, (buf + 2 >= 3) ? buf - 1 : buf + 2);
        CP_COMMIT();

        const unsigned aB = aBase + buf * ABUF;
        const unsigned bB = bBase + buf * BBUF;
        #pragma unroll
        for (int kk = 0; kk < 2; kk++) {
            unsigned af[4][4], bf[4][2];
            #pragma unroll
            for (int p = 0; p < 2; p++)
                ldsm_x4(bB + p * (16 * HPAD * 2) + kk * 32,
                        bf[2 * p][0], bf[2 * p][1], bf[2 * p + 1][0], bf[2 * p + 1][1]);
            #pragma unroll
            for (int mt = 0; mt < 4; mt++)
                ldsm_x4(aB + mt * (16 * HPAD * 2) + kk * 32,
                        af[mt][0], af[mt][1], af[mt][2], af[mt][3]);
            #pragma unroll
            for (int mt = 0; mt < 4; mt++)
                #pragma unroll
                for (int nt = 0; nt < 4; nt++)
                    mma_bf16(acc[mt][nt], af[mt], bf[nt]);
        }
        buf = (buf + 1 == 3) ? 0 : buf + 1;
    }

    #pragma unroll
    for (int mt = 0; mt < 4; mt++) {
        int r0 = row0 + wm * 64 + mt * 16 + g;
        int r1 = r0 + 8;
        #pragma unroll
        for (int nt = 0; nt < 4; nt++) {
            int c = col0 + wn * 32 + nt * 8 + 2 * t;
            float b0v = bias ? bias[c] : 0.f;
            float b1v = bias ? bias[c + 1] : 0.f;
            float v[4] = {acc[mt][nt][0] + b0v, acc[mt][nt][1] + b1v,
                          acc[mt][nt][2] + b0v, acc[mt][nt][3] + b1v};
            if (act == 1) {
                #pragma unroll
                for (int q = 0; q < 4; q++) v[q] = fmaxf(v[q], 0.f);
            }
            if (C) {
                *reinterpret_cast<float2*>(C + (size_t)r0 * ldc + c) = make_float2(v[0], v[1]);
                *reinterpret_cast<float2*>(C + (size_t)r1 * ldc + c) = make_float2(v[2], v[3]);
            }
            if (C2) {
                __nv_bfloat162 p0, p1;
                p0.x = __float2bfloat16_rn(v[0]); p0.y = __float2bfloat16_rn(v[1]);
                p1.x = __float2bfloat16_rn(v[2]); p1.y = __float2bfloat16_rn(v[3]);
                *reinterpret_cast<__nv_bfloat162*>(C2 + (size_t)r0 * ldc + c) = p0;
                *reinterpret_cast<__nv_bfloat162*>(C2 + (size_t)r1 * ldc + c) = p1;
            }
        }
    }
}

// ---------------- prep kernels ----------------
__global__ void round_tf32_kernel(const float* __restrict__ src, float* __restrict__ dst, int n4) {
    int i = blockIdx.x * blockDim.x + threadIdx.x;
    if (i >= n4) return;
    float4 v = reinterpret_cast<const float4*>(src)[i];
    v.x = round_tf32f(v.x); v.y = round_tf32f(v.y);
    v.z = round_tf32f(v.z); v.w = round_tf32f(v.w);
    reinterpret_cast<float4*>(dst)[i] = v;
}

__global__ void prep_x_kernel(const float* __restrict__ src, float* __restrict__ xt,
                              __nv_bfloat16* __restrict__ hi, __nv_bfloat16* __restrict__ lo,
                              int n4) {
    int i = blockIdx.x * blockDim.x + threadIdx.x;
    if (i >= n4) return;
    float4 v = reinterpret_cast<const float4*>(src)[i];
    float4 r;
    r.x = round_tf32f(v.x); r.y = round_tf32f(v.y);
    r.z = round_tf32f(v.z); r.w = round_tf32f(v.w);
    reinterpret_cast<float4*>(xt)[i] = r;
    __nv_bfloat162 h0, h1, l0, l1;
    h0.x = __float2bfloat16_rn(v.x); l0.x = __float2bfloat16_rn(v.x - __bfloat162float(h0.x));
    h0.y = __float2bfloat16_rn(v.y); l0.y = __float2bfloat16_rn(v.y - __bfloat162float(h0.y));
    h1.x = __float2bfloat16_rn(v.z); l1.x = __float2bfloat16_rn(v.z - __bfloat162float(h1.x));
    h1.y = __float2bfloat16_rn(v.w); l1.y = __float2bfloat16_rn(v.w - __bfloat162float(h1.y));
    reinterpret_cast<__nv_bfloat162*>(hi)[2 * i] = h0;
    reinterpret_cast<__nv_bfloat162*>(hi)[2 * i + 1] = h1;
    reinterpret_cast<__nv_bfloat162*>(lo)[2 * i] = l0;
    reinterpret_cast<__nv_bfloat162*>(lo)[2 * i + 1] = l1;
}

__global__ void split_bf16_kernel(const float* __restrict__ src, __nv_bfloat16* __restrict__ hi,
                                  __nv_bfloat16* __restrict__ lo, int n) {
    int i = blockIdx.x * blockDim.x + threadIdx.x;
    if (i >= n) return;
    float v = src[i];
    __nv_bfloat16 h = __float2bfloat16_rn(v);
    hi[i] = h;
    lo[i] = __float2bfloat16_rn(v - __bfloat162float(h));
}

__global__ void round_bf16_kernel(const float* __restrict__ src, __nv_bfloat16* __restrict__ dst, int n) {
    int i = blockIdx.x * blockDim.x + threadIdx.x;
    if (i >= n) return;
    dst[i] = __float2bfloat16_rn(src[i]);
}

__global__ void repack_convw(const float* __restrict__ cw, float* __restrict__ out) {
    int idx = blockIdx.x * blockDim.x + threadIdx.x;
    const int total = NDIL * 3 * HDIM * HDIM;
    if (idx >= total) return;
    int hi = idx & (HDIM - 1);
    int t = idx >> 10;
    int ho = t & (HDIM - 1);
    int t2 = t >> 10;
    int k = t2 % 3;
    int d = t2 / 3;
    out[idx] = round_tf32f(cw[(((size_t)d * HDIM + ho) * HDIM + hi) * 3 + k]);
}

__global__ void zero_usage(float* usage) {
    int i = blockIdx.x * blockDim.x + threadIdx.x;
    if (i < PDIM) usage[i] = 0.f;
}

// ---------------- top-8 (bf16 logits) + fp32 rescore + exact top-2 ----------------
__device__ __forceinline__ bool better(float va, int ia, float vb, int ib) {
    return (va > vb) || (va == vb && ia < ib);
}
__device__ __forceinline__ void ins2(float& v1, int& i1, float& v2, int& i2, float v, int i) {
    if (better(v, i, v1, i1)) { v2 = v1; i2 = i1; v1 = v; i1 = i; }
    else if (better(v, i, v2, i2)) { v2 = v; i2 = i; }
}

__global__ void __launch_bounds__(256) topk_rescore_kernel(
    const __nv_bfloat16* __restrict__ logits, const float* __restrict__ inter,
    const float* __restrict__ w2, const float* __restrict__ b2,
    const float* __restrict__ tpool, const float* __restrict__ temp_p,
    float* __restrict__ combined, float* __restrict__ usage)
{
    int gw = (blockIdx.x * blockDim.x + threadIdx.x) >> 5;
    int lane = threadIdx.x & 31;
    if (gw >= NTOK) return;
    float temp = fminf(fmaxf(*temp_p, 0.1f), 5.0f);
    float invt = 1.f / temp;

    const __nv_bfloat16* lrow = logits + (size_t)gw * PDIM;
    float tv[8]; int ti[8];
    #pragma unroll
    for (int k = 0; k < 8; k++) { tv[k] = -FLT_MAX; ti[k] = 0x3fffffff; }
    auto push = [&](float v, int j) {
        if (better(v, j, tv[7], ti[7])) {
            tv[7] = v; ti[7] = j;
            #pragma unroll
            for (int k = 7; k > 0; k--) {
                bool sw = better(tv[k], ti[k], tv[k - 1], ti[k - 1]);
                float av = sw ? tv[k] : tv[k - 1];
                float bv2 = sw ? tv[k - 1] : tv[k];
                int ai = sw ? ti[k] : ti[k - 1];
                int bi = sw ? ti[k - 1] : ti[k];
                tv[k - 1] = av; tv[k] = bv2; ti[k - 1] = ai; ti[k] = bi;
            }
        }
    };
    for (int j = lane * 2; j < PDIM; j += 64) {
        __nv_bfloat162 p = *reinterpret_cast<const __nv_bfloat162*>(lrow + j);
        push(fminf(fmaxf(__bfloat162float(p.x) * invt, -10.f), 10.f), j);
        push(fminf(fmaxf(__bfloat162float(p.y) * invt, -10.f), 10.f), j + 1);
    }

    int cand[8];
    #pragma unroll
    for (int r = 0; r < 8; r++) {
        float bvv = tv[0]; int bii = ti[0];
        #pragma unroll
        for (int off = 16; off; off >>= 1) {
            float ov = __shfl_xor_sync(0xffffffffu, bvv, off);
            int oi = __shfl_xor_sync(0xffffffffu, bii, off);
            if (better(ov, oi, bvv, bii)) { bvv = ov; bii = oi; }
        }
        cand[r] = bii;
        if (ti[0] == bii) {
            #pragma unroll
            for (int k = 0; k < 7; k++) { tv[k] = tv[k + 1]; ti[k] = ti[k + 1]; }
            tv[7] = -FLT_MAX; ti[7] = 0x3fffffff;
        }
    }

    const float* irow = inter + (size_t)gw * INTER_DIM;
    float xv[32];
    #pragma unroll
    for (int q = 0; q < 32; q++) xv[q] = irow[lane + q * 32];

    float v1 = -FLT_MAX, v2 = -FLT_MAX;
    int i1 = 0x3fffffff, i2 = 0x3fffffff;
    #pragma unroll
    for (int r = 0; r < 8; r++) {
        const float* wrow = w2 + (size_t)cand[r] * INTER_DIM;
        float s = 0.f;
        #pragma unroll
        for (int q = 0; q < 32; q++) s = fmaf(xv[q], wrow[lane + q * 32], s);
        #pragma unroll
        for (int off = 16; off; off >>= 1) s += __shfl_xor_sync(0xffffffffu, s, off);
        float v = fminf(fmaxf((s + b2[cand[r]]) * invt, -10.f), 10.f);
        ins2(v1, i1, v2, i2, v, cand[r]);
    }

    float e = expf(v2 - v1);
    float w1 = 1.f / (1.f + e);
    float w2s = e / (1.f + e);
    if (lane == 0) {
        atomicAdd(&usage[i1], w1);
        atomicAdd(&usage[i2], w2s);
    }
    const float* p1 = tpool + (size_t)i1 * DDIM;
    const float* p2 = tpool + (size_t)i2 * DDIM;
    float* dst = combined + (size_t)gw * (2 * DDIM) + DDIM;
    for (int d = lane; d < DDIM; d += 32)
        dst[d] = round_tf32f(w1 * p1[d] + w2s * p2[d]);
}

// ---------------- layernorm over D=512, writes rounded combined[:, :512] ----------------
__global__ void ln_kernel(const float* __restrict__ proj, const float* __restrict__ g,
                          const float* __restrict__ b, float* __restrict__ combined)
{
    __shared__ float sh[33];
    int n = blockIdx.x;
    const float* row = proj + (size_t)n * DDIM;
    float v[4];
    float s = 0.f;
    #pragma unroll
    for (int j = 0; j < 4; j++) { v[j] = row[threadIdx.x + j * 128]; s += v[j]; }
    float mean = block_reduce_sum(s, sh) * (1.f / DDIM);
    float q = 0.f;
    #pragma unroll
    for (int j = 0; j < 4; j++) { float d = v[j] - mean; q += d * d; }
    float var = block_reduce_sum(q, sh) * (1.f / DDIM);
    float rstd = rsqrtf(var + 1e-5f);
    float* dst = combined + (size_t)n * (2 * DDIM);
    #pragma unroll
    for (int j = 0; j < 4; j++) {
        int idx = threadIdx.x + j * 128;
        dst[idx] = round_tf32f((v[j] - mean) * rstd * g[idx] + b[idx]);
    }
}

// ---------------- gate + final mix ----------------
__global__ void gate_combine(const float* __restrict__ x, const float* __restrict__ wg,
                             const float* __restrict__ bg, const float* __restrict__ local,
                             const float* __restrict__ glob, float* __restrict__ out)
{
    __shared__ float sh[33];
    int n = blockIdx.x;
    const float* xr = x + (size_t)n * HDIM;
    float s = 0.f;
    for (int j = threadIdx.x; j < HDIM; j += 128) s += xr[j] * wg[j];
    float dot = block_reduce_sum(s, sh);
    float g = 1.f / (1.f + expf(-(dot + bg[0])));
    const float* lr = local + (size_t)n * HDIM;
    const float* gr = glob + (size_t)n * HDIM;
    float* orow = out + (size_t)n * HDIM;
    for (int j = threadIdx.x; j < HDIM; j += 128)
        orow[j] = g * lr[j] + (1.f - g) * gr[j];
}

// ---------------- diversity loss ----------------
__global__ void divloss_kernel(const float* __restrict__ usage, float* __restrict__ out) {
    __shared__ float sh[33];
    float s = 0.f;
    for (int j = threadIdx.x; j < PDIM; j += 1024) s += usage[j];
    float total = block_reduce_sum(s, sh);
    float inv = 1.f / (total + 1e-8f);
    float q = 0.f;
    const float ip = 1.f / (float)PDIM;
    for (int j = threadIdx.x; j < PDIM; j += 1024) {
        float f = usage[j] * inv - ip;
        q += f * f;
    }
    float qt = block_reduce_sum(q, sh);
    if (threadIdx.x == 0) out[0] = (qt / (float)PDIM) * 0.01f;
}

// ---------------- host launcher ----------------
extern "C" void kernel_launch(void* const* d_in, const int* in_sizes, int n_in,
                              void* d_out, int out_size)
{
    const float* x      = (const float*)d_in[0];
    const float* tpool  = (const float*)d_in[1];
    const float* w1     = (const float*)d_in[2];
    const float* b1     = (const float*)d_in[3];
    const float* w2     = (const float*)d_in[4];
    const float* b2     = (const float*)d_in[5];
    const float* temp   = (const float*)d_in[6];
    const float* wproj  = (const float*)d_in[7];
    const float* bproj  = (const float*)d_in[8];
    const float* ln_g   = (const float*)d_in[9];
    const float* ln_b   = (const float*)d_in[10];
    const float* wmap   = (const float*)d_in[11];
    const float* bmap   = (const float*)d_in[12];
    const float* conv_w = (const float*)d_in[13];
    const float* conv_b = (const float*)d_in[14];
    const float* wout   = (const float*)d_in[15];
    const float* bout   = (const float*)d_in[16];
    const float* wrp    = (const float*)d_in[17];
    const float* brp    = (const float*)d_in[18];
    const float* wg     = (const float*)d_in[19];
    const float* bg     = (const float*)d_in[20];
    float* out = (float*)d_out;

    float *inter, *concat, *local, *combined, *transf, *glob, *proj;
    float *convwt, *usage, *xt, *wprojt, *woutt, *wmapt, *wrpt;
    __nv_bfloat16 *logitsb, *xhb, *xlb, *w1hb, *w1lb, *w2b, *interb;
    cudaGetSymbolAddress((void**)&inter,    g_inter);
    cudaGetSymbolAddress((void**)&logitsb,  g_logitsb);
    cudaGetSymbolAddress((void**)&concat,   g_concat);
    cudaGetSymbolAddress((void**)&local,    g_local);
    cudaGetSymbolAddress((void**)&combined, g_combined);
    cudaGetSymbolAddress((void**)&transf,   g_transf);
    cudaGetSymbolAddress((void**)&glob,     g_global);
    cudaGetSymbolAddress((void**)&proj,     g_proj);
    cudaGetSymbolAddress((void**)&convwt,   g_convwt);
    cudaGetSymbolAddress((void**)&usage,    g_usage);
    cudaGetSymbolAddress((void**)&xt,       g_xt);
    cudaGetSymbolAddress((void**)&wprojt,   g_wprojt);
    cudaGetSymbolAddress((void**)&woutt,    g_woutt);
    cudaGetSymbolAddress((void**)&wmapt,    g_wmapt);
    cudaGetSymbolAddress((void**)&wrpt,     g_wrpt);
    cudaGetSymbolAddress((void**)&xhb,      g_xhb);
    cudaGetSymbolAddress((void**)&xlb,      g_xlb);
    cudaGetSymbolAddress((void**)&w1hb,     g_w1hb);
    cudaGetSymbolAddress((void**)&w1lb,     g_w1lb);
    cudaGetSymbolAddress((void**)&w2b,      g_w2b);
    cudaGetSymbolAddress((void**)&interb,   g_interb);

    const int TF_SMEM = 3 * (256 + 128) * TFPAD * sizeof(float);          // 165888 B
    const int BF_SMEM = 3 * (256 + 128) * HPAD * sizeof(__nv_bfloat16);   // 92160 B
    cudaFuncSetAttribute(gemm_tf32<0>, cudaFuncAttributeMaxDynamicSharedMemorySize, TF_SMEM);
    cudaFuncSetAttribute(gemm_tf32<1>, cudaFuncAttributeMaxDynamicSharedMemorySize, TF_SMEM);
    cudaFuncSetAttribute(gemm_bf16k<0>, cudaFuncAttributeMaxDynamicSharedMemorySize, BF_SMEM);
    cudaFuncSetAttribute(gemm_bf16k<2>, cudaFuncAttributeMaxDynamicSharedMemorySize, BF_SMEM);

    // ---- prep ----
    const int total_cw = NDIL * 3 * HDIM * HDIM;
    repack_convw<<<(total_cw + 255) / 256, 256>>>(conv_w, convwt);
    zero_usage<<<(PDIM + 255) / 256, 256>>>(usage);
    prep_x_kernel<<<(NTOK * HDIM / 4 + 255) / 256, 256>>>(x, xt, xhb, xlb, NTOK * HDIM / 4);
    round_tf32_kernel<<<(DDIM * HDIM / 4 + 255) / 256, 256>>>(wproj, wprojt, DDIM * HDIM / 4);
    round_tf32_kernel<<<(HDIM * 3 * HDIM / 4 + 255) / 256, 256>>>(wout, woutt, HDIM * 3 * HDIM / 4);
    round_tf32_kernel<<<(DDIM * 2 * DDIM / 4 + 255) / 256, 256>>>(wmap, wmapt, DDIM * 2 * DDIM / 4);
    round_tf32_kernel<<<(HDIM * DDIM / 4 + 255) / 256, 256>>>(wrp, wrpt, HDIM * DDIM / 4);
    split_bf16_kernel<<<(INTER_DIM * HDIM + 255) / 256, 256>>>(w1, w1hb, w1lb, INTER_DIM * HDIM);
    round_bf16_kernel<<<((int)((size_t)PDIM * INTER_DIM) + 255) / 256, 256>>>(
        w2, w2b, PDIM * INTER_DIM);

    // ---- router inter: 3xBF16 split, relu; dual write fp32 + bf16 ----
    gemm_bf16k<2><<<dim3(INTER_DIM / 128, NTOK / 256), 512, BF_SMEM>>>(
        xhb, xlb, w1hb, w1lb, b1, inter, interb, 3 * HDIM, INTER_DIM, 1);

    // ---- logits: single bf16, bf16 output (top-8 screen only) ----
    gemm_bf16k<0><<<dim3(PDIM / 128, NTOK / 256), 512, BF_SMEM>>>(
        interb, nullptr, w2b, nullptr, b2, nullptr, logitsb, INTER_DIM, PDIM, 0);

    topk_rescore_kernel<<<(NTOK * 32 + 255) / 256, 256>>>(
        logitsb, inter, w2, b2, tpool, temp, combined, usage);

    // ---- projected_x (tf32) -> LN -> combined[:, :512] ----
    gemm_tf32<0><<<dim3(DDIM / 128, NTOK / 256), 512, TF_SMEM>>>(
        xt, wprojt, bproj, proj, HDIM, DDIM, 0, 0, 0);
    ln_kernel<<<NTOK, 128>>>(proj, ln_g, ln_b, combined);

    // ---- dilated convs: fused launch, blockIdx.z = dilation (1,2,4) ----
    gemm_tf32<1><<<dim3(HDIM / 128, NTOK / 256, NDIL), 512, TF_SMEM>>>(
        xt, convwt, conv_b, concat, 3 * HDIM, 3 * HDIM, 0, 2, 1);

    // ---- local out (tf32) ----
    gemm_tf32<0><<<dim3(HDIM / 128, NTOK / 256), 512, TF_SMEM>>>(
        concat, woutt, bout, local, 3 * HDIM, HDIM, 0, 0, 0);

    // ---- transformation (rounded out) + global out (tf32) ----
    gemm_tf32<0><<<dim3(DDIM / 128, NTOK / 256), 512, TF_SMEM>>>(
        combined, wmapt, bmap, transf, 2 * DDIM, DDIM, 0, 0, 1);
    gemm_tf32<0><<<dim3(HDIM / 128, NTOK / 256), 512, TF_SMEM>>>(
        transf, wrpt, brp, glob, DDIM, HDIM, 0, 0, 0);

    // gate + mix -> out
    gate_combine<<<NTOK, 128>>>(x, wg, bg, local, glob, out);

    // diversity loss -> last output element
    if (out_size > NTOK * HDIM)
        divloss_kernel<<<1, 1024>>>(usage, out + (size_t)NTOK * HDIM);
}

// round 11
// speedup vs baseline: 1.0752x; 1.0752x over previous
#include <cuda_runtime.h>
#include <cuda_bf16.h>
#include <cstdint>
#include <float.h>

// ---------------- problem constants ----------------
#define BDIM 4
#define SDIM 4096
#define HDIM 1024
#define PDIM 4096
#define DDIM 512
#define NTOK (BDIM * SDIM)          // 16384
#define INTER_DIM 1024
#define NDIL 3

// ---------------- scratch (device globals; no allocs allowed) ----------------
__device__ float g_inter[NTOK * INTER_DIM];         // near-exact fp32 (rescore)
__device__ __nv_bfloat16 g_logitsb[(size_t)NTOK * PDIM]; // bf16 screen logits
__device__ float g_concat[(size_t)NTOK * 3 * HDIM]; // tf32-rounded GELU out
__device__ float g_local[NTOK * HDIM];
__device__ float g_combined[NTOK * 2 * DDIM];       // tf32-rounded
__device__ float g_transf[NTOK * DDIM];             // tf32-rounded
__device__ float g_global[NTOK * HDIM];
__device__ float g_proj[NTOK * DDIM];
__device__ float g_convwt[NDIL * 3 * HDIM * HDIM];  // repacked + tf32-rounded
__device__ float g_usage[PDIM];
// pre-rounded tf32 operands (continuous paths)
__device__ float g_xt[NTOK * HDIM];                 // tf32(x)
__device__ float g_wprojt[DDIM * HDIM];
__device__ float g_woutt[HDIM * 3 * HDIM];
__device__ float g_wmapt[DDIM * 2 * DDIM];
__device__ float g_wrpt[HDIM * DDIM];
// bf16 router operands
__device__ __nv_bfloat16 g_xhb[NTOK * HDIM];        // hi(x) bf16
__device__ __nv_bfloat16 g_xlb[NTOK * HDIM];        // lo(x) bf16
__device__ __nv_bfloat16 g_w1hb[INTER_DIM * HDIM];
__device__ __nv_bfloat16 g_w1lb[INTER_DIM * HDIM];
__device__ __nv_bfloat16 g_w2b[(size_t)PDIM * INTER_DIM];
__device__ __nv_bfloat16 g_interb[NTOK * INTER_DIM];// bf16(inter) (logits A)

// ---------------- helpers ----------------
__device__ __forceinline__ float block_reduce_sum(float v, float* sh) {
    int tid = threadIdx.x;
    #pragma unroll
    for (int o = 16; o; o >>= 1) v += __shfl_xor_sync(0xffffffffu, v, o);
    if ((tid & 31) == 0) sh[tid >> 5] = v;
    __syncthreads();
    int nw = blockDim.x >> 5;
    float r = (tid < nw) ? sh[tid] : 0.f;
    if (tid < 32) {
        #pragma unroll
        for (int o = 16; o; o >>= 1) r += __shfl_xor_sync(0xffffffffu, r, o);
        if (tid == 0) sh[32] = r;
    }
    __syncthreads();
    float total = sh[32];
    __syncthreads();
    return total;
}

__device__ __forceinline__ unsigned cvt_tf32(float x) {
    unsigned r;
    asm("cvt.rna.tf32.f32 %0, %1;" : "=r"(r) : "f"(x));
    return r;
}
__device__ __forceinline__ float round_tf32f(float x) {
    return __uint_as_float(cvt_tf32(x));
}

__device__ __forceinline__ void mma_tf32(float* c, const unsigned* a, const unsigned* b) {
    asm volatile(
        "mma.sync.aligned.m16n8k8.row.col.f32.tf32.tf32.f32 "
        "{%0,%1,%2,%3}, {%4,%5,%6,%7}, {%8,%9}, {%0,%1,%2,%3};\n"
        : "+f"(c[0]), "+f"(c[1]), "+f"(c[2]), "+f"(c[3])
        : "r"(a[0]), "r"(a[1]), "r"(a[2]), "r"(a[3]), "r"(b[0]), "r"(b[1]));
}

__device__ __forceinline__ void mma_bf16(float* c, const unsigned* a, const unsigned* b) {
    asm volatile(
        "mma.sync.aligned.m16n8k16.row.col.f32.bf16.bf16.f32 "
        "{%0,%1,%2,%3}, {%4,%5,%6,%7}, {%8,%9}, {%0,%1,%2,%3};\n"
        : "+f"(c[0]), "+f"(c[1]), "+f"(c[2]), "+f"(c[3])
        : "r"(a[0]), "r"(a[1]), "r"(a[2]), "r"(a[3]), "r"(b[0]), "r"(b[1]));
}

__device__ __forceinline__ void ldsm_x4(unsigned addr, unsigned& r0, unsigned& r1,
                                        unsigned& r2, unsigned& r3) {
    asm volatile("ldmatrix.sync.aligned.m8n8.x4.shared.b16 {%0,%1,%2,%3}, [%4];"
                 : "=r"(r0), "=r"(r1), "=r"(r2), "=r"(r3) : "r"(addr));
}

__device__ __forceinline__ void cp16(void* dst_smem, const void* src, bool pred) {
    unsigned d = (unsigned)__cvta_generic_to_shared(dst_smem);
    int sz = pred ? 16 : 0;
    asm volatile("cp.async.cg.shared.global [%0], [%1], 16, %2;\n"
                 :: "r"(d), "l"(src), "r"(sz));
}
#define CP_COMMIT() asm volatile("cp.async.commit_group;\n" ::)
#define CP_WAIT1()  asm volatile("cp.async.wait_group 1;\n" ::)

// =====================================================================
// TF32 GEMM (R8-proven core: BM=BN=128, BK=32, 256 threads, 8 warps,
// warp 64x32, cp.async 3-stage, one __syncthreads per chunk, 2 CTAs/SM).
// MODE 0: plain single GEMM (primary param set).
// MODE 1: blockIdx.z in [0..3]: z<3 => conv virtual-im2col (dil = 1<<z),
//         z==3 => secondary plain GEMM (proj), active only x < nx2.
// MODE 2: blockIdx.z in [0..1]: z=0 primary plain (local),
//         z=1 secondary plain (map), active only x < nx2.
// =====================================================================
#define TFPAD 36

template<int MODE>
__global__ void __launch_bounds__(256, 2) gemm_tf32(
    const float* __restrict__ A, const float* __restrict__ W,
    const float* __restrict__ bias, float* __restrict__ C,
    int K, int ldc, int coff, int act, int roundC,
    const float* __restrict__ A2, const float* __restrict__ W2,
    const float* __restrict__ bias2, float* __restrict__ C2,
    int K2, int ldc2, int act2, int round2, int nx2)
{
    // ---- resolve per-z configuration ----
    const float* Ae = A;
    const float* We = W;
    const float* biase = bias;
    float* Ce = C;
    int Ke = K, ldce = ldc, coffe = coff, acte = act, rounde = roundC, dile = 0;
    bool convpath = false;
    if (MODE == 1) {
        int z = blockIdx.z;
        if (z < 3) {
            convpath = true;
            dile = 1 << z;
            We = W + (size_t)z * 3 * HDIM * HDIM;
            biase = bias + z * HDIM;
            coffe = coff + z * HDIM;
        } else {
            if ((int)blockIdx.x >= nx2) return;
            Ae = A2; We = W2; biase = bias2; Ce = C2;
            Ke = K2; ldce = ldc2; coffe = 0; acte = act2; rounde = round2;
        }
    } else if (MODE == 2) {
        if (blockIdx.z == 1) {
            if ((int)blockIdx.x >= nx2) return;
            Ae = A2; We = W2; biase = bias2; Ce = C2;
            Ke = K2; ldce = ldc2; coffe = 0; acte = act2; rounde = round2;
        }
    }

    extern __shared__ float smem[];
    float* As = smem;                      // [3][128][TFPAD]
    float* Bs = smem + 3 * 128 * TFPAD;    // [3][128][TFPAD]

    const int tid = threadIdx.x;
    const int lane = tid & 31;
    const int wid = tid >> 5;
    const int wm = wid >> 2;
    const int wn = wid & 3;
    const int g = lane >> 2;
    const int t = lane & 3;
    const int row0 = blockIdx.y * 128;
    const int col0 = blockIdx.x * 128;
    const int KT = Ke >> 5;

    const unsigned sA = (unsigned)__cvta_generic_to_shared(As);
    const unsigned sB = (unsigned)__cvta_generic_to_shared(Bs);
    const unsigned aBase = sA + (((wm * 64 + (lane & 15)) * TFPAD + ((lane >> 4) & 1) * 4) << 2);
    const unsigned bBase = sB + (((wn * 32 + (lane & 7) + ((lane >> 4) & 1) * 8) * TFPAD
                                  + ((lane >> 3) & 1) * 4) << 2);
    const unsigned BUFO = 128 * TFPAD * 4;

    float acc[4][4][4];
    #pragma unroll
    for (int i = 0; i < 4; i++)
        #pragma unroll
        for (int j = 0; j < 4; j++)
            #pragma unroll
            for (int q = 0; q < 4; q++) acc[i][j][q] = 0.f;

    auto load_tile = [&](int kt, int buf) {
        int k0 = kt << 5;
        int ksl = 0, h0 = k0, shift = 0;
        if (convpath) {
            ksl = k0 >> 10;
            h0 = k0 & (HDIM - 1);
            shift = (ksl - 1) * dile;
        }
        float* Ad = As + buf * 128 * TFPAD;
        float* Bd = Bs + buf * 128 * TFPAD;
        #pragma unroll
        for (int i = 0; i < 4; i++) {
            int idx = tid + i * 256;
            int r = idx >> 3;
            int c4 = (idx & 7) << 2;
            const float* srcA;
            bool pred = true;
            if (convpath) {
                int n = row0 + r;
                int s2 = (n & (SDIM - 1)) + shift;
                pred = ((unsigned)s2 < (unsigned)SDIM);
                srcA = pred ? (Ae + (size_t)(n + shift) * HDIM + h0 + c4) : Ae;
            } else {
                srcA = Ae + (size_t)(row0 + r) * Ke + k0 + c4;
            }
            cp16(Ad + r * TFPAD + c4, srcA, pred);
            const float* srcB;
            if (convpath)
                srcB = We + ((size_t)ksl * HDIM + col0 + r) * HDIM + h0 + c4;
            else
                srcB = We + (size_t)(col0 + r) * Ke + k0 + c4;
            cp16(Bd + r * TFPAD + c4, srcB, true);
        }
    };

    load_tile(0, 0); CP_COMMIT();
    if (KT > 1) load_tile(1, 1);
    CP_COMMIT();

    int buf = 0;
    for (int kt = 0; kt < KT; kt++) {
        CP_WAIT1();
        __syncthreads();
        if (kt + 2 < KT) load_tile(kt + 2, (buf + 2 >= 3) ? buf - 1 : buf + 2);
        CP_COMMIT();

        const unsigned aB = aBase + buf * BUFO;
        const unsigned bB = bBase + buf * BUFO;
        #pragma unroll
        for (int kk = 0; kk < 4; kk++) {
            unsigned af[4][4], bf[4][2];
            #pragma unroll
            for (int p = 0; p < 2; p++)
                ldsm_x4(bB + p * (16 * TFPAD * 4) + kk * 32,
                        bf[2 * p][0], bf[2 * p][1], bf[2 * p + 1][0], bf[2 * p + 1][1]);
            #pragma unroll
            for (int mt = 0; mt < 4; mt++)
                ldsm_x4(aB + mt * (16 * TFPAD * 4) + kk * 32,
                        af[mt][0], af[mt][1], af[mt][2], af[mt][3]);
            #pragma unroll
            for (int mt = 0; mt < 4; mt++)
                #pragma unroll
                for (int nt = 0; nt < 4; nt++)
                    mma_tf32(acc[mt][nt], af[mt], bf[nt]);
        }
        buf = (buf + 1 == 3) ? 0 : buf + 1;
    }

    #pragma unroll
    for (int mt = 0; mt < 4; mt++) {
        int r0 = row0 + wm * 64 + mt * 16 + g;
        int r1 = r0 + 8;
        #pragma unroll
        for (int nt = 0; nt < 4; nt++) {
            int c = col0 + wn * 32 + nt * 8 + 2 * t;
            float b0v = biase ? biase[c] : 0.f;
            float b1v = biase ? biase[c + 1] : 0.f;
            float v[4] = {acc[mt][nt][0] + b0v, acc[mt][nt][1] + b1v,
                          acc[mt][nt][2] + b0v, acc[mt][nt][3] + b1v};
            if (acte == 2) {
                #pragma unroll
                for (int q = 0; q < 4; q++)
                    v[q] = 0.5f * v[q] * (1.f + erff(v[q] * 0.70710678118654752f));
            } else if (acte == 1) {
                #pragma unroll
                for (int q = 0; q < 4; q++) v[q] = fmaxf(v[q], 0.f);
            }
            if (rounde) {
                #pragma unroll
                for (int q = 0; q < 4; q++) v[q] = round_tf32f(v[q]);
            }
            *reinterpret_cast<float2*>(Ce + (size_t)r0 * ldce + coffe + c) = make_float2(v[0], v[1]);
            *reinterpret_cast<float2*>(Ce + (size_t)r1 * ldce + coffe + c) = make_float2(v[2], v[3]);
        }
    }
}

// =====================================================================
// BF16 GEMM (router, R8 core unchanged).
// MODE 0: plain. MODE 2: 3xBF16 virtual K=3072.
// =====================================================================
#define HPAD 40

template<int MODE>
__global__ void __launch_bounds__(256, 2) gemm_bf16k(
    const __nv_bfloat16* __restrict__ A, const __nv_bfloat16* __restrict__ Alo,
    const __nv_bfloat16* __restrict__ W, const __nv_bfloat16* __restrict__ Wlo,
    const float* __restrict__ bias, float* __restrict__ C, __nv_bfloat16* __restrict__ C2,
    int K, int ldc, int act)
{
    extern __shared__ __nv_bfloat16 hsm[];
    __nv_bfloat16* As = hsm;                   // [3][128][HPAD]
    __nv_bfloat16* Bs = hsm + 3 * 128 * HPAD;

    const int tid = threadIdx.x;
    const int lane = tid & 31;
    const int wid = tid >> 5;
    const int wm = wid >> 2;
    const int wn = wid & 3;
    const int g = lane >> 2;
    const int t = lane & 3;
    const int row0 = blockIdx.y * 128;
    const int col0 = blockIdx.x * 128;
    const int KT = K >> 5;

    const unsigned sA = (unsigned)__cvta_generic_to_shared(As);
    const unsigned sB = (unsigned)__cvta_generic_to_shared(Bs);
    const unsigned aBase = sA + (wm * 64 + (lane & 15)) * (HPAD * 2) + ((lane >> 4) & 1) * 16;
    const unsigned bBase = sB + (wn * 32 + (lane & 7) + ((lane >> 4) & 1) * 8) * (HPAD * 2)
                              + ((lane >> 3) & 1) * 16;
    const unsigned BUFO = 128 * HPAD * 2;

    float acc[4][4][4];
    #pragma unroll
    for (int i = 0; i < 4; i++)
        #pragma unroll
        for (int j = 0; j < 4; j++)
            #pragma unroll
            for (int q = 0; q < 4; q++) acc[i][j][q] = 0.f;

    auto load_tile = [&](int kt, int buf) {
        int k0 = kt << 5;
        int ksl = 0, h0 = k0;
        if (MODE == 2) { ksl = k0 >> 10; h0 = k0 & (HDIM - 1); }
        __nv_bfloat16* Ad = As + buf * 128 * HPAD;
        __nv_bfloat16* Bd = Bs + buf * 128 * HPAD;
        #pragma unroll
        for (int i = 0; i < 2; i++) {
            int idx = tid + i * 256;
            int r = idx >> 2;
            int c8 = (idx & 3) << 3;
            const __nv_bfloat16* srcA;
            if (MODE == 2) {
                const __nv_bfloat16* Ab = (ksl == 2) ? Alo : A;
                srcA = Ab + (size_t)(row0 + r) * HDIM + h0 + c8;
            } else {
                srcA = A + (size_t)(row0 + r) * K + k0 + c8;
            }
            cp16(Ad + r * HPAD + c8, srcA, true);
            const __nv_bfloat16* srcB;
            if (MODE == 2) {
                const __nv_bfloat16* Wb = (ksl == 1) ? Wlo : W;
                srcB = Wb + (size_t)(col0 + r) * HDIM + h0 + c8;
            } else {
                srcB = W + (size_t)(col0 + r) * K + k0 + c8;
            }
            cp16(Bd + r * HPAD + c8, srcB, true);
        }
    };

    load_tile(0, 0); CP_COMMIT();
    if (KT > 1) load_tile(1, 1);
    CP_COMMIT();

    int buf = 0;
    for (int kt = 0; kt < KT; kt++) {
        CP_WAIT1();
        __syncthreads();
        if (kt + 2 < KT) load_tile(kt + 2, (buf + 2 >= 3) ? buf - 1 : buf + 2);
        CP_COMMIT();

        const unsigned aB = aBase + buf * BUFO;
        const unsigned bB = bBase + buf * BUFO;
        #pragma unroll
        for (int kk = 0; kk < 2; kk++) {
            unsigned af[4][4], bf[4][2];
            #pragma unroll
            for (int p = 0; p < 2; p++)
                ldsm_x4(bB + p * (16 * HPAD * 2) + kk * 32,
                        bf[2 * p][0], bf[2 * p][1], bf[2 * p + 1][0], bf[2 * p + 1][1]);
            #pragma unroll
            for (int mt = 0; mt < 4; mt++)
                ldsm_x4(aB + mt * (16 * HPAD * 2) + kk * 32,
                        af[mt][0], af[mt][1], af[mt][2], af[mt][3]);
            #pragma unroll
            for (int mt = 0; mt < 4; mt++)
                #pragma unroll
                for (int nt = 0; nt < 4; nt++)
                    mma_bf16(acc[mt][nt], af[mt], bf[nt]);
        }
        buf = (buf + 1 == 3) ? 0 : buf + 1;
    }

    #pragma unroll
    for (int mt = 0; mt < 4; mt++) {
        int r0 = row0 + wm * 64 + mt * 16 + g;
        int r1 = r0 + 8;
        #pragma unroll
        for (int nt = 0; nt < 4; nt++) {
            int c = col0 + wn * 32 + nt * 8 + 2 * t;
            float b0v = bias ? bias[c] : 0.f;
            float b1v = bias ? bias[c + 1] : 0.f;
            float v[4] = {acc[mt][nt][0] + b0v, acc[mt][nt][1] + b1v,
                          acc[mt][nt][2] + b0v, acc[mt][nt][3] + b1v};
            if (act == 1) {
                #pragma unroll
                for (int q = 0; q < 4; q++) v[q] = fmaxf(v[q], 0.f);
            }
            if (C) {
                *reinterpret_cast<float2*>(C + (size_t)r0 * ldc + c) = make_float2(v[0], v[1]);
                *reinterpret_cast<float2*>(C + (size_t)r1 * ldc + c) = make_float2(v[2], v[3]);
            }
            if (C2) {
                __nv_bfloat162 p0, p1;
                p0.x = __float2bfloat16_rn(v[0]); p0.y = __float2bfloat16_rn(v[1]);
                p1.x = __float2bfloat16_rn(v[2]); p1.y = __float2bfloat16_rn(v[3]);
                *reinterpret_cast<__nv_bfloat162*>(C2 + (size_t)r0 * ldc + c) = p0;
                *reinterpret_cast<__nv_bfloat162*>(C2 + (size_t)r1 * ldc + c) = p1;
            }
        }
    }
}

// ---------------- prep kernels ----------------
// multi-array tf32 rounder: blockIdx.z selects {wproj, wout, wmap, wrp}
__global__ void round_weights_kernel(
    const float* __restrict__ s0, float* __restrict__ d0, int n0,
    const float* __restrict__ s1, float* __restrict__ d1, int n1,
    const float* __restrict__ s2, float* __restrict__ d2, int n2,
    const float* __restrict__ s3, float* __restrict__ d3, int n3)
{
    const float* src; float* dst; int n4;
    switch (blockIdx.z) {
        case 0: src = s0; dst = d0; n4 = n0; break;
        case 1: src = s1; dst = d1; n4 = n1; break;
        case 2: src = s2; dst = d2; n4 = n2; break;
        default: src = s3; dst = d3; n4 = n3; break;
    }
    int i = blockIdx.x * blockDim.x + threadIdx.x;
    if (i >= n4) return;
    float4 v = reinterpret_cast<const float4*>(src)[i];
    v.x = round_tf32f(v.x); v.y = round_tf32f(v.y);
    v.z = round_tf32f(v.z); v.w = round_tf32f(v.w);
    reinterpret_cast<float4*>(dst)[i] = v;
}

__global__ void prep_x_kernel(const float* __restrict__ src, float* __restrict__ xt,
                              __nv_bfloat16* __restrict__ hi, __nv_bfloat16* __restrict__ lo,
                              int n4) {
    int i = blockIdx.x * blockDim.x + threadIdx.x;
    if (i >= n4) return;
    float4 v = reinterpret_cast<const float4*>(src)[i];
    float4 r;
    r.x = round_tf32f(v.x); r.y = round_tf32f(v.y);
    r.z = round_tf32f(v.z); r.w = round_tf32f(v.w);
    reinterpret_cast<float4*>(xt)[i] = r;
    __nv_bfloat162 h0, h1, l0, l1;
    h0.x = __float2bfloat16_rn(v.x); l0.x = __float2bfloat16_rn(v.x - __bfloat162float(h0.x));
    h0.y = __float2bfloat16_rn(v.y); l0.y = __float2bfloat16_rn(v.y - __bfloat162float(h0.y));
    h1.x = __float2bfloat16_rn(v.z); l1.x = __float2bfloat16_rn(v.z - __bfloat162float(h1.x));
    h1.y = __float2bfloat16_rn(v.w); l1.y = __float2bfloat16_rn(v.w - __bfloat162float(h1.y));
    reinterpret_cast<__nv_bfloat162*>(hi)[2 * i] = h0;
    reinterpret_cast<__nv_bfloat162*>(hi)[2 * i + 1] = h1;
    reinterpret_cast<__nv_bfloat162*>(lo)[2 * i] = l0;
    reinterpret_cast<__nv_bfloat162*>(lo)[2 * i + 1] = l1;
}

__global__ void split_bf16_kernel(const float* __restrict__ src, __nv_bfloat16* __restrict__ hi,
                                  __nv_bfloat16* __restrict__ lo, int n) {
    int i = blockIdx.x * blockDim.x + threadIdx.x;
    if (i >= n) return;
    float v = src[i];
    __nv_bfloat16 h = __float2bfloat16_rn(v);
    hi[i] = h;
    lo[i] = __float2bfloat16_rn(v - __bfloat162float(h));
}

__global__ void round_bf16_kernel(const float* __restrict__ src, __nv_bfloat16* __restrict__ dst, int n) {
    int i = blockIdx.x * blockDim.x + threadIdx.x;
    if (i >= n) return;
    dst[i] = __float2bfloat16_rn(src[i]);
}

__global__ void repack_convw(const float* __restrict__ cw, float* __restrict__ out) {
    int idx = blockIdx.x * blockDim.x + threadIdx.x;
    const int total = NDIL * 3 * HDIM * HDIM;
    if (idx >= total) return;
    int hi = idx & (HDIM - 1);
    int t = idx >> 10;
    int ho = t & (HDIM - 1);
    int t2 = t >> 10;
    int k = t2 % 3;
    int d = t2 / 3;
    out[idx] = round_tf32f(cw[(((size_t)d * HDIM + ho) * HDIM + hi) * 3 + k]);
}

__global__ void zero_usage(float* usage) {
    int i = blockIdx.x * blockDim.x + threadIdx.x;
    if (i < PDIM) usage[i] = 0.f;
}

// ---------------- top-8 (bf16 logits) + fp32 rescore + exact top-2 ----------------
__device__ __forceinline__ bool better(float va, int ia, float vb, int ib) {
    return (va > vb) || (va == vb && ia < ib);
}
__device__ __forceinline__ void ins2(float& v1, int& i1, float& v2, int& i2, float v, int i) {
    if (better(v, i, v1, i1)) { v2 = v1; i2 = i1; v1 = v; i1 = i; }
    else if (better(v, i, v2, i2)) { v2 = v; i2 = i; }
}

__global__ void __launch_bounds__(256) topk_rescore_kernel(
    const __nv_bfloat16* __restrict__ logits, const float* __restrict__ inter,
    const float* __restrict__ w2, const float* __restrict__ b2,
    const float* __restrict__ tpool, const float* __restrict__ temp_p,
    float* __restrict__ combined, float* __restrict__ usage)
{
    int gw = (blockIdx.x * blockDim.x + threadIdx.x) >> 5;
    int lane = threadIdx.x & 31;
    if (gw >= NTOK) return;
    float temp = fminf(fmaxf(*temp_p, 0.1f), 5.0f);
    float invt = 1.f / temp;

    const __nv_bfloat16* lrow = logits + (size_t)gw * PDIM;
    float tv[8]; int ti[8];
    #pragma unroll
    for (int k = 0; k < 8; k++) { tv[k] = -FLT_MAX; ti[k] = 0x3fffffff; }
    auto push = [&](float v, int j) {
        if (better(v, j, tv[7], ti[7])) {
            tv[7] = v; ti[7] = j;
            #pragma unroll
            for (int k = 7; k > 0; k--) {
                bool sw = better(tv[k], ti[k], tv[k - 1], ti[k - 1]);
                float av = sw ? tv[k] : tv[k - 1];
                float bv2 = sw ? tv[k - 1] : tv[k];
                int ai = sw ? ti[k] : ti[k - 1];
                int bi = sw ? ti[k - 1] : ti[k];
                tv[k - 1] = av; tv[k] = bv2; ti[k - 1] = ai; ti[k] = bi;
            }
        }
    };
    for (int j = lane * 2; j < PDIM; j += 64) {
        __nv_bfloat162 p = *reinterpret_cast<const __nv_bfloat162*>(lrow + j);
        push(fminf(fmaxf(__bfloat162float(p.x) * invt, -10.f), 10.f), j);
        push(fminf(fmaxf(__bfloat162float(p.y) * invt, -10.f), 10.f), j + 1);
    }

    int cand[8];
    #pragma unroll
    for (int r = 0; r < 8; r++) {
        float bvv = tv[0]; int bii = ti[0];
        #pragma unroll
        for (int off = 16; off; off >>= 1) {
            float ov = __shfl_xor_sync(0xffffffffu, bvv, off);
            int oi = __shfl_xor_sync(0xffffffffu, bii, off);
            if (better(ov, oi, bvv, bii)) { bvv = ov; bii = oi; }
        }
        cand[r] = bii;
        if (ti[0] == bii) {
            #pragma unroll
            for (int k = 0; k < 7; k++) { tv[k] = tv[k + 1]; ti[k] = ti[k + 1]; }
            tv[7] = -FLT_MAX; ti[7] = 0x3fffffff;
        }
    }

    const float* irow = inter + (size_t)gw * INTER_DIM;
    float xv[32];
    #pragma unroll
    for (int q = 0; q < 32; q++) xv[q] = irow[lane + q * 32];

    float v1 = -FLT_MAX, v2 = -FLT_MAX;
    int i1 = 0x3fffffff, i2 = 0x3fffffff;
    #pragma unroll
    for (int r = 0; r < 8; r++) {
        const float* wrow = w2 + (size_t)cand[r] * INTER_DIM;
        float s = 0.f;
        #pragma unroll
        for (int q = 0; q < 32; q++) s = fmaf(xv[q], wrow[lane + q * 32], s);
        #pragma unroll
        for (int off = 16; off; off >>= 1) s += __shfl_xor_sync(0xffffffffu, s, off);
        float v = fminf(fmaxf((s + b2[cand[r]]) * invt, -10.f), 10.f);
        ins2(v1, i1, v2, i2, v, cand[r]);
    }

    float e = expf(v2 - v1);
    float w1 = 1.f / (1.f + e);
    float w2s = e / (1.f + e);
    if (lane == 0) {
        atomicAdd(&usage[i1], w1);
        atomicAdd(&usage[i2], w2s);
    }
    const float* p1 = tpool + (size_t)i1 * DDIM;
    const float* p2 = tpool + (size_t)i2 * DDIM;
    float* dst = combined + (size_t)gw * (2 * DDIM) + DDIM;
    for (int d = lane; d < DDIM; d += 32)
        dst[d] = round_tf32f(w1 * p1[d] + w2s * p2[d]);
}

// ---------------- layernorm over D=512, writes rounded combined[:, :512] ----------------
__global__ void ln_kernel(const float* __restrict__ proj, const float* __restrict__ g,
                          const float* __restrict__ b, float* __restrict__ combined)
{
    __shared__ float sh[33];
    int n = blockIdx.x;
    const float* row = proj + (size_t)n * DDIM;
    float v[4];
    float s = 0.f;
    #pragma unroll
    for (int j = 0; j < 4; j++) { v[j] = row[threadIdx.x + j * 128]; s += v[j]; }
    float mean = block_reduce_sum(s, sh) * (1.f / DDIM);
    float q = 0.f;
    #pragma unroll
    for (int j = 0; j < 4; j++) { float d = v[j] - mean; q += d * d; }
    float var = block_reduce_sum(q, sh) * (1.f / DDIM);
    float rstd = rsqrtf(var + 1e-5f);
    float* dst = combined + (size_t)n * (2 * DDIM);
    #pragma unroll
    for (int j = 0; j < 4; j++) {
        int idx = threadIdx.x + j * 128;
        dst[idx] = round_tf32f((v[j] - mean) * rstd * g[idx] + b[idx]);
    }
}

// ---------------- gate + final mix ----------------
__global__ void gate_combine(const float* __restrict__ x, const float* __restrict__ wg,
                             const float* __restrict__ bg, const float* __restrict__ local,
                             const float* __restrict__ glob, float* __restrict__ out)
{
    __shared__ float sh[33];
    int n = blockIdx.x;
    const float* xr = x + (size_t)n * HDIM;
    float s = 0.f;
    for (int j = threadIdx.x; j < HDIM; j += 128) s += xr[j] * wg[j];
    float dot = block_reduce_sum(s, sh);
    float g = 1.f / (1.f + expf(-(dot + bg[0])));
    const float* lr = local + (size_t)n * HDIM;
    const float* gr = glob + (size_t)n * HDIM;
    float* orow = out + (size_t)n * HDIM;
    for (int j = threadIdx.x; j < HDIM; j += 128)
        orow[j] = g * lr[j] + (1.f - g) * gr[j];
}

// ---------------- diversity loss ----------------
__global__ void divloss_kernel(const float* __restrict__ usage, float* __restrict__ out) {
    __shared__ float sh[33];
    float s = 0.f;
    for (int j = threadIdx.x; j < PDIM; j += 1024) s += usage[j];
    float total = block_reduce_sum(s, sh);
    float inv = 1.f / (total + 1e-8f);
    float q = 0.f;
    const float ip = 1.f / (float)PDIM;
    for (int j = threadIdx.x; j < PDIM; j += 1024) {
        float f = usage[j] * inv - ip;
        q += f * f;
    }
    float qt = block_reduce_sum(q, sh);
    if (threadIdx.x == 0) out[0] = (qt / (float)PDIM) * 0.01f;
}

// ---------------- host launcher ----------------
extern "C" void kernel_launch(void* const* d_in, const int* in_sizes, int n_in,
                              void* d_out, int out_size)
{
    const float* x      = (const float*)d_in[0];
    const float* tpool  = (const float*)d_in[1];
    const float* w1     = (const float*)d_in[2];
    const float* b1     = (const float*)d_in[3];
    const float* w2     = (const float*)d_in[4];
    const float* b2     = (const float*)d_in[5];
    const float* temp   = (const float*)d_in[6];
    const float* wproj  = (const float*)d_in[7];
    const float* bproj  = (const float*)d_in[8];
    const float* ln_g   = (const float*)d_in[9];
    const float* ln_b   = (const float*)d_in[10];
    const float* wmap   = (const float*)d_in[11];
    const float* bmap   = (const float*)d_in[12];
    const float* conv_w = (const float*)d_in[13];
    const float* conv_b = (const float*)d_in[14];
    const float* wout   = (const float*)d_in[15];
    const float* bout   = (const float*)d_in[16];
    const float* wrp    = (const float*)d_in[17];
    const float* brp    = (const float*)d_in[18];
    const float* wg     = (const float*)d_in[19];
    const float* bg     = (const float*)d_in[20];
    float* out = (float*)d_out;

    float *inter, *concat, *local, *combined, *transf, *glob, *proj;
    float *convwt, *usage, *xt, *wprojt, *woutt, *wmapt, *wrpt;
    __nv_bfloat16 *logitsb, *xhb, *xlb, *w1hb, *w1lb, *w2b, *interb;
    cudaGetSymbolAddress((void**)&inter,    g_inter);
    cudaGetSymbolAddress((void**)&logitsb,  g_logitsb);
    cudaGetSymbolAddress((void**)&concat,   g_concat);
    cudaGetSymbolAddress((void**)&local,    g_local);
    cudaGetSymbolAddress((void**)&combined, g_combined);
    cudaGetSymbolAddress((void**)&transf,   g_transf);
    cudaGetSymbolAddress((void**)&glob,     g_global);
    cudaGetSymbolAddress((void**)&proj,     g_proj);
    cudaGetSymbolAddress((void**)&convwt,   g_convwt);
    cudaGetSymbolAddress((void**)&usage,    g_usage);
    cudaGetSymbolAddress((void**)&xt,       g_xt);
    cudaGetSymbolAddress((void**)&wprojt,   g_wprojt);
    cudaGetSymbolAddress((void**)&woutt,    g_woutt);
    cudaGetSymbolAddress((void**)&wmapt,    g_wmapt);
    cudaGetSymbolAddress((void**)&wrpt,     g_wrpt);
    cudaGetSymbolAddress((void**)&xhb,      g_xhb);
    cudaGetSymbolAddress((void**)&xlb,      g_xlb);
    cudaGetSymbolAddress((void**)&w1hb,     g_w1hb);
    cudaGetSymbolAddress((void**)&w1lb,     g_w1lb);
    cudaGetSymbolAddress((void**)&w2b,      g_w2b);
    cudaGetSymbolAddress((void**)&interb,   g_interb);

    const int TF_SMEM = 6 * 128 * TFPAD * sizeof(float);          // 110592 B
    const int BF_SMEM = 6 * 128 * HPAD * sizeof(__nv_bfloat16);   // 61440 B
    cudaFuncSetAttribute(gemm_tf32<0>, cudaFuncAttributeMaxDynamicSharedMemorySize, TF_SMEM);
    cudaFuncSetAttribute(gemm_tf32<1>, cudaFuncAttributeMaxDynamicSharedMemorySize, TF_SMEM);
    cudaFuncSetAttribute(gemm_tf32<2>, cudaFuncAttributeMaxDynamicSharedMemorySize, TF_SMEM);
    cudaFuncSetAttribute(gemm_bf16k<0>, cudaFuncAttributeMaxDynamicSharedMemorySize, BF_SMEM);
    cudaFuncSetAttribute(gemm_bf16k<2>, cudaFuncAttributeMaxDynamicSharedMemorySize, BF_SMEM);

    // ---- prep ----
    const int total_cw = NDIL * 3 * HDIM * HDIM;
    repack_convw<<<(total_cw + 255) / 256, 256>>>(conv_w, convwt);
    zero_usage<<<(PDIM + 255) / 256, 256>>>(usage);
    prep_x_kernel<<<(NTOK * HDIM / 4 + 255) / 256, 256>>>(x, xt, xhb, xlb, NTOK * HDIM / 4);
    {
        // fused rounding of 4 weight matrices (z selects array)
        int n0 = DDIM * HDIM / 4, n1 = HDIM * 3 * HDIM / 4;
        int n2 = DDIM * 2 * DDIM / 4, n3 = HDIM * DDIM / 4;
        int nmax = n1;  // largest
        round_weights_kernel<<<dim3((nmax + 255) / 256, 1, 4), 256>>>(
            wproj, wprojt, n0, wout, woutt, n1, wmap, wmapt, n2, wrp, wrpt, n3);
    }
    split_bf16_kernel<<<(INTER_DIM * HDIM + 255) / 256, 256>>>(w1, w1hb, w1lb, INTER_DIM * HDIM);
    round_bf16_kernel<<<((int)((size_t)PDIM * INTER_DIM) + 255) / 256, 256>>>(
        w2, w2b, PDIM * INTER_DIM);

    // ---- router inter: 3xBF16 split, relu; dual write fp32 + bf16 ----
    gemm_bf16k<2><<<dim3(INTER_DIM / 128, NTOK / 128), 256, BF_SMEM>>>(
        xhb, xlb, w1hb, w1lb, b1, inter, interb, 3 * HDIM, INTER_DIM, 1);

    // ---- logits: single bf16, bf16 output (top-8 screen only) ----
    gemm_bf16k<0><<<dim3(PDIM / 128, NTOK / 128), 256, BF_SMEM>>>(
        interb, nullptr, w2b, nullptr, b2, nullptr, logitsb, INTER_DIM, PDIM, 0);

    topk_rescore_kernel<<<(NTOK * 32 + 255) / 256, 256>>>(
        logitsb, inter, w2, b2, tpool, temp, combined, usage);

    // ---- fused: dilated convs (z=0..2) + projected_x (z=3) ----
    gemm_tf32<1><<<dim3(HDIM / 128, NTOK / 128, NDIL + 1), 256, TF_SMEM>>>(
        xt, convwt, conv_b, concat, 3 * HDIM, 3 * HDIM, 0, 2, 1,
        xt, wprojt, bproj, proj, HDIM, DDIM, 0, 0, DDIM / 128);

    ln_kernel<<<NTOK, 128>>>(proj, ln_g, ln_b, combined);

    // ---- fused: local out (z=0) + transformation/map (z=1, rounded) ----
    gemm_tf32<2><<<dim3(HDIM / 128, NTOK / 128, 2), 256, TF_SMEM>>>(
        concat, woutt, bout, local, 3 * HDIM, HDIM, 0, 0, 0,
        combined, wmapt, bmap, transf, 2 * DDIM, DDIM, 0, 1, DDIM / 128);

    // ---- global out ----
    gemm_tf32<0><<<dim3(HDIM / 128, NTOK / 128), 256, TF_SMEM>>>(
        transf, wrpt, brp, glob, DDIM, HDIM, 0, 0, 0,
        nullptr, nullptr, nullptr, nullptr, 0, 0, 0, 0, 0);

    // gate + mix -> out
    gate_combine<<<NTOK, 128>>>(x, wg, bg, local, glob, out);

    // diversity loss -> last output element
    if (out_size > NTOK * HDIM)
        divloss_kernel<<<1, 1024>>>(usage, out + (size_t)NTOK * HDIM);
}

// round 12
// speedup vs baseline: 1.1157x; 1.0377x over previous
#include <cuda_runtime.h>
#include <cuda_bf16.h>
#include <cstdint>
#include <float.h>

// ---------------- problem constants ----------------
#define BDIM 4
#define SDIM 4096
#define HDIM 1024
#define PDIM 4096
#define DDIM 512
#define NTOK (BDIM * SDIM)          // 16384
#define INTER_DIM 1024
#define NDIL 3

// ---------------- scratch (device globals; no allocs allowed) ----------------
__device__ float g_inter[NTOK * INTER_DIM];         // near-exact fp32 (rescore)
__device__ __nv_bfloat16 g_logitsb[(size_t)NTOK * PDIM]; // bf16 screen logits
__device__ float g_concat[(size_t)NTOK * 3 * HDIM]; // tf32-rounded GELU out
__device__ float g_local[NTOK * HDIM];
__device__ float g_combined[NTOK * 2 * DDIM];       // tf32-rounded
__device__ float g_transf[NTOK * DDIM];             // tf32-rounded
__device__ float g_global[NTOK * HDIM];
__device__ float g_proj[NTOK * DDIM];
__device__ float g_convwt[NDIL * 3 * HDIM * HDIM];  // repacked + tf32-rounded
__device__ float g_usage[PDIM];
// pre-rounded tf32 operands (continuous paths)
__device__ float g_xt[NTOK * HDIM];                 // tf32(x)
__device__ float g_wprojt[DDIM * HDIM];
__device__ float g_woutt[HDIM * 3 * HDIM];
__device__ float g_wmapt[DDIM * 2 * DDIM];
__device__ float g_wrpt[HDIM * DDIM];
// bf16 router operands
__device__ __nv_bfloat16 g_xhb[NTOK * HDIM];        // hi(x) bf16
__device__ __nv_bfloat16 g_xlb[NTOK * HDIM];        // lo(x) bf16
__device__ __nv_bfloat16 g_w1hb[INTER_DIM * HDIM];
__device__ __nv_bfloat16 g_w1lb[INTER_DIM * HDIM];
__device__ __nv_bfloat16 g_w2b[(size_t)PDIM * INTER_DIM];
__device__ __nv_bfloat16 g_interb[NTOK * INTER_DIM];// bf16(inter) (logits A)

// ---------------- helpers ----------------
__device__ __forceinline__ float block_reduce_sum(float v, float* sh) {
    int tid = threadIdx.x;
    #pragma unroll
    for (int o = 16; o; o >>= 1) v += __shfl_xor_sync(0xffffffffu, v, o);
    if ((tid & 31) == 0) sh[tid >> 5] = v;
    __syncthreads();
    int nw = blockDim.x >> 5;
    float r = (tid < nw) ? sh[tid] : 0.f;
    if (tid < 32) {
        #pragma unroll
        for (int o = 16; o; o >>= 1) r += __shfl_xor_sync(0xffffffffu, r, o);
        if (tid == 0) sh[32] = r;
    }
    __syncthreads();
    float total = sh[32];
    __syncthreads();
    return total;
}

__device__ __forceinline__ unsigned cvt_tf32(float x) {
    unsigned r;
    asm("cvt.rna.tf32.f32 %0, %1;" : "=r"(r) : "f"(x));
    return r;
}
__device__ __forceinline__ float round_tf32f(float x) {
    return __uint_as_float(cvt_tf32(x));
}

__device__ __forceinline__ void mma_tf32(float* c, const unsigned* a, const unsigned* b) {
    asm volatile(
        "mma.sync.aligned.m16n8k8.row.col.f32.tf32.tf32.f32 "
        "{%0,%1,%2,%3}, {%4,%5,%6,%7}, {%8,%9}, {%0,%1,%2,%3};\n"
        : "+f"(c[0]), "+f"(c[1]), "+f"(c[2]), "+f"(c[3])
        : "r"(a[0]), "r"(a[1]), "r"(a[2]), "r"(a[3]), "r"(b[0]), "r"(b[1]));
}

__device__ __forceinline__ void mma_bf16(float* c, const unsigned* a, const unsigned* b) {
    asm volatile(
        "mma.sync.aligned.m16n8k16.row.col.f32.bf16.bf16.f32 "
        "{%0,%1,%2,%3}, {%4,%5,%6,%7}, {%8,%9}, {%0,%1,%2,%3};\n"
        : "+f"(c[0]), "+f"(c[1]), "+f"(c[2]), "+f"(c[3])
        : "r"(a[0]), "r"(a[1]), "r"(a[2]), "r"(a[3]), "r"(b[0]), "r"(b[1]));
}

__device__ __forceinline__ void ldsm_x4(unsigned addr, unsigned& r0, unsigned& r1,
                                        unsigned& r2, unsigned& r3) {
    asm volatile("ldmatrix.sync.aligned.m8n8.x4.shared.b16 {%0,%1,%2,%3}, [%4];"
                 : "=r"(r0), "=r"(r1), "=r"(r2), "=r"(r3) : "r"(addr));
}

__device__ __forceinline__ void cp16(void* dst_smem, const void* src, bool pred) {
    unsigned d = (unsigned)__cvta_generic_to_shared(dst_smem);
    int sz = pred ? 16 : 0;
    asm volatile("cp.async.cg.shared.global [%0], [%1], 16, %2;\n"
                 :: "r"(d), "l"(src), "r"(sz));
}
#define CP_COMMIT() asm volatile("cp.async.commit_group;\n" ::)
#define CP_WAIT1()  asm volatile("cp.async.wait_group 1;\n" ::)

// =====================================================================
// TF32 GEMM (R8 core: BM=BN=128, BK=32, 256 threads, 8 warps,
// warp 64x32, cp.async 3-stage, one __syncthreads per chunk, 2 CTAs/SM).
// MODE 0: plain  C = act(A @ W^T + b)
// MODE 1: conv   A = virtual im2col of x; dil = 1 << blockIdx.z,
//                W/bias/coff offset by blockIdx.z (fused 3-dilation grid).
// =====================================================================
#define TFPAD 36

template<int MODE>
__global__ void __launch_bounds__(256, 2) gemm_tf32(
    const float* __restrict__ A, const float* __restrict__ W,
    const float* __restrict__ bias, float* __restrict__ C,
    int K, int ldc, int coff, int act, int roundC)
{
    extern __shared__ float smem[];
    float* As = smem;                      // [3][128][TFPAD]
    float* Bs = smem + 3 * 128 * TFPAD;    // [3][128][TFPAD]

    int dil = 0;
    if (MODE == 1) {
        int z = blockIdx.z;
        dil = 1 << z;
        W += (size_t)z * 3 * HDIM * HDIM;
        bias += z * HDIM;
        coff += z * HDIM;
    }

    const int tid = threadIdx.x;
    const int lane = tid & 31;
    const int wid = tid >> 5;
    const int wm = wid >> 2;
    const int wn = wid & 3;
    const int g = lane >> 2;
    const int t = lane & 3;
    const int row0 = blockIdx.y * 128;
    const int col0 = blockIdx.x * 128;
    const int KT = K >> 5;

    const unsigned sA = (unsigned)__cvta_generic_to_shared(As);
    const unsigned sB = (unsigned)__cvta_generic_to_shared(Bs);
    const unsigned aBase = sA + (((wm * 64 + (lane & 15)) * TFPAD + ((lane >> 4) & 1) * 4) << 2);
    const unsigned bBase = sB + (((wn * 32 + (lane & 7) + ((lane >> 4) & 1) * 8) * TFPAD
                                  + ((lane >> 3) & 1) * 4) << 2);
    const unsigned BUFO = 128 * TFPAD * 4;

    float acc[4][4][4];
    #pragma unroll
    for (int i = 0; i < 4; i++)
        #pragma unroll
        for (int j = 0; j < 4; j++)
            #pragma unroll
            for (int q = 0; q < 4; q++) acc[i][j][q] = 0.f;

    auto load_tile = [&](int kt, int buf) {
        int k0 = kt << 5;
        int ksl = 0, h0 = k0, shift = 0;
        if (MODE == 1) {
            ksl = k0 >> 10;
            h0 = k0 & (HDIM - 1);
            shift = (ksl - 1) * dil;
        }
        float* Ad = As + buf * 128 * TFPAD;
        float* Bd = Bs + buf * 128 * TFPAD;
        #pragma unroll
        for (int i = 0; i < 4; i++) {
            int idx = tid + i * 256;
            int r = idx >> 3;
            int c4 = (idx & 7) << 2;
            const float* srcA;
            bool pred = true;
            if (MODE == 1) {
                int n = row0 + r;
                int s2 = (n & (SDIM - 1)) + shift;
                pred = ((unsigned)s2 < (unsigned)SDIM);
                srcA = pred ? (A + (size_t)(n + shift) * HDIM + h0 + c4) : A;
            } else {
                srcA = A + (size_t)(row0 + r) * K + k0 + c4;
            }
            cp16(Ad + r * TFPAD + c4, srcA, pred);
            const float* srcB;
            if (MODE == 1)
                srcB = W + ((size_t)ksl * HDIM + col0 + r) * HDIM + h0 + c4;
            else
                srcB = W + (size_t)(col0 + r) * K + k0 + c4;
            cp16(Bd + r * TFPAD + c4, srcB, true);
        }
    };

    load_tile(0, 0); CP_COMMIT();
    if (KT > 1) load_tile(1, 1);
    CP_COMMIT();

    int buf = 0;
    for (int kt = 0; kt < KT; kt++) {
        CP_WAIT1();
        __syncthreads();
        if (kt + 2 < KT) load_tile(kt + 2, (buf + 2 >= 3) ? buf - 1 : buf + 2);
        CP_COMMIT();

        const unsigned aB = aBase + buf * BUFO;
        const unsigned bB = bBase + buf * BUFO;
        #pragma unroll
        for (int kk = 0; kk < 4; kk++) {
            unsigned af[4][4], bf[4][2];
            #pragma unroll
            for (int p = 0; p < 2; p++)
                ldsm_x4(bB + p * (16 * TFPAD * 4) + kk * 32,
                        bf[2 * p][0], bf[2 * p][1], bf[2 * p + 1][0], bf[2 * p + 1][1]);
            #pragma unroll
            for (int mt = 0; mt < 4; mt++)
                ldsm_x4(aB + mt * (16 * TFPAD * 4) + kk * 32,
                        af[mt][0], af[mt][1], af[mt][2], af[mt][3]);
            #pragma unroll
            for (int mt = 0; mt < 4; mt++)
                #pragma unroll
                for (int nt = 0; nt < 4; nt++)
                    mma_tf32(acc[mt][nt], af[mt], bf[nt]);
        }
        buf = (buf + 1 == 3) ? 0 : buf + 1;
    }

    #pragma unroll
    for (int mt = 0; mt < 4; mt++) {
        int r0 = row0 + wm * 64 + mt * 16 + g;
        int r1 = r0 + 8;
        #pragma unroll
        for (int nt = 0; nt < 4; nt++) {
            int c = col0 + wn * 32 + nt * 8 + 2 * t;
            float b0v = bias ? bias[c] : 0.f;
            float b1v = bias ? bias[c + 1] : 0.f;
            float v[4] = {acc[mt][nt][0] + b0v, acc[mt][nt][1] + b1v,
                          acc[mt][nt][2] + b0v, acc[mt][nt][3] + b1v};
            if (act == 2) {
                #pragma unroll
                for (int q = 0; q < 4; q++)
                    v[q] = 0.5f * v[q] * (1.f + erff(v[q] * 0.70710678118654752f));
            } else if (act == 1) {
                #pragma unroll
                for (int q = 0; q < 4; q++) v[q] = fmaxf(v[q], 0.f);
            }
            if (roundC) {
                #pragma unroll
                for (int q = 0; q < 4; q++) v[q] = round_tf32f(v[q]);
            }
            *reinterpret_cast<float2*>(C + (size_t)r0 * ldc + coff + c) = make_float2(v[0], v[1]);
            *reinterpret_cast<float2*>(C + (size_t)r1 * ldc + coff + c) = make_float2(v[2], v[3]);
        }
    }
}

// =====================================================================
// BF16 GEMM (router, R8 core unchanged).
// MODE 0: plain. MODE 2: 3xBF16 virtual K=3072.
// =====================================================================
#define HPAD 40

template<int MODE>
__global__ void __launch_bounds__(256, 2) gemm_bf16k(
    const __nv_bfloat16* __restrict__ A, const __nv_bfloat16* __restrict__ Alo,
    const __nv_bfloat16* __restrict__ W, const __nv_bfloat16* __restrict__ Wlo,
    const float* __restrict__ bias, float* __restrict__ C, __nv_bfloat16* __restrict__ C2,
    int K, int ldc, int act)
{
    extern __shared__ __nv_bfloat16 hsm[];
    __nv_bfloat16* As = hsm;                   // [3][128][HPAD]
    __nv_bfloat16* Bs = hsm + 3 * 128 * HPAD;

    const int tid = threadIdx.x;
    const int lane = tid & 31;
    const int wid = tid >> 5;
    const int wm = wid >> 2;
    const int wn = wid & 3;
    const int g = lane >> 2;
    const int t = lane & 3;
    const int row0 = blockIdx.y * 128;
    const int col0 = blockIdx.x * 128;
    const int KT = K >> 5;

    const unsigned sA = (unsigned)__cvta_generic_to_shared(As);
    const unsigned sB = (unsigned)__cvta_generic_to_shared(Bs);
    const unsigned aBase = sA + (wm * 64 + (lane & 15)) * (HPAD * 2) + ((lane >> 4) & 1) * 16;
    const unsigned bBase = sB + (wn * 32 + (lane & 7) + ((lane >> 4) & 1) * 8) * (HPAD * 2)
                              + ((lane >> 3) & 1) * 16;
    const unsigned BUFO = 128 * HPAD * 2;

    float acc[4][4][4];
    #pragma unroll
    for (int i = 0; i < 4; i++)
        #pragma unroll
        for (int j = 0; j < 4; j++)
            #pragma unroll
            for (int q = 0; q < 4; q++) acc[i][j][q] = 0.f;

    auto load_tile = [&](int kt, int buf) {
        int k0 = kt << 5;
        int ksl = 0, h0 = k0;
        if (MODE == 2) { ksl = k0 >> 10; h0 = k0 & (HDIM - 1); }
        __nv_bfloat16* Ad = As + buf * 128 * HPAD;
        __nv_bfloat16* Bd = Bs + buf * 128 * HPAD;
        #pragma unroll
        for (int i = 0; i < 2; i++) {
            int idx = tid + i * 256;
            int r = idx >> 2;
            int c8 = (idx & 3) << 3;
            const __nv_bfloat16* srcA;
            if (MODE == 2) {
                const __nv_bfloat16* Ab = (ksl == 2) ? Alo : A;
                srcA = Ab + (size_t)(row0 + r) * HDIM + h0 + c8;
            } else {
                srcA = A + (size_t)(row0 + r) * K + k0 + c8;
            }
            cp16(Ad + r * HPAD + c8, srcA, true);
            const __nv_bfloat16* srcB;
            if (MODE == 2) {
                const __nv_bfloat16* Wb = (ksl == 1) ? Wlo : W;
                srcB = Wb + (size_t)(col0 + r) * HDIM + h0 + c8;
            } else {
                srcB = W + (size_t)(col0 + r) * K + k0 + c8;
            }
            cp16(Bd + r * HPAD + c8, srcB, true);
        }
    };

    load_tile(0, 0); CP_COMMIT();
    if (KT > 1) load_tile(1, 1);
    CP_COMMIT();

    int buf = 0;
    for (int kt = 0; kt < KT; kt++) {
        CP_WAIT1();
        __syncthreads();
        if (kt + 2 < KT) load_tile(kt + 2, (buf + 2 >= 3) ? buf - 1 : buf + 2);
        CP_COMMIT();

        const unsigned aB = aBase + buf * BUFO;
        const unsigned bB = bBase + buf * BUFO;
        #pragma unroll
        for (int kk = 0; kk < 2; kk++) {
            unsigned af[4][4], bf[4][2];
            #pragma unroll
            for (int p = 0; p < 2; p++)
                ldsm_x4(bB + p * (16 * HPAD * 2) + kk * 32,
                        bf[2 * p][0], bf[2 * p][1], bf[2 * p + 1][0], bf[2 * p + 1][1]);
            #pragma unroll
            for (int mt = 0; mt < 4; mt++)
                ldsm_x4(aB + mt * (16 * HPAD * 2) + kk * 32,
                        af[mt][0], af[mt][1], af[mt][2], af[mt][3]);
            #pragma unroll
            for (int mt = 0; mt < 4; mt++)
                #pragma unroll
                for (int nt = 0; nt < 4; nt++)
                    mma_bf16(acc[mt][nt], af[mt], bf[nt]);
        }
        buf = (buf + 1 == 3) ? 0 : buf + 1;
    }

    #pragma unroll
    for (int mt = 0; mt < 4; mt++) {
        int r0 = row0 + wm * 64 + mt * 16 + g;
        int r1 = r0 + 8;
        #pragma unroll
        for (int nt = 0; nt < 4; nt++) {
            int c = col0 + wn * 32 + nt * 8 + 2 * t;
            float b0v = bias ? bias[c] : 0.f;
            float b1v = bias ? bias[c + 1] : 0.f;
            float v[4] = {acc[mt][nt][0] + b0v, acc[mt][nt][1] + b1v,
                          acc[mt][nt][2] + b0v, acc[mt][nt][3] + b1v};
            if (act == 1) {
                #pragma unroll
                for (int q = 0; q < 4; q++) v[q] = fmaxf(v[q], 0.f);
            }
            if (C) {
                *reinterpret_cast<float2*>(C + (size_t)r0 * ldc + c) = make_float2(v[0], v[1]);
                *reinterpret_cast<float2*>(C + (size_t)r1 * ldc + c) = make_float2(v[2], v[3]);
            }
            if (C2) {
                __nv_bfloat162 p0, p1;
                p0.x = __float2bfloat16_rn(v[0]); p0.y = __float2bfloat16_rn(v[1]);
                p1.x = __float2bfloat16_rn(v[2]); p1.y = __float2bfloat16_rn(v[3]);
                *reinterpret_cast<__nv_bfloat162*>(C2 + (size_t)r0 * ldc + c) = p0;
                *reinterpret_cast<__nv_bfloat162*>(C2 + (size_t)r1 * ldc + c) = p1;
            }
        }
    }
}

// ---------------- prep kernels ----------------
// multi-array tf32 rounder: blockIdx.z selects {wproj, wout, wmap, wrp}
__global__ void round_weights_kernel(
    const float* __restrict__ s0, float* __restrict__ d0, int n0,
    const float* __restrict__ s1, float* __restrict__ d1, int n1,
    const float* __restrict__ s2, float* __restrict__ d2, int n2,
    const float* __restrict__ s3, float* __restrict__ d3, int n3)
{
    const float* src; float* dst; int n4;
    switch (blockIdx.z) {
        case 0: src = s0; dst = d0; n4 = n0; break;
        case 1: src = s1; dst = d1; n4 = n1; break;
        case 2: src = s2; dst = d2; n4 = n2; break;
        default: src = s3; dst = d3; n4 = n3; break;
    }
    int i = blockIdx.x * blockDim.x + threadIdx.x;
    if (i >= n4) return;
    float4 v = reinterpret_cast<const float4*>(src)[i];
    v.x = round_tf32f(v.x); v.y = round_tf32f(v.y);
    v.z = round_tf32f(v.z); v.w = round_tf32f(v.w);
    reinterpret_cast<float4*>(dst)[i] = v;
}

__global__ void prep_x_kernel(const float* __restrict__ src, float* __restrict__ xt,
                              __nv_bfloat16* __restrict__ hi, __nv_bfloat16* __restrict__ lo,
                              int n4) {
    int i = blockIdx.x * blockDim.x + threadIdx.x;
    if (i >= n4) return;
    float4 v = reinterpret_cast<const float4*>(src)[i];
    float4 r;
    r.x = round_tf32f(v.x); r.y = round_tf32f(v.y);
    r.z = round_tf32f(v.z); r.w = round_tf32f(v.w);
    reinterpret_cast<float4*>(xt)[i] = r;
    __nv_bfloat162 h0, h1, l0, l1;
    h0.x = __float2bfloat16_rn(v.x); l0.x = __float2bfloat16_rn(v.x - __bfloat162float(h0.x));
    h0.y = __float2bfloat16_rn(v.y); l0.y = __float2bfloat16_rn(v.y - __bfloat162float(h0.y));
    h1.x = __float2bfloat16_rn(v.z); l1.x = __float2bfloat16_rn(v.z - __bfloat162float(h1.x));
    h1.y = __float2bfloat16_rn(v.w); l1.y = __float2bfloat16_rn(v.w - __bfloat162float(h1.y));
    reinterpret_cast<__nv_bfloat162*>(hi)[2 * i] = h0;
    reinterpret_cast<__nv_bfloat162*>(hi)[2 * i + 1] = h1;
    reinterpret_cast<__nv_bfloat162*>(lo)[2 * i] = l0;
    reinterpret_cast<__nv_bfloat162*>(lo)[2 * i + 1] = l1;
}

__global__ void split_bf16_kernel(const float* __restrict__ src, __nv_bfloat16* __restrict__ hi,
                                  __nv_bfloat16* __restrict__ lo, int n) {
    int i = blockIdx.x * blockDim.x + threadIdx.x;
    if (i >= n) return;
    float v = src[i];
    __nv_bfloat16 h = __float2bfloat16_rn(v);
    hi[i] = h;
    lo[i] = __float2bfloat16_rn(v - __bfloat162float(h));
}

__global__ void round_bf16_kernel(const float* __restrict__ src, __nv_bfloat16* __restrict__ dst, int n) {
    int i = blockIdx.x * blockDim.x + threadIdx.x;
    if (i >= n) return;
    dst[i] = __float2bfloat16_rn(src[i]);
}

__global__ void repack_convw(const float* __restrict__ cw, float* __restrict__ out) {
    int idx = blockIdx.x * blockDim.x + threadIdx.x;
    const int total = NDIL * 3 * HDIM * HDIM;
    if (idx >= total) return;
    int hi = idx & (HDIM - 1);
    int t = idx >> 10;
    int ho = t & (HDIM - 1);
    int t2 = t >> 10;
    int k = t2 % 3;
    int d = t2 / 3;
    out[idx] = round_tf32f(cw[(((size_t)d * HDIM + ho) * HDIM + hi) * 3 + k]);
}

__global__ void zero_usage(float* usage) {
    int i = blockIdx.x * blockDim.x + threadIdx.x;
    if (i < PDIM) usage[i] = 0.f;
}

// ---------------- top-8 (bf16 logits) + fp32 rescore + exact top-2 ----------------
__device__ __forceinline__ bool better(float va, int ia, float vb, int ib) {
    return (va > vb) || (va == vb && ia < ib);
}
__device__ __forceinline__ void ins2(float& v1, int& i1, float& v2, int& i2, float v, int i) {
    if (better(v, i, v1, i1)) { v2 = v1; i2 = i1; v1 = v; i1 = i; }
    else if (better(v, i, v2, i2)) { v2 = v; i2 = i; }
}

__global__ void __launch_bounds__(256) topk_rescore_kernel(
    const __nv_bfloat16* __restrict__ logits, const float* __restrict__ inter,
    const float* __restrict__ w2, const float* __restrict__ b2,
    const float* __restrict__ tpool, const float* __restrict__ temp_p,
    float* __restrict__ combined, float* __restrict__ usage)
{
    int gw = (blockIdx.x * blockDim.x + threadIdx.x) >> 5;
    int lane = threadIdx.x & 31;
    if (gw >= NTOK) return;
    float temp = fminf(fmaxf(*temp_p, 0.1f), 5.0f);
    float invt = 1.f / temp;

    const __nv_bfloat16* lrow = logits + (size_t)gw * PDIM;
    float tv[8]; int ti[8];
    #pragma unroll
    for (int k = 0; k < 8; k++) { tv[k] = -FLT_MAX; ti[k] = 0x3fffffff; }
    auto push = [&](float v, int j) {
        if (better(v, j, tv[7], ti[7])) {
            tv[7] = v; ti[7] = j;
            #pragma unroll
            for (int k = 7; k > 0; k--) {
                bool sw = better(tv[k], ti[k], tv[k - 1], ti[k - 1]);
                float av = sw ? tv[k] : tv[k - 1];
                float bv2 = sw ? tv[k - 1] : tv[k];
                int ai = sw ? ti[k] : ti[k - 1];
                int bi = sw ? ti[k - 1] : ti[k];
                tv[k - 1] = av; tv[k] = bv2; ti[k - 1] = ai; ti[k] = bi;
            }
        }
    };
    for (int j = lane * 2; j < PDIM; j += 64) {
        __nv_bfloat162 p = *reinterpret_cast<const __nv_bfloat162*>(lrow + j);
        push(fminf(fmaxf(__bfloat162float(p.x) * invt, -10.f), 10.f), j);
        push(fminf(fmaxf(__bfloat162float(p.y) * invt, -10.f), 10.f), j + 1);
    }

    int cand[8];
    #pragma unroll
    for (int r = 0; r < 8; r++) {
        float bvv = tv[0]; int bii = ti[0];
        #pragma unroll
        for (int off = 16; off; off >>= 1) {
            float ov = __shfl_xor_sync(0xffffffffu, bvv, off);
            int oi = __shfl_xor_sync(0xffffffffu, bii, off);
            if (better(ov, oi, bvv, bii)) { bvv = ov; bii = oi; }
        }
        cand[r] = bii;
        if (ti[0] == bii) {
            #pragma unroll
            for (int k = 0; k < 7; k++) { tv[k] = tv[k + 1]; ti[k] = ti[k + 1]; }
            tv[7] = -FLT_MAX; ti[7] = 0x3fffffff;
        }
    }

    const float* irow = inter + (size_t)gw * INTER_DIM;
    float xv[32];
    #pragma unroll
    for (int q = 0; q < 32; q++) xv[q] = irow[lane + q * 32];

    float v1 = -FLT_MAX, v2 = -FLT_MAX;
    int i1 = 0x3fffffff, i2 = 0x3fffffff;
    #pragma unroll
    for (int r = 0; r < 8; r++) {
        const float* wrow = w2 + (size_t)cand[r] * INTER_DIM;
        float s = 0.f;
        #pragma unroll
        for (int q = 0; q < 32; q++) s = fmaf(xv[q], wrow[lane + q * 32], s);
        #pragma unroll
        for (int off = 16; off; off >>= 1) s += __shfl_xor_sync(0xffffffffu, s, off);
        float v = fminf(fmaxf((s + b2[cand[r]]) * invt, -10.f), 10.f);
        ins2(v1, i1, v2, i2, v, cand[r]);
    }

    float e = expf(v2 - v1);
    float w1 = 1.f / (1.f + e);
    float w2s = e / (1.f + e);
    if (lane == 0) {
        atomicAdd(&usage[i1], w1);
        atomicAdd(&usage[i2], w2s);
    }
    const float* p1 = tpool + (size_t)i1 * DDIM;
    const float* p2 = tpool + (size_t)i2 * DDIM;
    float* dst = combined + (size_t)gw * (2 * DDIM) + DDIM;
    for (int d = lane; d < DDIM; d += 32)
        dst[d] = round_tf32f(w1 * p1[d] + w2s * p2[d]);
}

// ---------------- layernorm over D=512, writes rounded combined[:, :512] ----------------
__global__ void ln_kernel(const float* __restrict__ proj, const float* __restrict__ g,
                          const float* __restrict__ b, float* __restrict__ combined)
{
    __shared__ float sh[33];
    int n = blockIdx.x;
    const float* row = proj + (size_t)n * DDIM;
    float v[4];
    float s = 0.f;
    #pragma unroll
    for (int j = 0; j < 4; j++) { v[j] = row[threadIdx.x + j * 128]; s += v[j]; }
    float mean = block_reduce_sum(s, sh) * (1.f / DDIM);
    float q = 0.f;
    #pragma unroll
    for (int j = 0; j < 4; j++) { float d = v[j] - mean; q += d * d; }
    float var = block_reduce_sum(q, sh) * (1.f / DDIM);
    float rstd = rsqrtf(var + 1e-5f);
    float* dst = combined + (size_t)n * (2 * DDIM);
    #pragma unroll
    for (int j = 0; j < 4; j++) {
        int idx = threadIdx.x + j * 128;
        dst[idx] = round_tf32f((v[j] - mean) * rstd * g[idx] + b[idx]);
    }
}

// ---------------- gate + final mix ----------------
__global__ void gate_combine(const float* __restrict__ x, const float* __restrict__ wg,
                             const float* __restrict__ bg, const float* __restrict__ local,
                             const float* __restrict__ glob, float* __restrict__ out)
{
    __shared__ float sh[33];
    int n = blockIdx.x;
    const float* xr = x + (size_t)n * HDIM;
    float s = 0.f;
    for (int j = threadIdx.x; j < HDIM; j += 128) s += xr[j] * wg[j];
    float dot = block_reduce_sum(s, sh);
    float g = 1.f / (1.f + expf(-(dot + bg[0])));
    const float* lr = local + (size_t)n * HDIM;
    const float* gr = glob + (size_t)n * HDIM;
    float* orow = out + (size_t)n * HDIM;
    for (int j = threadIdx.x; j < HDIM; j += 128)
        orow[j] = g * lr[j] + (1.f - g) * gr[j];
}

// ---------------- diversity loss ----------------
__global__ void divloss_kernel(const float* __restrict__ usage, float* __restrict__ out) {
    __shared__ float sh[33];
    float s = 0.f;
    for (int j = threadIdx.x; j < PDIM; j += 1024) s += usage[j];
    float total = block_reduce_sum(s, sh);
    float inv = 1.f / (total + 1e-8f);
    float q = 0.f;
    const float ip = 1.f / (float)PDIM;
    for (int j = threadIdx.x; j < PDIM; j += 1024) {
        float f = usage[j] * inv - ip;
        q += f * f;
    }
    float qt = block_reduce_sum(q, sh);
    if (threadIdx.x == 0) out[0] = (qt / (float)PDIM) * 0.01f;
}

// ---------------- host launcher ----------------
extern "C" void kernel_launch(void* const* d_in, const int* in_sizes, int n_in,
                              void* d_out, int out_size)
{
    const float* x      = (const float*)d_in[0];
    const float* tpool  = (const float*)d_in[1];
    const float* w1     = (const float*)d_in[2];
    const float* b1     = (const float*)d_in[3];
    const float* w2     = (const float*)d_in[4];
    const float* b2     = (const float*)d_in[5];
    const float* temp   = (const float*)d_in[6];
    const float* wproj  = (const float*)d_in[7];
    const float* bproj  = (const float*)d_in[8];
    const float* ln_g   = (const float*)d_in[9];
    const float* ln_b   = (const float*)d_in[10];
    const float* wmap   = (const float*)d_in[11];
    const float* bmap   = (const float*)d_in[12];
    const float* conv_w = (const float*)d_in[13];
    const float* conv_b = (const float*)d_in[14];
    const float* wout   = (const float*)d_in[15];
    const float* bout   = (const float*)d_in[16];
    const float* wrp    = (const float*)d_in[17];
    const float* brp    = (const float*)d_in[18];
    const float* wg     = (const float*)d_in[19];
    const float* bg     = (const float*)d_in[20];
    float* out = (float*)d_out;

    float *inter, *concat, *local, *combined, *transf, *glob, *proj;
    float *convwt, *usage, *xt, *wprojt, *woutt, *wmapt, *wrpt;
    __nv_bfloat16 *logitsb, *xhb, *xlb, *w1hb, *w1lb, *w2b, *interb;
    cudaGetSymbolAddress((void**)&inter,    g_inter);
    cudaGetSymbolAddress((void**)&logitsb,  g_logitsb);
    cudaGetSymbolAddress((void**)&concat,   g_concat);
    cudaGetSymbolAddress((void**)&local,    g_local);
    cudaGetSymbolAddress((void**)&combined, g_combined);
    cudaGetSymbolAddress((void**)&transf,   g_transf);
    cudaGetSymbolAddress((void**)&glob,     g_global);
    cudaGetSymbolAddress((void**)&proj,     g_proj);
    cudaGetSymbolAddress((void**)&convwt,   g_convwt);
    cudaGetSymbolAddress((void**)&usage,    g_usage);
    cudaGetSymbolAddress((void**)&xt,       g_xt);
    cudaGetSymbolAddress((void**)&wprojt,   g_wprojt);
    cudaGetSymbolAddress((void**)&woutt,    g_woutt);
    cudaGetSymbolAddress((void**)&wmapt,    g_wmapt);
    cudaGetSymbolAddress((void**)&wrpt,     g_wrpt);
    cudaGetSymbolAddress((void**)&xhb,      g_xhb);
    cudaGetSymbolAddress((void**)&xlb,      g_xlb);
    cudaGetSymbolAddress((void**)&w1hb,     g_w1hb);
    cudaGetSymbolAddress((void**)&w1lb,     g_w1lb);
    cudaGetSymbolAddress((void**)&w2b,      g_w2b);
    cudaGetSymbolAddress((void**)&interb,   g_interb);

    const int TF_SMEM = 6 * 128 * TFPAD * sizeof(float);          // 110592 B
    const int BF_SMEM = 6 * 128 * HPAD * sizeof(__nv_bfloat16);   // 61440 B
    cudaFuncSetAttribute(gemm_tf32<0>, cudaFuncAttributeMaxDynamicSharedMemorySize, TF_SMEM);
    cudaFuncSetAttribute(gemm_tf32<1>, cudaFuncAttributeMaxDynamicSharedMemorySize, TF_SMEM);
    cudaFuncSetAttribute(gemm_bf16k<0>, cudaFuncAttributeMaxDynamicSharedMemorySize, BF_SMEM);
    cudaFuncSetAttribute(gemm_bf16k<2>, cudaFuncAttributeMaxDynamicSharedMemorySize, BF_SMEM);

    // ---- prep ----
    const int total_cw = NDIL * 3 * HDIM * HDIM;
    repack_convw<<<(total_cw + 255) / 256, 256>>>(conv_w, convwt);
    zero_usage<<<(PDIM + 255) / 256, 256>>>(usage);
    prep_x_kernel<<<(NTOK * HDIM / 4 + 255) / 256, 256>>>(x, xt, xhb, xlb, NTOK * HDIM / 4);
    {
        int n0 = DDIM * HDIM / 4, n1 = HDIM * 3 * HDIM / 4;
        int n2 = DDIM * 2 * DDIM / 4, n3 = HDIM * DDIM / 4;
        round_weights_kernel<<<dim3((n1 + 255) / 256, 1, 4), 256>>>(
            wproj, wprojt, n0, wout, woutt, n1, wmap, wmapt, n2, wrp, wrpt, n3);
    }
    split_bf16_kernel<<<(INTER_DIM * HDIM + 255) / 256, 256>>>(w1, w1hb, w1lb, INTER_DIM * HDIM);
    round_bf16_kernel<<<((int)((size_t)PDIM * INTER_DIM) + 255) / 256, 256>>>(
        w2, w2b, PDIM * INTER_DIM);

    // ---- router inter: 3xBF16 split, relu; dual write fp32 + bf16 ----
    gemm_bf16k<2><<<dim3(INTER_DIM / 128, NTOK / 128), 256, BF_SMEM>>>(
        xhb, xlb, w1hb, w1lb, b1, inter, interb, 3 * HDIM, INTER_DIM, 1);

    // ---- logits: single bf16, bf16 output (top-8 screen only) ----
    gemm_bf16k<0><<<dim3(PDIM / 128, NTOK / 128), 256, BF_SMEM>>>(
        interb, nullptr, w2b, nullptr, b2, nullptr, logitsb, INTER_DIM, PDIM, 0);

    topk_rescore_kernel<<<(NTOK * 32 + 255) / 256, 256>>>(
        logitsb, inter, w2, b2, tpool, temp, combined, usage);

    // ---- projected_x (tf32) -> LN -> combined[:, :512] ----
    gemm_tf32<0><<<dim3(DDIM / 128, NTOK / 128), 256, TF_SMEM>>>(
        xt, wprojt, bproj, proj, HDIM, DDIM, 0, 0, 0);
    ln_kernel<<<NTOK, 128>>>(proj, ln_g, ln_b, combined);

    // ---- dilated convs: single fused launch over blockIdx.z (dil = 1<<z) ----
    gemm_tf32<1><<<dim3(HDIM / 128, NTOK / 128, NDIL), 256, TF_SMEM>>>(
        xt, convwt, conv_b, concat, 3 * HDIM, 3 * HDIM, 0, 2, 1);

    // ---- local out (tf32) ----
    gemm_tf32<0><<<dim3(HDIM / 128, NTOK / 128), 256, TF_SMEM>>>(
        concat, woutt, bout, local, 3 * HDIM, HDIM, 0, 0, 0);

    // ---- transformation (rounded out) + global out (tf32) ----
    gemm_tf32<0><<<dim3(DDIM / 128, NTOK / 128), 256, TF_SMEM>>>(
        combined, wmapt, bmap, transf, 2 * DDIM, DDIM, 0, 0, 1);
    gemm_tf32<0><<<dim3(HDIM / 128, NTOK / 128), 256, TF_SMEM>>>(
        transf, wrpt, brp, glob, DDIM, HDIM, 0, 0, 0);

    // gate + mix -> out
    gate_combine<<<NTOK, 128>>>(x, wg, bg, local, glob, out);

    // diversity loss -> last output element
    if (out_size > NTOK * HDIM)
        divloss_kernel<<<1, 1024>>>(usage, out + (size_t)NTOK * HDIM);
}

// round 13
// speedup vs baseline: 1.1326x; 1.0151x over previous
#include <cuda_runtime.h>
#include <cuda_bf16.h>
#include <cstdint>
#include <float.h>

// ---------------- problem constants ----------------
#define BDIM 4
#define SDIM 4096
#define HDIM 1024
#define PDIM 4096
#define DDIM 512
#define NTOK (BDIM * SDIM)          // 16384
#define INTER_DIM 1024
#define NDIL 3

// ---------------- scratch (device globals; no allocs allowed) ----------------
__device__ float g_inter[NTOK * INTER_DIM];         // near-exact fp32 (rescore)
__device__ __nv_bfloat16 g_logitsb[(size_t)NTOK * PDIM]; // bf16 screen logits
__device__ float g_concat[(size_t)NTOK * 3 * HDIM]; // tf32-rounded GELU out
__device__ float g_local[NTOK * HDIM];
__device__ float g_combined[NTOK * 2 * DDIM];       // tf32-rounded
__device__ float g_transf[NTOK * DDIM];             // tf32-rounded
__device__ float g_global[NTOK * HDIM];
__device__ float g_proj[NTOK * DDIM];
__device__ float g_convwt[NDIL * 3 * HDIM * HDIM];  // repacked + tf32-rounded
__device__ float g_usage[PDIM];
// pre-rounded tf32 operands (continuous paths)
__device__ float g_xt[NTOK * HDIM];                 // tf32(x)
__device__ float g_wprojt[DDIM * HDIM];
__device__ float g_woutt[HDIM * 3 * HDIM];
__device__ float g_wmapt[DDIM * 2 * DDIM];
__device__ float g_wrpt[HDIM * DDIM];
// bf16 router operands
__device__ __nv_bfloat16 g_xhb[NTOK * HDIM];        // hi(x) bf16
__device__ __nv_bfloat16 g_xlb[NTOK * HDIM];        // lo(x) bf16
__device__ __nv_bfloat16 g_w1hb[INTER_DIM * HDIM];
__device__ __nv_bfloat16 g_w1lb[INTER_DIM * HDIM];
__device__ __nv_bfloat16 g_w2b[(size_t)PDIM * INTER_DIM];
__device__ __nv_bfloat16 g_interb[NTOK * INTER_DIM];// bf16(inter) (logits A)

// ---------------- helpers ----------------
__device__ __forceinline__ float block_reduce_sum(float v, float* sh) {
    int tid = threadIdx.x;
    #pragma unroll
    for (int o = 16; o; o >>= 1) v += __shfl_xor_sync(0xffffffffu, v, o);
    if ((tid & 31) == 0) sh[tid >> 5] = v;
    __syncthreads();
    int nw = blockDim.x >> 5;
    float r = (tid < nw) ? sh[tid] : 0.f;
    if (tid < 32) {
        #pragma unroll
        for (int o = 16; o; o >>= 1) r += __shfl_xor_sync(0xffffffffu, r, o);
        if (tid == 0) sh[32] = r;
    }
    __syncthreads();
    float total = sh[32];
    __syncthreads();
    return total;
}

__device__ __forceinline__ unsigned cvt_tf32(float x) {
    unsigned r;
    asm("cvt.rna.tf32.f32 %0, %1;" : "=r"(r) : "f"(x));
    return r;
}
__device__ __forceinline__ float round_tf32f(float x) {
    return __uint_as_float(cvt_tf32(x));
}

__device__ __forceinline__ void mma_tf32(float* c, const unsigned* a, const unsigned* b) {
    asm volatile(
        "mma.sync.aligned.m16n8k8.row.col.f32.tf32.tf32.f32 "
        "{%0,%1,%2,%3}, {%4,%5,%6,%7}, {%8,%9}, {%0,%1,%2,%3};\n"
        : "+f"(c[0]), "+f"(c[1]), "+f"(c[2]), "+f"(c[3])
        : "r"(a[0]), "r"(a[1]), "r"(a[2]), "r"(a[3]), "r"(b[0]), "r"(b[1]));
}

__device__ __forceinline__ void mma_bf16(float* c, const unsigned* a, const unsigned* b) {
    asm volatile(
        "mma.sync.aligned.m16n8k16.row.col.f32.bf16.bf16.f32 "
        "{%0,%1,%2,%3}, {%4,%5,%6,%7}, {%8,%9}, {%0,%1,%2,%3};\n"
        : "+f"(c[0]), "+f"(c[1]), "+f"(c[2]), "+f"(c[3])
        : "r"(a[0]), "r"(a[1]), "r"(a[2]), "r"(a[3]), "r"(b[0]), "r"(b[1]));
}

__device__ __forceinline__ void ldsm_x4(unsigned addr, unsigned& r0, unsigned& r1,
                                        unsigned& r2, unsigned& r3) {
    asm volatile("ldmatrix.sync.aligned.m8n8.x4.shared.b16 {%0,%1,%2,%3}, [%4];"
                 : "=r"(r0), "=r"(r1), "=r"(r2), "=r"(r3) : "r"(addr));
}

__device__ __forceinline__ void cp16(void* dst_smem, const void* src, bool pred) {
    unsigned d = (unsigned)__cvta_generic_to_shared(dst_smem);
    int sz = pred ? 16 : 0;
    asm volatile("cp.async.cg.shared.global [%0], [%1], 16, %2;\n"
                 :: "r"(d), "l"(src), "r"(sz));
}
#define CP_COMMIT() asm volatile("cp.async.commit_group;\n" ::)
#define CP_WAIT1()  asm volatile("cp.async.wait_group 1;\n" ::)

// =====================================================================
// TF32 GEMM (R8 core: BM=BN=128, BK=32, 256 threads, 8 warps,
// warp 64x32, cp.async 3-stage, one __syncthreads per chunk, 2 CTAs/SM).
// MODE 0: plain  C = act(A @ W^T + b)
// MODE 1: conv   A = virtual im2col of x; dil = 1 << blockIdx.z,
//                W/bias/coff offset by blockIdx.z (fused 3-dilation grid).
// =====================================================================
#define TFPAD 36

template<int MODE>
__global__ void __launch_bounds__(256, 2) gemm_tf32(
    const float* __restrict__ A, const float* __restrict__ W,
    const float* __restrict__ bias, float* __restrict__ C,
    int K, int ldc, int coff, int act, int roundC)
{
    extern __shared__ float smem[];
    float* As = smem;                      // [3][128][TFPAD]
    float* Bs = smem + 3 * 128 * TFPAD;    // [3][128][TFPAD]

    int dil = 0;
    if (MODE == 1) {
        int z = blockIdx.z;
        dil = 1 << z;
        W += (size_t)z * 3 * HDIM * HDIM;
        bias += z * HDIM;
        coff += z * HDIM;
    }

    const int tid = threadIdx.x;
    const int lane = tid & 31;
    const int wid = tid >> 5;
    const int wm = wid >> 2;
    const int wn = wid & 3;
    const int g = lane >> 2;
    const int t = lane & 3;
    const int row0 = blockIdx.y * 128;
    const int col0 = blockIdx.x * 128;
    const int KT = K >> 5;

    const unsigned sA = (unsigned)__cvta_generic_to_shared(As);
    const unsigned sB = (unsigned)__cvta_generic_to_shared(Bs);
    const unsigned aBase = sA + (((wm * 64 + (lane & 15)) * TFPAD + ((lane >> 4) & 1) * 4) << 2);
    const unsigned bBase = sB + (((wn * 32 + (lane & 7) + ((lane >> 4) & 1) * 8) * TFPAD
                                  + ((lane >> 3) & 1) * 4) << 2);
    const unsigned BUFO = 128 * TFPAD * 4;

    float acc[4][4][4];
    #pragma unroll
    for (int i = 0; i < 4; i++)
        #pragma unroll
        for (int j = 0; j < 4; j++)
            #pragma unroll
            for (int q = 0; q < 4; q++) acc[i][j][q] = 0.f;

    auto load_tile = [&](int kt, int buf) {
        int k0 = kt << 5;
        int ksl = 0, h0 = k0, shift = 0;
        if (MODE == 1) {
            ksl = k0 >> 10;
            h0 = k0 & (HDIM - 1);
            shift = (ksl - 1) * dil;
        }
        float* Ad = As + buf * 128 * TFPAD;
        float* Bd = Bs + buf * 128 * TFPAD;
        #pragma unroll
        for (int i = 0; i < 4; i++) {
            int idx = tid + i * 256;
            int r = idx >> 3;
            int c4 = (idx & 7) << 2;
            const float* srcA;
            bool pred = true;
            if (MODE == 1) {
                int n = row0 + r;
                int s2 = (n & (SDIM - 1)) + shift;
                pred = ((unsigned)s2 < (unsigned)SDIM);
                srcA = pred ? (A + (size_t)(n + shift) * HDIM + h0 + c4) : A;
            } else {
                srcA = A + (size_t)(row0 + r) * K + k0 + c4;
            }
            cp16(Ad + r * TFPAD + c4, srcA, pred);
            const float* srcB;
            if (MODE == 1)
                srcB = W + ((size_t)ksl * HDIM + col0 + r) * HDIM + h0 + c4;
            else
                srcB = W + (size_t)(col0 + r) * K + k0 + c4;
            cp16(Bd + r * TFPAD + c4, srcB, true);
        }
    };

    load_tile(0, 0); CP_COMMIT();
    if (KT > 1) load_tile(1, 1);
    CP_COMMIT();

    int buf = 0;
    for (int kt = 0; kt < KT; kt++) {
        CP_WAIT1();
        __syncthreads();
        if (kt + 2 < KT) load_tile(kt + 2, (buf + 2 >= 3) ? buf - 1 : buf + 2);
        CP_COMMIT();

        const unsigned aB = aBase + buf * BUFO;
        const unsigned bB = bBase + buf * BUFO;
        #pragma unroll
        for (int kk = 0; kk < 4; kk++) {
            unsigned af[4][4], bf[4][2];
            #pragma unroll
            for (int p = 0; p < 2; p++)
                ldsm_x4(bB + p * (16 * TFPAD * 4) + kk * 32,
                        bf[2 * p][0], bf[2 * p][1], bf[2 * p + 1][0], bf[2 * p + 1][1]);
            #pragma unroll
            for (int mt = 0; mt < 4; mt++)
                ldsm_x4(aB + mt * (16 * TFPAD * 4) + kk * 32,
                        af[mt][0], af[mt][1], af[mt][2], af[mt][3]);
            #pragma unroll
            for (int mt = 0; mt < 4; mt++)
                #pragma unroll
                for (int nt = 0; nt < 4; nt++)
                    mma_tf32(acc[mt][nt], af[mt], bf[nt]);
        }
        buf = (buf + 1 == 3) ? 0 : buf + 1;
    }

    #pragma unroll
    for (int mt = 0; mt < 4; mt++) {
        int r0 = row0 + wm * 64 + mt * 16 + g;
        int r1 = r0 + 8;
        #pragma unroll
        for (int nt = 0; nt < 4; nt++) {
            int c = col0 + wn * 32 + nt * 8 + 2 * t;
            float b0v = bias ? bias[c] : 0.f;
            float b1v = bias ? bias[c + 1] : 0.f;
            float v[4] = {acc[mt][nt][0] + b0v, acc[mt][nt][1] + b1v,
                          acc[mt][nt][2] + b0v, acc[mt][nt][3] + b1v};
            if (act == 2) {
                #pragma unroll
                for (int q = 0; q < 4; q++)
                    v[q] = 0.5f * v[q] * (1.f + erff(v[q] * 0.70710678118654752f));
            } else if (act == 1) {
                #pragma unroll
                for (int q = 0; q < 4; q++) v[q] = fmaxf(v[q], 0.f);
            }
            if (roundC) {
                #pragma unroll
                for (int q = 0; q < 4; q++) v[q] = round_tf32f(v[q]);
            }
            *reinterpret_cast<float2*>(C + (size_t)r0 * ldc + coff + c) = make_float2(v[0], v[1]);
            *reinterpret_cast<float2*>(C + (size_t)r1 * ldc + coff + c) = make_float2(v[2], v[3]);
        }
    }
}

// =====================================================================
// BF16 GEMM (router). BK=64 halves (128 B/row = 4 k16 slabs per chunk,
// matching the tf32 kernel's per-chunk intensity). HPAD=72 (144 B row
// stride, ldsm conflict-free: 72*2 mod 128 -> banks 4r mod 32).
// MODE 0: plain. MODE 2: 3xBF16 virtual K=3072.
// =====================================================================
#define HPAD 72

template<int MODE>
__global__ void __launch_bounds__(256, 2) gemm_bf16k(
    const __nv_bfloat16* __restrict__ A, const __nv_bfloat16* __restrict__ Alo,
    const __nv_bfloat16* __restrict__ W, const __nv_bfloat16* __restrict__ Wlo,
    const float* __restrict__ bias, float* __restrict__ C, __nv_bfloat16* __restrict__ C2,
    int K, int ldc, int act)
{
    extern __shared__ __nv_bfloat16 hsm[];
    __nv_bfloat16* As = hsm;                   // [3][128][HPAD]
    __nv_bfloat16* Bs = hsm + 3 * 128 * HPAD;

    const int tid = threadIdx.x;
    const int lane = tid & 31;
    const int wid = tid >> 5;
    const int wm = wid >> 2;
    const int wn = wid & 3;
    const int g = lane >> 2;
    const int t = lane & 3;
    const int row0 = blockIdx.y * 128;
    const int col0 = blockIdx.x * 128;
    const int KT = K >> 6;          // 64 halves per chunk

    const unsigned sA = (unsigned)__cvta_generic_to_shared(As);
    const unsigned sB = (unsigned)__cvta_generic_to_shared(Bs);
    const unsigned aBase = sA + (wm * 64 + (lane & 15)) * (HPAD * 2) + ((lane >> 4) & 1) * 16;
    const unsigned bBase = sB + (wn * 32 + (lane & 7) + ((lane >> 4) & 1) * 8) * (HPAD * 2)
                              + ((lane >> 3) & 1) * 16;
    const unsigned BUFO = 128 * HPAD * 2;

    float acc[4][4][4];
    #pragma unroll
    for (int i = 0; i < 4; i++)
        #pragma unroll
        for (int j = 0; j < 4; j++)
            #pragma unroll
            for (int q = 0; q < 4; q++) acc[i][j][q] = 0.f;

    auto load_tile = [&](int kt, int buf) {
        int k0 = kt << 6;
        int ksl = 0, h0 = k0;
        if (MODE == 2) { ksl = k0 >> 10; h0 = k0 & (HDIM - 1); }
        __nv_bfloat16* Ad = As + buf * 128 * HPAD;
        __nv_bfloat16* Bd = Bs + buf * 128 * HPAD;
        // 128 rows x 64 halves = 1024 x 8-half(16B) chunks each; 4/thread each
        #pragma unroll
        for (int i = 0; i < 4; i++) {
            int idx = tid + i * 256;
            int r = idx >> 3;
            int c8 = (idx & 7) << 3;
            const __nv_bfloat16* srcA;
            if (MODE == 2) {
                const __nv_bfloat16* Ab = (ksl == 2) ? Alo : A;
                srcA = Ab + (size_t)(row0 + r) * HDIM + h0 + c8;
            } else {
                srcA = A + (size_t)(row0 + r) * K + k0 + c8;
            }
            cp16(Ad + r * HPAD + c8, srcA, true);
            const __nv_bfloat16* srcB;
            if (MODE == 2) {
                const __nv_bfloat16* Wb = (ksl == 1) ? Wlo : W;
                srcB = Wb + (size_t)(col0 + r) * HDIM + h0 + c8;
            } else {
                srcB = W + (size_t)(col0 + r) * K + k0 + c8;
            }
            cp16(Bd + r * HPAD + c8, srcB, true);
        }
    };

    load_tile(0, 0); CP_COMMIT();
    if (KT > 1) load_tile(1, 1);
    CP_COMMIT();

    int buf = 0;
    for (int kt = 0; kt < KT; kt++) {
        CP_WAIT1();
        __syncthreads();
        if (kt + 2 < KT) load_tile(kt + 2, (buf + 2 >= 3) ? buf - 1 : buf + 2);
        CP_COMMIT();

        const unsigned aB = aBase + buf * BUFO;
        const unsigned bB = bBase + buf * BUFO;
        #pragma unroll
        for (int kk = 0; kk < 4; kk++) {   // four k16 slabs per 64-half chunk
            unsigned af[4][4], bf[4][2];
            #pragma unroll
            for (int p = 0; p < 2; p++)
                ldsm_x4(bB + p * (16 * HPAD * 2) + kk * 32,
                        bf[2 * p][0], bf[2 * p][1], bf[2 * p + 1][0], bf[2 * p + 1][1]);
            #pragma unroll
            for (int mt = 0; mt < 4; mt++)
                ldsm_x4(aB + mt * (16 * HPAD * 2) + kk * 32,
                        af[mt][0], af[mt][1], af[mt][2], af[mt][3]);
            #pragma unroll
            for (int mt = 0; mt < 4; mt++)
                #pragma unroll
                for (int nt = 0; nt < 4; nt++)
                    mma_bf16(acc[mt][nt], af[mt], bf[nt]);
        }
        buf = (buf + 1 == 3) ? 0 : buf + 1;
    }

    #pragma unroll
    for (int mt = 0; mt < 4; mt++) {
        int r0 = row0 + wm * 64 + mt * 16 + g;
        int r1 = r0 + 8;
        #pragma unroll
        for (int nt = 0; nt < 4; nt++) {
            int c = col0 + wn * 32 + nt * 8 + 2 * t;
            float b0v = bias ? bias[c] : 0.f;
            float b1v = bias ? bias[c + 1] : 0.f;
            float v[4] = {acc[mt][nt][0] + b0v, acc[mt][nt][1] + b1v,
                          acc[mt][nt][2] + b0v, acc[mt][nt][3] + b1v};
            if (act == 1) {
                #pragma unroll
                for (int q = 0; q < 4; q++) v[q] = fmaxf(v[q], 0.f);
            }
            if (C) {
                *reinterpret_cast<float2*>(C + (size_t)r0 * ldc + c) = make_float2(v[0], v[1]);
                *reinterpret_cast<float2*>(C + (size_t)r1 * ldc + c) = make_float2(v[2], v[3]);
            }
            if (C2) {
                __nv_bfloat162 p0, p1;
                p0.x = __float2bfloat16_rn(v[0]); p0.y = __float2bfloat16_rn(v[1]);
                p1.x = __float2bfloat16_rn(v[2]); p1.y = __float2bfloat16_rn(v[3]);
                *reinterpret_cast<__nv_bfloat162*>(C2 + (size_t)r0 * ldc + c) = p0;
                *reinterpret_cast<__nv_bfloat162*>(C2 + (size_t)r1 * ldc + c) = p1;
            }
        }
    }
}

// ---------------- prep kernels ----------------
__global__ void round_weights_kernel(
    const float* __restrict__ s0, float* __restrict__ d0, int n0,
    const float* __restrict__ s1, float* __restrict__ d1, int n1,
    const float* __restrict__ s2, float* __restrict__ d2, int n2,
    const float* __restrict__ s3, float* __restrict__ d3, int n3)
{
    const float* src; float* dst; int n4;
    switch (blockIdx.z) {
        case 0: src = s0; dst = d0; n4 = n0; break;
        case 1: src = s1; dst = d1; n4 = n1; break;
        case 2: src = s2; dst = d2; n4 = n2; break;
        default: src = s3; dst = d3; n4 = n3; break;
    }
    int i = blockIdx.x * blockDim.x + threadIdx.x;
    if (i >= n4) return;
    float4 v = reinterpret_cast<const float4*>(src)[i];
    v.x = round_tf32f(v.x); v.y = round_tf32f(v.y);
    v.z = round_tf32f(v.z); v.w = round_tf32f(v.w);
    reinterpret_cast<float4*>(dst)[i] = v;
}

__global__ void prep_x_kernel(const float* __restrict__ src, float* __restrict__ xt,
                              __nv_bfloat16* __restrict__ hi, __nv_bfloat16* __restrict__ lo,
                              int n4) {
    int i = blockIdx.x * blockDim.x + threadIdx.x;
    if (i >= n4) return;
    float4 v = reinterpret_cast<const float4*>(src)[i];
    float4 r;
    r.x = round_tf32f(v.x); r.y = round_tf32f(v.y);
    r.z = round_tf32f(v.z); r.w = round_tf32f(v.w);
    reinterpret_cast<float4*>(xt)[i] = r;
    __nv_bfloat162 h0, h1, l0, l1;
    h0.x = __float2bfloat16_rn(v.x); l0.x = __float2bfloat16_rn(v.x - __bfloat162float(h0.x));
    h0.y = __float2bfloat16_rn(v.y); l0.y = __float2bfloat16_rn(v.y - __bfloat162float(h0.y));
    h1.x = __float2bfloat16_rn(v.z); l1.x = __float2bfloat16_rn(v.z - __bfloat162float(h1.x));
    h1.y = __float2bfloat16_rn(v.w); l1.y = __float2bfloat16_rn(v.w - __bfloat162float(h1.y));
    reinterpret_cast<__nv_bfloat162*>(hi)[2 * i] = h0;
    reinterpret_cast<__nv_bfloat162*>(hi)[2 * i + 1] = h1;
    reinterpret_cast<__nv_bfloat162*>(lo)[2 * i] = l0;
    reinterpret_cast<__nv_bfloat162*>(lo)[2 * i + 1] = l1;
}

__global__ void split_bf16_kernel(const float* __restrict__ src, __nv_bfloat16* __restrict__ hi,
                                  __nv_bfloat16* __restrict__ lo, int n) {
    int i = blockIdx.x * blockDim.x + threadIdx.x;
    if (i >= n) return;
    float v = src[i];
    __nv_bfloat16 h = __float2bfloat16_rn(v);
    hi[i] = h;
    lo[i] = __float2bfloat16_rn(v - __bfloat162float(h));
}

__global__ void round_bf16_kernel(const float* __restrict__ src, __nv_bfloat16* __restrict__ dst, int n) {
    int i = blockIdx.x * blockDim.x + threadIdx.x;
    if (i >= n) return;
    dst[i] = __float2bfloat16_rn(src[i]);
}

__global__ void repack_convw(const float* __restrict__ cw, float* __restrict__ out) {
    int idx = blockIdx.x * blockDim.x + threadIdx.x;
    const int total = NDIL * 3 * HDIM * HDIM;
    if (idx >= total) return;
    int hi = idx & (HDIM - 1);
    int t = idx >> 10;
    int ho = t & (HDIM - 1);
    int t2 = t >> 10;
    int k = t2 % 3;
    int d = t2 / 3;
    out[idx] = round_tf32f(cw[(((size_t)d * HDIM + ho) * HDIM + hi) * 3 + k]);
}

__global__ void zero_usage(float* usage) {
    int i = blockIdx.x * blockDim.x + threadIdx.x;
    if (i < PDIM) usage[i] = 0.f;
}

// ---------------- top-8 (bf16 logits) + fp32 rescore + exact top-2 ----------------
__device__ __forceinline__ bool better(float va, int ia, float vb, int ib) {
    return (va > vb) || (va == vb && ia < ib);
}
__device__ __forceinline__ void ins2(float& v1, int& i1, float& v2, int& i2, float v, int i) {
    if (better(v, i, v1, i1)) { v2 = v1; i2 = i1; v1 = v; i1 = i; }
    else if (better(v, i, v2, i2)) { v2 = v; i2 = i; }
}

__global__ void __launch_bounds__(256) topk_rescore_kernel(
    const __nv_bfloat16* __restrict__ logits, const float* __restrict__ inter,
    const float* __restrict__ w2, const float* __restrict__ b2,
    const float* __restrict__ tpool, const float* __restrict__ temp_p,
    float* __restrict__ combined, float* __restrict__ usage)
{
    int gw = (blockIdx.x * blockDim.x + threadIdx.x) >> 5;
    int lane = threadIdx.x & 31;
    if (gw >= NTOK) return;
    float temp = fminf(fmaxf(*temp_p, 0.1f), 5.0f);
    float invt = 1.f / temp;

    const __nv_bfloat16* lrow = logits + (size_t)gw * PDIM;
    float tv[8]; int ti[8];
    #pragma unroll
    for (int k = 0; k < 8; k++) { tv[k] = -FLT_MAX; ti[k] = 0x3fffffff; }
    auto push = [&](float v, int j) {
        if (better(v, j, tv[7], ti[7])) {
            tv[7] = v; ti[7] = j;
            #pragma unroll
            for (int k = 7; k > 0; k--) {
                bool sw = better(tv[k], ti[k], tv[k - 1], ti[k - 1]);
                float av = sw ? tv[k] : tv[k - 1];
                float bv2 = sw ? tv[k - 1] : tv[k];
                int ai = sw ? ti[k] : ti[k - 1];
                int bi = sw ? ti[k - 1] : ti[k];
                tv[k - 1] = av; tv[k] = bv2; ti[k - 1] = ai; ti[k] = bi;
            }
        }
    };
    for (int j = lane * 2; j < PDIM; j += 64) {
        __nv_bfloat162 p = *reinterpret_cast<const __nv_bfloat162*>(lrow + j);
        push(fminf(fmaxf(__bfloat162float(p.x) * invt, -10.f), 10.f), j);
        push(fminf(fmaxf(__bfloat162float(p.y) * invt, -10.f), 10.f), j + 1);
    }

    int cand[8];
    #pragma unroll
    for (int r = 0; r < 8; r++) {
        float bvv = tv[0]; int bii = ti[0];
        #pragma unroll
        for (int off = 16; off; off >>= 1) {
            float ov = __shfl_xor_sync(0xffffffffu, bvv, off);
            int oi = __shfl_xor_sync(0xffffffffu, bii, off);
            if (better(ov, oi, bvv, bii)) { bvv = ov; bii = oi; }
        }
        cand[r] = bii;
        if (ti[0] == bii) {
            #pragma unroll
            for (int k = 0; k < 7; k++) { tv[k] = tv[k + 1]; ti[k] = ti[k + 1]; }
            tv[7] = -FLT_MAX; ti[7] = 0x3fffffff;
        }
    }

    const float* irow = inter + (size_t)gw * INTER_DIM;
    float xv[32];
    #pragma unroll
    for (int q = 0; q < 32; q++) xv[q] = irow[lane + q * 32];

    float v1 = -FLT_MAX, v2 = -FLT_MAX;
    int i1 = 0x3fffffff, i2 = 0x3fffffff;
    #pragma unroll
    for (int r = 0; r < 8; r++) {
        const float* wrow = w2 + (size_t)cand[r] * INTER_DIM;
        float s = 0.f;
        #pragma unroll
        for (int q = 0; q < 32; q++) s = fmaf(xv[q], wrow[lane + q * 32], s);
        #pragma unroll
        for (int off = 16; off; off >>= 1) s += __shfl_xor_sync(0xffffffffu, s, off);
        float v = fminf(fmaxf((s + b2[cand[r]]) * invt, -10.f), 10.f);
        ins2(v1, i1, v2, i2, v, cand[r]);
    }

    float e = expf(v2 - v1);
    float w1 = 1.f / (1.f + e);
    float w2s = e / (1.f + e);
    if (lane == 0) {
        atomicAdd(&usage[i1], w1);
        atomicAdd(&usage[i2], w2s);
    }
    const float* p1 = tpool + (size_t)i1 * DDIM;
    const float* p2 = tpool + (size_t)i2 * DDIM;
    float* dst = combined + (size_t)gw * (2 * DDIM) + DDIM;
    for (int d = lane; d < DDIM; d += 32)
        dst[d] = round_tf32f(w1 * p1[d] + w2s * p2[d]);
}

// ---------------- layernorm over D=512, writes rounded combined[:, :512] ----------------
__global__ void ln_kernel(const float* __restrict__ proj, const float* __restrict__ g,
                          const float* __restrict__ b, float* __restrict__ combined)
{
    __shared__ float sh[33];
    int n = blockIdx.x;
    const float* row = proj + (size_t)n * DDIM;
    float v[4];
    float s = 0.f;
    #pragma unroll
    for (int j = 0; j < 4; j++) { v[j] = row[threadIdx.x + j * 128]; s += v[j]; }
    float mean = block_reduce_sum(s, sh) * (1.f / DDIM);
    float q = 0.f;
    #pragma unroll
    for (int j = 0; j < 4; j++) { float d = v[j] - mean; q += d * d; }
    float var = block_reduce_sum(q, sh) * (1.f / DDIM);
    float rstd = rsqrtf(var + 1e-5f);
    float* dst = combined + (size_t)n * (2 * DDIM);
    #pragma unroll
    for (int j = 0; j < 4; j++) {
        int idx = threadIdx.x + j * 128;
        dst[idx] = round_tf32f((v[j] - mean) * rstd * g[idx] + b[idx]);
    }
}

// ---------------- gate + final mix ----------------
__global__ void gate_combine(const float* __restrict__ x, const float* __restrict__ wg,
                             const float* __restrict__ bg, const float* __restrict__ local,
                             const float* __restrict__ glob, float* __restrict__ out)
{
    __shared__ float sh[33];
    int n = blockIdx.x;
    const float* xr = x + (size_t)n * HDIM;
    float s = 0.f;
    for (int j = threadIdx.x; j < HDIM; j += 128) s += xr[j] * wg[j];
    float dot = block_reduce_sum(s, sh);
    float g = 1.f / (1.f + expf(-(dot + bg[0])));
    const float* lr = local + (size_t)n * HDIM;
    const float* gr = glob + (size_t)n * HDIM;
    float* orow = out + (size_t)n * HDIM;
    for (int j = threadIdx.x; j < HDIM; j += 128)
        orow[j] = g * lr[j] + (1.f - g) * gr[j];
}

// ---------------- diversity loss ----------------
__global__ void divloss_kernel(const float* __restrict__ usage, float* __restrict__ out) {
    __shared__ float sh[33];
    float s = 0.f;
    for (int j = threadIdx.x; j < PDIM; j += 1024) s += usage[j];
    float total = block_reduce_sum(s, sh);
    float inv = 1.f / (total + 1e-8f);
    float q = 0.f;
    const float ip = 1.f / (float)PDIM;
    for (int j = threadIdx.x; j < PDIM; j += 1024) {
        float f = usage[j] * inv - ip;
        q += f * f;
    }
    float qt = block_reduce_sum(q, sh);
    if (threadIdx.x == 0) out[0] = (qt / (float)PDIM) * 0.01f;
}

// ---------------- host launcher ----------------
extern "C" void kernel_launch(void* const* d_in, const int* in_sizes, int n_in,
                              void* d_out, int out_size)
{
    const float* x      = (const float*)d_in[0];
    const float* tpool  = (const float*)d_in[1];
    const float* w1     = (const float*)d_in[2];
    const float* b1     = (const float*)d_in[3];
    const float* w2     = (const float*)d_in[4];
    const float* b2     = (const float*)d_in[5];
    const float* temp   = (const float*)d_in[6];
    const float* wproj  = (const float*)d_in[7];
    const float* bproj  = (const float*)d_in[8];
    const float* ln_g   = (const float*)d_in[9];
    const float* ln_b   = (const float*)d_in[10];
    const float* wmap   = (const float*)d_in[11];
    const float* bmap   = (const float*)d_in[12];
    const float* conv_w = (const float*)d_in[13];
    const float* conv_b = (const float*)d_in[14];
    const float* wout   = (const float*)d_in[15];
    const float* bout   = (const float*)d_in[16];
    const float* wrp    = (const float*)d_in[17];
    const float* brp    = (const float*)d_in[18];
    const float* wg     = (const float*)d_in[19];
    const float* bg     = (const float*)d_in[20];
    float* out = (float*)d_out;

    float *inter, *concat, *local, *combined, *transf, *glob, *proj;
    float *convwt, *usage, *xt, *wprojt, *woutt, *wmapt, *wrpt;
    __nv_bfloat16 *logitsb, *xhb, *xlb, *w1hb, *w1lb, *w2b, *interb;
    cudaGetSymbolAddress((void**)&inter,    g_inter);
    cudaGetSymbolAddress((void**)&logitsb,  g_logitsb);
    cudaGetSymbolAddress((void**)&concat,   g_concat);
    cudaGetSymbolAddress((void**)&local,    g_local);
    cudaGetSymbolAddress((void**)&combined, g_combined);
    cudaGetSymbolAddress((void**)&transf,   g_transf);
    cudaGetSymbolAddress((void**)&glob,     g_global);
    cudaGetSymbolAddress((void**)&proj,     g_proj);
    cudaGetSymbolAddress((void**)&convwt,   g_convwt);
    cudaGetSymbolAddress((void**)&usage,    g_usage);
    cudaGetSymbolAddress((void**)&xt,       g_xt);
    cudaGetSymbolAddress((void**)&wprojt,   g_wprojt);
    cudaGetSymbolAddress((void**)&woutt,    g_woutt);
    cudaGetSymbolAddress((void**)&wmapt,    g_wmapt);
    cudaGetSymbolAddress((void**)&wrpt,     g_wrpt);
    cudaGetSymbolAddress((void**)&xhb,      g_xhb);
    cudaGetSymbolAddress((void**)&xlb,      g_xlb);
    cudaGetSymbolAddress((void**)&w1hb,     g_w1hb);
    cudaGetSymbolAddress((void**)&w1lb,     g_w1lb);
    cudaGetSymbolAddress((void**)&w2b,      g_w2b);
    cudaGetSymbolAddress((void**)&interb,   g_interb);

    const int TF_SMEM = 6 * 128 * TFPAD * sizeof(float);          // 110592 B
    const int BF_SMEM = 6 * 128 * HPAD * sizeof(__nv_bfloat16);   // 110592 B
    cudaFuncSetAttribute(gemm_tf32<0>, cudaFuncAttributeMaxDynamicSharedMemorySize, TF_SMEM);
    cudaFuncSetAttribute(gemm_tf32<1>, cudaFuncAttributeMaxDynamicSharedMemorySize, TF_SMEM);
    cudaFuncSetAttribute(gemm_bf16k<0>, cudaFuncAttributeMaxDynamicSharedMemorySize, BF_SMEM);
    cudaFuncSetAttribute(gemm_bf16k<2>, cudaFuncAttributeMaxDynamicSharedMemorySize, BF_SMEM);

    // ---- prep ----
    const int total_cw = NDIL * 3 * HDIM * HDIM;
    repack_convw<<<(total_cw + 255) / 256, 256>>>(conv_w, convwt);
    zero_usage<<<(PDIM + 255) / 256, 256>>>(usage);
    prep_x_kernel<<<(NTOK * HDIM / 4 + 255) / 256, 256>>>(x, xt, xhb, xlb, NTOK * HDIM / 4);
    {
        int n0 = DDIM * HDIM / 4, n1 = HDIM * 3 * HDIM / 4;
        int n2 = DDIM * 2 * DDIM / 4, n3 = HDIM * DDIM / 4;
        round_weights_kernel<<<dim3((n1 + 255) / 256, 1, 4), 256>>>(
            wproj, wprojt, n0, wout, woutt, n1, wmap, wmapt, n2, wrp, wrpt, n3);
    }
    split_bf16_kernel<<<(INTER_DIM * HDIM + 255) / 256, 256>>>(w1, w1hb, w1lb, INTER_DIM * HDIM);
    round_bf16_kernel<<<((int)((size_t)PDIM * INTER_DIM) + 255) / 256, 256>>>(
        w2, w2b, PDIM * INTER_DIM);

    // ---- router inter: 3xBF16 split, relu; dual write fp32 + bf16 ----
    gemm_bf16k<2><<<dim3(INTER_DIM / 128, NTOK / 128), 256, BF_SMEM>>>(
        xhb, xlb, w1hb, w1lb, b1, inter, interb, 3 * HDIM, INTER_DIM, 1);

    // ---- logits: single bf16, bf16 output (top-8 screen only) ----
    gemm_bf16k<0><<<dim3(PDIM / 128, NTOK / 128), 256, BF_SMEM>>>(
        interb, nullptr, w2b, nullptr, b2, nullptr, logitsb, INTER_DIM, PDIM, 0);

    topk_rescore_kernel<<<(NTOK * 32 + 255) / 256, 256>>>(
        logitsb, inter, w2, b2, tpool, temp, combined, usage);

    // ---- projected_x (tf32) -> LN -> combined[:, :512] ----
    gemm_tf32<0><<<dim3(DDIM / 128, NTOK / 128), 256, TF_SMEM>>>(
        xt, wprojt, bproj, proj, HDIM, DDIM, 0, 0, 0);
    ln_kernel<<<NTOK, 128>>>(proj, ln_g, ln_b, combined);

    // ---- dilated convs: single fused launch over blockIdx.z (dil = 1<<z) ----
    gemm_tf32<1><<<dim3(HDIM / 128, NTOK / 128, NDIL), 256, TF_SMEM>>>(
        xt, convwt, conv_b, concat, 3 * HDIM, 3 * HDIM, 0, 2, 1);

    // ---- local out (tf32) ----
    gemm_tf32<0><<<dim3(HDIM / 128, NTOK / 128), 256, TF_SMEM>>>(
        concat, woutt, bout, local, 3 * HDIM, HDIM, 0, 0, 0);

    // ---- transformation (rounded out) + global out (tf32) ----
    gemm_tf32<0><<<dim3(DDIM / 128, NTOK / 128), 256, TF_SMEM>>>(
        combined, wmapt, bmap, transf, 2 * DDIM, DDIM, 0, 0, 1);
    gemm_tf32<0><<<dim3(HDIM / 128, NTOK / 128), 256, TF_SMEM>>>(
        transf, wrpt, brp, glob, DDIM, HDIM, 0, 0, 0);

    // gate + mix -> out
    gate_combine<<<NTOK, 128>>>(x, wg, bg, local, glob, out);

    // diversity loss -> last output element
    if (out_size > NTOK * HDIM)
        divloss_kernel<<<1, 1024>>>(usage, out + (size_t)NTOK * HDIM);
}

// round 14
// speedup vs baseline: 1.1480x; 1.0136x over previous
#include <cuda_runtime.h>
#include <cuda_bf16.h>
#include <cstdint>
#include <float.h>

// ---------------- problem constants ----------------
#define BDIM 4
#define SDIM 4096
#define HDIM 1024
#define PDIM 4096
#define DDIM 512
#define NTOK (BDIM * SDIM)          // 16384
#define INTER_DIM 1024
#define NDIL 3

// ---------------- scratch (device globals; no allocs allowed) ----------------
__device__ float g_inter[NTOK * INTER_DIM];         // near-exact fp32 (rescore)
__device__ __nv_bfloat16 g_logitsb[(size_t)NTOK * PDIM]; // bf16 screen logits
__device__ float g_concat[(size_t)NTOK * 3 * HDIM]; // tf32-rounded GELU out
__device__ float g_local[NTOK * HDIM];
__device__ float g_combined[NTOK * 2 * DDIM];       // tf32-rounded
__device__ float g_transf[NTOK * DDIM];             // tf32-rounded
__device__ float g_proj[NTOK * DDIM];
__device__ float g_convwt[NDIL * 3 * HDIM * HDIM];  // repacked + tf32-rounded
__device__ float g_usage[PDIM];
__device__ float g_gates[NTOK];                     // sigmoid(x.wg + bg)
// pre-rounded tf32 operands (continuous paths)
__device__ float g_xt[NTOK * HDIM];                 // tf32(x)
__device__ float g_wprojt[DDIM * HDIM];
__device__ float g_woutt[HDIM * 3 * HDIM];
__device__ float g_wmapt[DDIM * 2 * DDIM];
__device__ float g_wrpt[HDIM * DDIM];
// bf16 router operands
__device__ __nv_bfloat16 g_xhb[NTOK * HDIM];        // hi(x) bf16
__device__ __nv_bfloat16 g_xlb[NTOK * HDIM];        // lo(x) bf16
__device__ __nv_bfloat16 g_w1hb[INTER_DIM * HDIM];
__device__ __nv_bfloat16 g_w1lb[INTER_DIM * HDIM];
__device__ __nv_bfloat16 g_w2b[(size_t)PDIM * INTER_DIM];
__device__ __nv_bfloat16 g_interb[NTOK * INTER_DIM];// bf16(inter) (logits A)

// ---------------- helpers ----------------
__device__ __forceinline__ float block_reduce_sum(float v, float* sh) {
    int tid = threadIdx.x;
    #pragma unroll
    for (int o = 16; o; o >>= 1) v += __shfl_xor_sync(0xffffffffu, v, o);
    if ((tid & 31) == 0) sh[tid >> 5] = v;
    __syncthreads();
    int nw = blockDim.x >> 5;
    float r = (tid < nw) ? sh[tid] : 0.f;
    if (tid < 32) {
        #pragma unroll
        for (int o = 16; o; o >>= 1) r += __shfl_xor_sync(0xffffffffu, r, o);
        if (tid == 0) sh[32] = r;
    }
    __syncthreads();
    float total = sh[32];
    __syncthreads();
    return total;
}

__device__ __forceinline__ unsigned cvt_tf32(float x) {
    unsigned r;
    asm("cvt.rna.tf32.f32 %0, %1;" : "=r"(r) : "f"(x));
    return r;
}
__device__ __forceinline__ float round_tf32f(float x) {
    return __uint_as_float(cvt_tf32(x));
}

__device__ __forceinline__ void mma_tf32(float* c, const unsigned* a, const unsigned* b) {
    asm volatile(
        "mma.sync.aligned.m16n8k8.row.col.f32.tf32.tf32.f32 "
        "{%0,%1,%2,%3}, {%4,%5,%6,%7}, {%8,%9}, {%0,%1,%2,%3};\n"
        : "+f"(c[0]), "+f"(c[1]), "+f"(c[2]), "+f"(c[3])
        : "r"(a[0]), "r"(a[1]), "r"(a[2]), "r"(a[3]), "r"(b[0]), "r"(b[1]));
}

__device__ __forceinline__ void mma_bf16(float* c, const unsigned* a, const unsigned* b) {
    asm volatile(
        "mma.sync.aligned.m16n8k16.row.col.f32.bf16.bf16.f32 "
        "{%0,%1,%2,%3}, {%4,%5,%6,%7}, {%8,%9}, {%0,%1,%2,%3};\n"
        : "+f"(c[0]), "+f"(c[1]), "+f"(c[2]), "+f"(c[3])
        : "r"(a[0]), "r"(a[1]), "r"(a[2]), "r"(a[3]), "r"(b[0]), "r"(b[1]));
}

__device__ __forceinline__ void ldsm_x4(unsigned addr, unsigned& r0, unsigned& r1,
                                        unsigned& r2, unsigned& r3) {
    asm volatile("ldmatrix.sync.aligned.m8n8.x4.shared.b16 {%0,%1,%2,%3}, [%4];"
                 : "=r"(r0), "=r"(r1), "=r"(r2), "=r"(r3) : "r"(addr));
}

__device__ __forceinline__ void cp16(void* dst_smem, const void* src, bool pred) {
    unsigned d = (unsigned)__cvta_generic_to_shared(dst_smem);
    int sz = pred ? 16 : 0;
    asm volatile("cp.async.cg.shared.global [%0], [%1], 16, %2;\n"
                 :: "r"(d), "l"(src), "r"(sz));
}
#define CP_COMMIT() asm volatile("cp.async.commit_group;\n" ::)
#define CP_WAIT1()  asm volatile("cp.async.wait_group 1;\n" ::)

// =====================================================================
// TF32 GEMM (R8 core: BM=BN=128, BK=32, 256 threads, 8 warps,
// warp 64x32, cp.async 3-stage, one __syncthreads per chunk, 2 CTAs/SM).
// MODE 0: plain  C = act(A @ W^T + b)
// MODE 1: conv   A = virtual im2col of x; dil = 1 << blockIdx.z.
// MODE 3: gated epilogue: C = g*local + (1-g)*(A @ W^T + b)
//         (gates/locl used only when MODE==3; dead args otherwise)
// =====================================================================
#define TFPAD 36

template<int MODE>
__global__ void __launch_bounds__(256, 2) gemm_tf32(
    const float* __restrict__ A, const float* __restrict__ W,
    const float* __restrict__ bias, float* __restrict__ C,
    int K, int ldc, int coff, int act, int roundC,
    const float* __restrict__ gates, const float* __restrict__ locl)
{
    extern __shared__ float smem[];
    float* As = smem;                      // [3][128][TFPAD]
    float* Bs = smem + 3 * 128 * TFPAD;    // [3][128][TFPAD]

    int dil = 0;
    if (MODE == 1) {
        int z = blockIdx.z;
        dil = 1 << z;
        W += (size_t)z * 3 * HDIM * HDIM;
        bias += z * HDIM;
        coff += z * HDIM;
    }

    const int tid = threadIdx.x;
    const int lane = tid & 31;
    const int wid = tid >> 5;
    const int wm = wid >> 2;
    const int wn = wid & 3;
    const int g = lane >> 2;
    const int t = lane & 3;
    const int row0 = blockIdx.y * 128;
    const int col0 = blockIdx.x * 128;
    const int KT = K >> 5;

    const unsigned sA = (unsigned)__cvta_generic_to_shared(As);
    const unsigned sB = (unsigned)__cvta_generic_to_shared(Bs);
    const unsigned aBase = sA + (((wm * 64 + (lane & 15)) * TFPAD + ((lane >> 4) & 1) * 4) << 2);
    const unsigned bBase = sB + (((wn * 32 + (lane & 7) + ((lane >> 4) & 1) * 8) * TFPAD
                                  + ((lane >> 3) & 1) * 4) << 2);
    const unsigned BUFO = 128 * TFPAD * 4;

    float acc[4][4][4];
    #pragma unroll
    for (int i = 0; i < 4; i++)
        #pragma unroll
        for (int j = 0; j < 4; j++)
            #pragma unroll
            for (int q = 0; q < 4; q++) acc[i][j][q] = 0.f;

    auto load_tile = [&](int kt, int buf) {
        int k0 = kt << 5;
        int ksl = 0, h0 = k0, shift = 0;
        if (MODE == 1) {
            ksl = k0 >> 10;
            h0 = k0 & (HDIM - 1);
            shift = (ksl - 1) * dil;
        }
        float* Ad = As + buf * 128 * TFPAD;
        float* Bd = Bs + buf * 128 * TFPAD;
        #pragma unroll
        for (int i = 0; i < 4; i++) {
            int idx = tid + i * 256;
            int r = idx >> 3;
            int c4 = (idx & 7) << 2;
            const float* srcA;
            bool pred = true;
            if (MODE == 1) {
                int n = row0 + r;
                int s2 = (n & (SDIM - 1)) + shift;
                pred = ((unsigned)s2 < (unsigned)SDIM);
                srcA = pred ? (A + (size_t)(n + shift) * HDIM + h0 + c4) : A;
            } else {
                srcA = A + (size_t)(row0 + r) * K + k0 + c4;
            }
            cp16(Ad + r * TFPAD + c4, srcA, pred);
            const float* srcB;
            if (MODE == 1)
                srcB = W + ((size_t)ksl * HDIM + col0 + r) * HDIM + h0 + c4;
            else
                srcB = W + (size_t)(col0 + r) * K + k0 + c4;
            cp16(Bd + r * TFPAD + c4, srcB, true);
        }
    };

    load_tile(0, 0); CP_COMMIT();
    if (KT > 1) load_tile(1, 1);
    CP_COMMIT();

    int buf = 0;
    for (int kt = 0; kt < KT; kt++) {
        CP_WAIT1();
        __syncthreads();
        if (kt + 2 < KT) load_tile(kt + 2, (buf + 2 >= 3) ? buf - 1 : buf + 2);
        CP_COMMIT();

        const unsigned aB = aBase + buf * BUFO;
        const unsigned bB = bBase + buf * BUFO;
        #pragma unroll
        for (int kk = 0; kk < 4; kk++) {
            unsigned af[4][4], bf[4][2];
            #pragma unroll
            for (int p = 0; p < 2; p++)
                ldsm_x4(bB + p * (16 * TFPAD * 4) + kk * 32,
                        bf[2 * p][0], bf[2 * p][1], bf[2 * p + 1][0], bf[2 * p + 1][1]);
            #pragma unroll
            for (int mt = 0; mt < 4; mt++)
                ldsm_x4(aB + mt * (16 * TFPAD * 4) + kk * 32,
                        af[mt][0], af[mt][1], af[mt][2], af[mt][3]);
            #pragma unroll
            for (int mt = 0; mt < 4; mt++)
                #pragma unroll
                for (int nt = 0; nt < 4; nt++)
                    mma_tf32(acc[mt][nt], af[mt], bf[nt]);
        }
        buf = (buf + 1 == 3) ? 0 : buf + 1;
    }

    #pragma unroll
    for (int mt = 0; mt < 4; mt++) {
        int r0 = row0 + wm * 64 + mt * 16 + g;
        int r1 = r0 + 8;
        float g0 = 0.f, g1 = 0.f;
        if (MODE == 3) { g0 = gates[r0]; g1 = gates[r1]; }
        #pragma unroll
        for (int nt = 0; nt < 4; nt++) {
            int c = col0 + wn * 32 + nt * 8 + 2 * t;
            float b0v = bias ? bias[c] : 0.f;
            float b1v = bias ? bias[c + 1] : 0.f;
            float v[4] = {acc[mt][nt][0] + b0v, acc[mt][nt][1] + b1v,
                          acc[mt][nt][2] + b0v, acc[mt][nt][3] + b1v};
            if (act == 2) {
                #pragma unroll
                for (int q = 0; q < 4; q++)
                    v[q] = 0.5f * v[q] * (1.f + erff(v[q] * 0.70710678118654752f));
            } else if (act == 1) {
                #pragma unroll
                for (int q = 0; q < 4; q++) v[q] = fmaxf(v[q], 0.f);
            }
            if (roundC) {
                #pragma unroll
                for (int q = 0; q < 4; q++) v[q] = round_tf32f(v[q]);
            }
            if (MODE == 3) {
                float2 l0 = *reinterpret_cast<const float2*>(locl + (size_t)r0 * ldc + c);
                float2 l1 = *reinterpret_cast<const float2*>(locl + (size_t)r1 * ldc + c);
                v[0] = g0 * l0.x + (1.f - g0) * v[0];
                v[1] = g0 * l0.y + (1.f - g0) * v[1];
                v[2] = g1 * l1.x + (1.f - g1) * v[2];
                v[3] = g1 * l1.y + (1.f - g1) * v[3];
            }
            *reinterpret_cast<float2*>(C + (size_t)r0 * ldc + coff + c) = make_float2(v[0], v[1]);
            *reinterpret_cast<float2*>(C + (size_t)r1 * ldc + coff + c) = make_float2(v[2], v[3]);
        }
    }
}

// =====================================================================
// BF16 GEMM (router). BK=64 halves, HPAD=72 (R12 winner, unchanged).
// MODE 0: plain. MODE 2: 3xBF16 virtual K=3072.
// =====================================================================
#define HPAD 72

template<int MODE>
__global__ void __launch_bounds__(256, 2) gemm_bf16k(
    const __nv_bfloat16* __restrict__ A, const __nv_bfloat16* __restrict__ Alo,
    const __nv_bfloat16* __restrict__ W, const __nv_bfloat16* __restrict__ Wlo,
    const float* __restrict__ bias, float* __restrict__ C, __nv_bfloat16* __restrict__ C2,
    int K, int ldc, int act)
{
    extern __shared__ __nv_bfloat16 hsm[];
    __nv_bfloat16* As = hsm;                   // [3][128][HPAD]
    __nv_bfloat16* Bs = hsm + 3 * 128 * HPAD;

    const int tid = threadIdx.x;
    const int lane = tid & 31;
    const int wid = tid >> 5;
    const int wm = wid >> 2;
    const int wn = wid & 3;
    const int g = lane >> 2;
    const int t = lane & 3;
    const int row0 = blockIdx.y * 128;
    const int col0 = blockIdx.x * 128;
    const int KT = K >> 6;

    const unsigned sA = (unsigned)__cvta_generic_to_shared(As);
    const unsigned sB = (unsigned)__cvta_generic_to_shared(Bs);
    const unsigned aBase = sA + (wm * 64 + (lane & 15)) * (HPAD * 2) + ((lane >> 4) & 1) * 16;
    const unsigned bBase = sB + (wn * 32 + (lane & 7) + ((lane >> 4) & 1) * 8) * (HPAD * 2)
                              + ((lane >> 3) & 1) * 16;
    const unsigned BUFO = 128 * HPAD * 2;

    float acc[4][4][4];
    #pragma unroll
    for (int i = 0; i < 4; i++)
        #pragma unroll
        for (int j = 0; j < 4; j++)
            #pragma unroll
            for (int q = 0; q < 4; q++) acc[i][j][q] = 0.f;

    auto load_tile = [&](int kt, int buf) {
        int k0 = kt << 6;
        int ksl = 0, h0 = k0;
        if (MODE == 2) { ksl = k0 >> 10; h0 = k0 & (HDIM - 1); }
        __nv_bfloat16* Ad = As + buf * 128 * HPAD;
        __nv_bfloat16* Bd = Bs + buf * 128 * HPAD;
        #pragma unroll
        for (int i = 0; i < 4; i++) {
            int idx = tid + i * 256;
            int r = idx >> 3;
            int c8 = (idx & 7) << 3;
            const __nv_bfloat16* srcA;
            if (MODE == 2) {
                const __nv_bfloat16* Ab = (ksl == 2) ? Alo : A;
                srcA = Ab + (size_t)(row0 + r) * HDIM + h0 + c8;
            } else {
                srcA = A + (size_t)(row0 + r) * K + k0 + c8;
            }
            cp16(Ad + r * HPAD + c8, srcA, true);
            const __nv_bfloat16* srcB;
            if (MODE == 2) {
                const __nv_bfloat16* Wb = (ksl == 1) ? Wlo : W;
                srcB = Wb + (size_t)(col0 + r) * HDIM + h0 + c8;
            } else {
                srcB = W + (size_t)(col0 + r) * K + k0 + c8;
            }
            cp16(Bd + r * HPAD + c8, srcB, true);
        }
    };

    load_tile(0, 0); CP_COMMIT();
    if (KT > 1) load_tile(1, 1);
    CP_COMMIT();

    int buf = 0;
    for (int kt = 0; kt < KT; kt++) {
        CP_WAIT1();
        __syncthreads();
        if (kt + 2 < KT) load_tile(kt + 2, (buf + 2 >= 3) ? buf - 1 : buf + 2);
        CP_COMMIT();

        const unsigned aB = aBase + buf * BUFO;
        const unsigned bB = bBase + buf * BUFO;
        #pragma unroll
        for (int kk = 0; kk < 4; kk++) {
            unsigned af[4][4], bf[4][2];
            #pragma unroll
            for (int p = 0; p < 2; p++)
                ldsm_x4(bB + p * (16 * HPAD * 2) + kk * 32,
                        bf[2 * p][0], bf[2 * p][1], bf[2 * p + 1][0], bf[2 * p + 1][1]);
            #pragma unroll
            for (int mt = 0; mt < 4; mt++)
                ldsm_x4(aB + mt * (16 * HPAD * 2) + kk * 32,
                        af[mt][0], af[mt][1], af[mt][2], af[mt][3]);
            #pragma unroll
            for (int mt = 0; mt < 4; mt++)
                #pragma unroll
                for (int nt = 0; nt < 4; nt++)
                    mma_bf16(acc[mt][nt], af[mt], bf[nt]);
        }
        buf = (buf + 1 == 3) ? 0 : buf + 1;
    }

    #pragma unroll
    for (int mt = 0; mt < 4; mt++) {
        int r0 = row0 + wm * 64 + mt * 16 + g;
        int r1 = r0 + 8;
        #pragma unroll
        for (int nt = 0; nt < 4; nt++) {
            int c = col0 + wn * 32 + nt * 8 + 2 * t;
            float b0v = bias ? bias[c] : 0.f;
            float b1v = bias ? bias[c + 1] : 0.f;
            float v[4] = {acc[mt][nt][0] + b0v, acc[mt][nt][1] + b1v,
                          acc[mt][nt][2] + b0v, acc[mt][nt][3] + b1v};
            if (act == 1) {
                #pragma unroll
                for (int q = 0; q < 4; q++) v[q] = fmaxf(v[q], 0.f);
            }
            if (C) {
                *reinterpret_cast<float2*>(C + (size_t)r0 * ldc + c) = make_float2(v[0], v[1]);
                *reinterpret_cast<float2*>(C + (size_t)r1 * ldc + c) = make_float2(v[2], v[3]);
            }
            if (C2) {
                __nv_bfloat162 p0, p1;
                p0.x = __float2bfloat16_rn(v[0]); p0.y = __float2bfloat16_rn(v[1]);
                p1.x = __float2bfloat16_rn(v[2]); p1.y = __float2bfloat16_rn(v[3]);
                *reinterpret_cast<__nv_bfloat162*>(C2 + (size_t)r0 * ldc + c) = p0;
                *reinterpret_cast<__nv_bfloat162*>(C2 + (size_t)r1 * ldc + c) = p1;
            }
        }
    }
}

// ---------------- prep kernels ----------------
__global__ void round_weights_kernel(
    const float* __restrict__ s0, float* __restrict__ d0, int n0,
    const float* __restrict__ s1, float* __restrict__ d1, int n1,
    const float* __restrict__ s2, float* __restrict__ d2, int n2,
    const float* __restrict__ s3, float* __restrict__ d3, int n3)
{
    const float* src; float* dst; int n4;
    switch (blockIdx.z) {
        case 0: src = s0; dst = d0; n4 = n0; break;
        case 1: src = s1; dst = d1; n4 = n1; break;
        case 2: src = s2; dst = d2; n4 = n2; break;
        default: src = s3; dst = d3; n4 = n3; break;
    }
    int i = blockIdx.x * blockDim.x + threadIdx.x;
    if (i >= n4) return;
    float4 v = reinterpret_cast<const float4*>(src)[i];
    v.x = round_tf32f(v.x); v.y = round_tf32f(v.y);
    v.z = round_tf32f(v.z); v.w = round_tf32f(v.w);
    reinterpret_cast<float4*>(dst)[i] = v;
}

__global__ void prep_x_kernel(const float* __restrict__ src, float* __restrict__ xt,
                              __nv_bfloat16* __restrict__ hi, __nv_bfloat16* __restrict__ lo,
                              int n4) {
    int i = blockIdx.x * blockDim.x + threadIdx.x;
    if (i >= n4) return;
    float4 v = reinterpret_cast<const float4*>(src)[i];
    float4 r;
    r.x = round_tf32f(v.x); r.y = round_tf32f(v.y);
    r.z = round_tf32f(v.z); r.w = round_tf32f(v.w);
    reinterpret_cast<float4*>(xt)[i] = r;
    __nv_bfloat162 h0, h1, l0, l1;
    h0.x = __float2bfloat16_rn(v.x); l0.x = __float2bfloat16_rn(v.x - __bfloat162float(h0.x));
    h0.y = __float2bfloat16_rn(v.y); l0.y = __float2bfloat16_rn(v.y - __bfloat162float(h0.y));
    h1.x = __float2bfloat16_rn(v.z); l1.x = __float2bfloat16_rn(v.z - __bfloat162float(h1.x));
    h1.y = __float2bfloat16_rn(v.w); l1.y = __float2bfloat16_rn(v.w - __bfloat162float(h1.y));
    reinterpret_cast<__nv_bfloat162*>(hi)[2 * i] = h0;
    reinterpret_cast<__nv_bfloat162*>(hi)[2 * i + 1] = h1;
    reinterpret_cast<__nv_bfloat162*>(lo)[2 * i] = l0;
    reinterpret_cast<__nv_bfloat162*>(lo)[2 * i + 1] = l1;
}

__global__ void split_bf16_kernel(const float* __restrict__ src, __nv_bfloat16* __restrict__ hi,
                                  __nv_bfloat16* __restrict__ lo, int n) {
    int i = blockIdx.x * blockDim.x + threadIdx.x;
    if (i >= n) return;
    float v = src[i];
    __nv_bfloat16 h = __float2bfloat16_rn(v);
    hi[i] = h;
    lo[i] = __float2bfloat16_rn(v - __bfloat162float(h));
}

__global__ void round_bf16_kernel(const float* __restrict__ src, __nv_bfloat16* __restrict__ dst, int n) {
    int i = blockIdx.x * blockDim.x + threadIdx.x;
    if (i >= n) return;
    dst[i] = __float2bfloat16_rn(src[i]);
}

__global__ void repack_convw(const float* __restrict__ cw, float* __restrict__ out) {
    int idx = blockIdx.x * blockDim.x + threadIdx.x;
    const int total = NDIL * 3 * HDIM * HDIM;
    if (idx >= total) return;
    int hi = idx & (HDIM - 1);
    int t = idx >> 10;
    int ho = t & (HDIM - 1);
    int t2 = t >> 10;
    int k = t2 % 3;
    int d = t2 / 3;
    out[idx] = round_tf32f(cw[(((size_t)d * HDIM + ho) * HDIM + hi) * 3 + k]);
}

__global__ void zero_usage(float* usage) {
    int i = blockIdx.x * blockDim.x + threadIdx.x;
    if (i < PDIM) usage[i] = 0.f;
}

// ---------------- gate precompute: gates[n] = sigmoid(x[n].wg + bg) ----------------
__global__ void __launch_bounds__(256) gate_kernel(
    const float* __restrict__ x, const float* __restrict__ wg,
    const float* __restrict__ bg, float* __restrict__ gates)
{
    int gw = (blockIdx.x * blockDim.x + threadIdx.x) >> 5;
    int lane = threadIdx.x & 31;
    if (gw >= NTOK) return;
    const float* xr = x + (size_t)gw * HDIM;
    float s = 0.f;
    #pragma unroll
    for (int q = 0; q < 32; q++) s = fmaf(xr[lane + q * 32], wg[lane + q * 32], s);
    #pragma unroll
    for (int off = 16; off; off >>= 1) s += __shfl_xor_sync(0xffffffffu, s, off);
    if (lane == 0) gates[gw] = 1.f / (1.f + expf(-(s + bg[0])));
}

// ---------------- top-8 (bf16 logits) + fp32 rescore + exact top-2 ----------------
__device__ __forceinline__ bool better(float va, int ia, float vb, int ib) {
    return (va > vb) || (va == vb && ia < ib);
}
__device__ __forceinline__ void ins2(float& v1, int& i1, float& v2, int& i2, float v, int i) {
    if (better(v, i, v1, i1)) { v2 = v1; i2 = i1; v1 = v; i1 = i; }
    else if (better(v, i, v2, i2)) { v2 = v; i2 = i; }
}

__global__ void __launch_bounds__(256) topk_rescore_kernel(
    const __nv_bfloat16* __restrict__ logits, const float* __restrict__ inter,
    const float* __restrict__ w2, const float* __restrict__ b2,
    const float* __restrict__ tpool, const float* __restrict__ temp_p,
    float* __restrict__ combined, float* __restrict__ usage)
{
    int gw = (blockIdx.x * blockDim.x + threadIdx.x) >> 5;
    int lane = threadIdx.x & 31;
    if (gw >= NTOK) return;
    float temp = fminf(fmaxf(*temp_p, 0.1f), 5.0f);
    float invt = 1.f / temp;

    const __nv_bfloat16* lrow = logits + (size_t)gw * PDIM;
    float tv[8]; int ti[8];
    #pragma unroll
    for (int k = 0; k < 8; k++) { tv[k] = -FLT_MAX; ti[k] = 0x3fffffff; }
    auto push = [&](float v, int j) {
        if (better(v, j, tv[7], ti[7])) {
            tv[7] = v; ti[7] = j;
            #pragma unroll
            for (int k = 7; k > 0; k--) {
                bool sw = better(tv[k], ti[k], tv[k - 1], ti[k - 1]);
                float av = sw ? tv[k] : tv[k - 1];
                float bv2 = sw ? tv[k - 1] : tv[k];
                int ai = sw ? ti[k] : ti[k - 1];
                int bi = sw ? ti[k - 1] : ti[k];
                tv[k - 1] = av; tv[k] = bv2; ti[k - 1] = ai; ti[k] = bi;
            }
        }
    };
    for (int j = lane * 2; j < PDIM; j += 64) {
        __nv_bfloat162 p = *reinterpret_cast<const __nv_bfloat162*>(lrow + j);
        push(fminf(fmaxf(__bfloat162float(p.x) * invt, -10.f), 10.f), j);
        push(fminf(fmaxf(__bfloat162float(p.y) * invt, -10.f), 10.f), j + 1);
    }

    int cand[8];
    #pragma unroll
    for (int r = 0; r < 8; r++) {
        float bvv = tv[0]; int bii = ti[0];
        #pragma unroll
        for (int off = 16; off; off >>= 1) {
            float ov = __shfl_xor_sync(0xffffffffu, bvv, off);
            int oi = __shfl_xor_sync(0xffffffffu, bii, off);
            if (better(ov, oi, bvv, bii)) { bvv = ov; bii = oi; }
        }
        cand[r] = bii;
        if (ti[0] == bii) {
            #pragma unroll
            for (int k = 0; k < 7; k++) { tv[k] = tv[k + 1]; ti[k] = ti[k + 1]; }
            tv[7] = -FLT_MAX; ti[7] = 0x3fffffff;
        }
    }

    const float* irow = inter + (size_t)gw * INTER_DIM;
    float xv[32];
    #pragma unroll
    for (int q = 0; q < 32; q++) xv[q] = irow[lane + q * 32];

    float v1 = -FLT_MAX, v2 = -FLT_MAX;
    int i1 = 0x3fffffff, i2 = 0x3fffffff;
    #pragma unroll
    for (int r = 0; r < 8; r++) {
        const float* wrow = w2 + (size_t)cand[r] * INTER_DIM;
        float s = 0.f;
        #pragma unroll
        for (int q = 0; q < 32; q++) s = fmaf(xv[q], wrow[lane + q * 32], s);
        #pragma unroll
        for (int off = 16; off; off >>= 1) s += __shfl_xor_sync(0xffffffffu, s, off);
        float v = fminf(fmaxf((s + b2[cand[r]]) * invt, -10.f), 10.f);
        ins2(v1, i1, v2, i2, v, cand[r]);
    }

    float e = expf(v2 - v1);
    float w1 = 1.f / (1.f + e);
    float w2s = e / (1.f + e);
    if (lane == 0) {
        atomicAdd(&usage[i1], w1);
        atomicAdd(&usage[i2], w2s);
    }
    const float* p1 = tpool + (size_t)i1 * DDIM;
    const float* p2 = tpool + (size_t)i2 * DDIM;
    float* dst = combined + (size_t)gw * (2 * DDIM) + DDIM;
    for (int d = lane; d < DDIM; d += 32)
        dst[d] = round_tf32f(w1 * p1[d] + w2s * p2[d]);
}

// ---------------- layernorm over D=512, writes rounded combined[:, :512] ----------------
__global__ void ln_kernel(const float* __restrict__ proj, const float* __restrict__ g,
                          const float* __restrict__ b, float* __restrict__ combined)
{
    __shared__ float sh[33];
    int n = blockIdx.x;
    const float* row = proj + (size_t)n * DDIM;
    float v[4];
    float s = 0.f;
    #pragma unroll
    for (int j = 0; j < 4; j++) { v[j] = row[threadIdx.x + j * 128]; s += v[j]; }
    float mean = block_reduce_sum(s, sh) * (1.f / DDIM);
    float q = 0.f;
    #pragma unroll
    for (int j = 0; j < 4; j++) { float d = v[j] - mean; q += d * d; }
    float var = block_reduce_sum(q, sh) * (1.f / DDIM);
    float rstd = rsqrtf(var + 1e-5f);
    float* dst = combined + (size_t)n * (2 * DDIM);
    #pragma unroll
    for (int j = 0; j < 4; j++) {
        int idx = threadIdx.x + j * 128;
        dst[idx] = round_tf32f((v[j] - mean) * rstd * g[idx] + b[idx]);
    }
}

// ---------------- diversity loss ----------------
__global__ void divloss_kernel(const float* __restrict__ usage, float* __restrict__ out) {
    __shared__ float sh[33];
    float s = 0.f;
    for (int j = threadIdx.x; j < PDIM; j += 1024) s += usage[j];
    float total = block_reduce_sum(s, sh);
    float inv = 1.f / (total + 1e-8f);
    float q = 0.f;
    const float ip = 1.f / (float)PDIM;
    for (int j = threadIdx.x; j < PDIM; j += 1024) {
        float f = usage[j] * inv - ip;
        q += f * f;
    }
    float qt = block_reduce_sum(q, sh);
    if (threadIdx.x == 0) out[0] = (qt / (float)PDIM) * 0.01f;
}

// ---------------- host launcher ----------------
extern "C" void kernel_launch(void* const* d_in, const int* in_sizes, int n_in,
                              void* d_out, int out_size)
{
    const float* x      = (const float*)d_in[0];
    const float* tpool  = (const float*)d_in[1];
    const float* w1     = (const float*)d_in[2];
    const float* b1     = (const float*)d_in[3];
    const float* w2     = (const float*)d_in[4];
    const float* b2     = (const float*)d_in[5];
    const float* temp   = (const float*)d_in[6];
    const float* wproj  = (const float*)d_in[7];
    const float* bproj  = (const float*)d_in[8];
    const float* ln_g   = (const float*)d_in[9];
    const float* ln_b   = (const float*)d_in[10];
    const float* wmap   = (const float*)d_in[11];
    const float* bmap   = (const float*)d_in[12];
    const float* conv_w = (const float*)d_in[13];
    const float* conv_b = (const float*)d_in[14];
    const float* wout   = (const float*)d_in[15];
    const float* bout   = (const float*)d_in[16];
    const float* wrp    = (const float*)d_in[17];
    const float* brp    = (const float*)d_in[18];
    const float* wg     = (const float*)d_in[19];
    const float* bg     = (const float*)d_in[20];
    float* out = (float*)d_out;

    float *inter, *concat, *local, *combined, *transf, *proj;
    float *convwt, *usage, *gates, *xt, *wprojt, *woutt, *wmapt, *wrpt;
    __nv_bfloat16 *logitsb, *xhb, *xlb, *w1hb, *w1lb, *w2b, *interb;
    cudaGetSymbolAddress((void**)&inter,    g_inter);
    cudaGetSymbolAddress((void**)&logitsb,  g_logitsb);
    cudaGetSymbolAddress((void**)&concat,   g_concat);
    cudaGetSymbolAddress((void**)&local,    g_local);
    cudaGetSymbolAddress((void**)&combined, g_combined);
    cudaGetSymbolAddress((void**)&transf,   g_transf);
    cudaGetSymbolAddress((void**)&proj,     g_proj);
    cudaGetSymbolAddress((void**)&convwt,   g_convwt);
    cudaGetSymbolAddress((void**)&usage,    g_usage);
    cudaGetSymbolAddress((void**)&gates,    g_gates);
    cudaGetSymbolAddress((void**)&xt,       g_xt);
    cudaGetSymbolAddress((void**)&wprojt,   g_wprojt);
    cudaGetSymbolAddress((void**)&woutt,    g_woutt);
    cudaGetSymbolAddress((void**)&wmapt,    g_wmapt);
    cudaGetSymbolAddress((void**)&wrpt,     g_wrpt);
    cudaGetSymbolAddress((void**)&xhb,      g_xhb);
    cudaGetSymbolAddress((void**)&xlb,      g_xlb);
    cudaGetSymbolAddress((void**)&w1hb,     g_w1hb);
    cudaGetSymbolAddress((void**)&w1lb,     g_w1lb);
    cudaGetSymbolAddress((void**)&w2b,      g_w2b);
    cudaGetSymbolAddress((void**)&interb,   g_interb);

    const int TF_SMEM = 6 * 128 * TFPAD * sizeof(float);          // 110592 B
    const int BF_SMEM = 6 * 128 * HPAD * sizeof(__nv_bfloat16);   // 110592 B
    cudaFuncSetAttribute(gemm_tf32<0>, cudaFuncAttributeMaxDynamicSharedMemorySize, TF_SMEM);
    cudaFuncSetAttribute(gemm_tf32<1>, cudaFuncAttributeMaxDynamicSharedMemorySize, TF_SMEM);
    cudaFuncSetAttribute(gemm_tf32<3>, cudaFuncAttributeMaxDynamicSharedMemorySize, TF_SMEM);
    cudaFuncSetAttribute(gemm_bf16k<0>, cudaFuncAttributeMaxDynamicSharedMemorySize, BF_SMEM);
    cudaFuncSetAttribute(gemm_bf16k<2>, cudaFuncAttributeMaxDynamicSharedMemorySize, BF_SMEM);

    // ---- prep ----
    const int total_cw = NDIL * 3 * HDIM * HDIM;
    repack_convw<<<(total_cw + 255) / 256, 256>>>(conv_w, convwt);
    zero_usage<<<(PDIM + 255) / 256, 256>>>(usage);
    prep_x_kernel<<<(NTOK * HDIM / 4 + 255) / 256, 256>>>(x, xt, xhb, xlb, NTOK * HDIM / 4);
    gate_kernel<<<(NTOK * 32 + 255) / 256, 256>>>(x, wg, bg, gates);
    {
        int n0 = DDIM * HDIM / 4, n1 = HDIM * 3 * HDIM / 4;
        int n2 = DDIM * 2 * DDIM / 4, n3 = HDIM * DDIM / 4;
        round_weights_kernel<<<dim3((n1 + 255) / 256, 1, 4), 256>>>(
            wproj, wprojt, n0, wout, woutt, n1, wmap, wmapt, n2, wrp, wrpt, n3);
    }
    split_bf16_kernel<<<(INTER_DIM * HDIM + 255) / 256, 256>>>(w1, w1hb, w1lb, INTER_DIM * HDIM);
    round_bf16_kernel<<<((int)((size_t)PDIM * INTER_DIM) + 255) / 256, 256>>>(
        w2, w2b, PDIM * INTER_DIM);

    // ---- router inter: 3xBF16 split, relu; dual write fp32 + bf16 ----
    gemm_bf16k<2><<<dim3(INTER_DIM / 128, NTOK / 128), 256, BF_SMEM>>>(
        xhb, xlb, w1hb, w1lb, b1, inter, interb, 3 * HDIM, INTER_DIM, 1);

    // ---- logits: single bf16, bf16 output (top-8 screen only) ----
    gemm_bf16k<0><<<dim3(PDIM / 128, NTOK / 128), 256, BF_SMEM>>>(
        interb, nullptr, w2b, nullptr, b2, nullptr, logitsb, INTER_DIM, PDIM, 0);

    topk_rescore_kernel<<<(NTOK * 32 + 255) / 256, 256>>>(
        logitsb, inter, w2, b2, tpool, temp, combined, usage);

    // ---- projected_x (tf32) -> LN -> combined[:, :512] ----
    gemm_tf32<0><<<dim3(DDIM / 128, NTOK / 128), 256, TF_SMEM>>>(
        xt, wprojt, bproj, proj, HDIM, DDIM, 0, 0, 0, nullptr, nullptr);
    ln_kernel<<<NTOK, 128>>>(proj, ln_g, ln_b, combined);

    // ---- dilated convs: single fused launch over blockIdx.z (dil = 1<<z) ----
    gemm_tf32<1><<<dim3(HDIM / 128, NTOK / 128, NDIL), 256, TF_SMEM>>>(
        xt, convwt, conv_b, concat, 3 * HDIM, 3 * HDIM, 0, 2, 1, nullptr, nullptr);

    // ---- local out (tf32) ----
    gemm_tf32<0><<<dim3(HDIM / 128, NTOK / 128), 256, TF_SMEM>>>(
        concat, woutt, bout, local, 3 * HDIM, HDIM, 0, 0, 0, nullptr, nullptr);

    // ---- transformation (rounded out) ----
    gemm_tf32<0><<<dim3(DDIM / 128, NTOK / 128), 256, TF_SMEM>>>(
        combined, wmapt, bmap, transf, 2 * DDIM, DDIM, 0, 0, 1, nullptr, nullptr);

    // ---- global out + gate mix fused: out = g*local + (1-g)*(transf@wrp^T + brp) ----
    gemm_tf32<3><<<dim3(HDIM / 128, NTOK / 128), 256, TF_SMEM>>>(
        transf, wrpt, brp, out, DDIM, HDIM, 0, 0, 0, gates, local);

    // diversity loss -> last output element
    if (out_size > NTOK * HDIM)
        divloss_kernel<<<1, 1024>>>(usage, out + (size_t)NTOK * HDIM);
}

// round 16
// speedup vs baseline: 1.1566x; 1.0075x over previous
#include <cuda_runtime.h>
#include <cuda_bf16.h>
#include <cstdint>
#include <float.h>

// ---------------- problem constants ----------------
#define BDIM 4
#define SDIM 4096
#define HDIM 1024
#define PDIM 4096
#define DDIM 512
#define NTOK (BDIM * SDIM)          // 16384
#define INTER_DIM 1024
#define NDIL 3

// ---------------- scratch (device globals; no allocs allowed) ----------------
__device__ float g_inter[NTOK * INTER_DIM];         // near-exact fp32 (rescore)
__device__ __nv_bfloat16 g_logitsb[(size_t)NTOK * PDIM]; // bf16 screen logits
__device__ float g_concat[(size_t)NTOK * 3 * HDIM]; // tf32-rounded GELU out
__device__ float g_local[NTOK * HDIM];
__device__ float g_combined[NTOK * 2 * DDIM];       // tf32-rounded
__device__ float g_transf[NTOK * DDIM];             // tf32-rounded
__device__ float g_proj[NTOK * DDIM];
__device__ float g_convwt[NDIL * 3 * HDIM * HDIM];  // repacked + tf32-rounded
__device__ float g_usage[PDIM];
__device__ float g_gates[NTOK];                     // sigmoid(x.wg + bg)
// pre-rounded tf32 operands (continuous paths)
__device__ float g_xt[NTOK * HDIM];                 // tf32(x)
__device__ float g_wprojt[DDIM * HDIM];
__device__ float g_woutt[HDIM * 3 * HDIM];
__device__ float g_wmapt[DDIM * 2 * DDIM];
__device__ float g_wrpt[HDIM * DDIM];
// bf16 router operands
__device__ __nv_bfloat16 g_xhb[NTOK * HDIM];        // hi(x) bf16
__device__ __nv_bfloat16 g_xlb[NTOK * HDIM];        // lo(x) bf16
__device__ __nv_bfloat16 g_w1hb[INTER_DIM * HDIM];
__device__ __nv_bfloat16 g_w1lb[INTER_DIM * HDIM];
__device__ __nv_bfloat16 g_w2b[(size_t)PDIM * INTER_DIM];
__device__ __nv_bfloat16 g_interb[NTOK * INTER_DIM];// bf16(inter) (logits A)

// ---------------- helpers ----------------
__device__ __forceinline__ float block_reduce_sum(float v, float* sh) {
    int tid = threadIdx.x;
    #pragma unroll
    for (int o = 16; o; o >>= 1) v += __shfl_xor_sync(0xffffffffu, v, o);
    if ((tid & 31) == 0) sh[tid >> 5] = v;
    __syncthreads();
    int nw = blockDim.x >> 5;
    float r = (tid < nw) ? sh[tid] : 0.f;
    if (tid < 32) {
        #pragma unroll
        for (int o = 16; o; o >>= 1) r += __shfl_xor_sync(0xffffffffu, r, o);
        if (tid == 0) sh[32] = r;
    }
    __syncthreads();
    float total = sh[32];
    __syncthreads();
    return total;
}

__device__ __forceinline__ unsigned cvt_tf32(float x) {
    unsigned r;
    asm("cvt.rna.tf32.f32 %0, %1;" : "=r"(r) : "f"(x));
    return r;
}
__device__ __forceinline__ float round_tf32f(float x) {
    return __uint_as_float(cvt_tf32(x));
}

__device__ __forceinline__ void mma_tf32(float* c, const unsigned* a, const unsigned* b) {
    asm volatile(
        "mma.sync.aligned.m16n8k8.row.col.f32.tf32.tf32.f32 "
        "{%0,%1,%2,%3}, {%4,%5,%6,%7}, {%8,%9}, {%0,%1,%2,%3};\n"
        : "+f"(c[0]), "+f"(c[1]), "+f"(c[2]), "+f"(c[3])
        : "r"(a[0]), "r"(a[1]), "r"(a[2]), "r"(a[3]), "r"(b[0]), "r"(b[1]));
}

__device__ __forceinline__ void mma_bf16(float* c, const unsigned* a, const unsigned* b) {
    asm volatile(
        "mma.sync.aligned.m16n8k16.row.col.f32.bf16.bf16.f32 "
        "{%0,%1,%2,%3}, {%4,%5,%6,%7}, {%8,%9}, {%0,%1,%2,%3};\n"
        : "+f"(c[0]), "+f"(c[1]), "+f"(c[2]), "+f"(c[3])
        : "r"(a[0]), "r"(a[1]), "r"(a[2]), "r"(a[3]), "r"(b[0]), "r"(b[1]));
}

__device__ __forceinline__ void ldsm_x4(unsigned addr, unsigned& r0, unsigned& r1,
                                        unsigned& r2, unsigned& r3) {
    asm volatile("ldmatrix.sync.aligned.m8n8.x4.shared.b16 {%0,%1,%2,%3}, [%4];"
                 : "=r"(r0), "=r"(r1), "=r"(r2), "=r"(r3) : "r"(addr));
}

__device__ __forceinline__ void cp16(void* dst_smem, const void* src, bool pred) {
    unsigned d = (unsigned)__cvta_generic_to_shared(dst_smem);
    int sz = pred ? 16 : 0;
    asm volatile("cp.async.cg.shared.global [%0], [%1], 16, %2;\n"
                 :: "r"(d), "l"(src), "r"(sz));
}
#define CP_COMMIT() asm volatile("cp.async.commit_group;\n" ::)
#define CP_WAIT1()  asm volatile("cp.async.wait_group 1;\n" ::)

// =====================================================================
// TF32 GEMM (R8 core: BM=BN=128, BK=32, 256 threads, 8 warps,
// warp 64x32, cp.async 3-stage, one __syncthreads per chunk, 2 CTAs/SM).
// MODE 0: plain  C = act(A @ W^T + b)
// MODE 1: conv   A = virtual im2col of x; dil = 1 << blockIdx.z.
// MODE 3: gated epilogue: C = g*local + (1-g)*(A @ W^T + b)
// =====================================================================
#define TFPAD 36

template<int MODE>
__global__ void __launch_bounds__(256, 2) gemm_tf32(
    const float* __restrict__ A, const float* __restrict__ W,
    const float* __restrict__ bias, float* __restrict__ C,
    int K, int ldc, int coff, int act, int roundC,
    const float* __restrict__ gates, const float* __restrict__ locl)
{
    extern __shared__ float smem[];
    float* As = smem;                      // [3][128][TFPAD]
    float* Bs = smem + 3 * 128 * TFPAD;    // [3][128][TFPAD]

    int dil = 0;
    if (MODE == 1) {
        int z = blockIdx.z;
        dil = 1 << z;
        W += (size_t)z * 3 * HDIM * HDIM;
        bias += z * HDIM;
        coff += z * HDIM;
    }

    const int tid = threadIdx.x;
    const int lane = tid & 31;
    const int wid = tid >> 5;
    const int wm = wid >> 2;
    const int wn = wid & 3;
    const int g = lane >> 2;
    const int t = lane & 3;
    const int row0 = blockIdx.y * 128;
    const int col0 = blockIdx.x * 128;
    const int KT = K >> 5;

    const unsigned sA = (unsigned)__cvta_generic_to_shared(As);
    const unsigned sB = (unsigned)__cvta_generic_to_shared(Bs);
    const unsigned aBase = sA + (((wm * 64 + (lane & 15)) * TFPAD + ((lane >> 4) & 1) * 4) << 2);
    const unsigned bBase = sB + (((wn * 32 + (lane & 7) + ((lane >> 4) & 1) * 8) * TFPAD
                                  + ((lane >> 3) & 1) * 4) << 2);
    const unsigned BUFO = 128 * TFPAD * 4;

    float acc[4][4][4];
    #pragma unroll
    for (int i = 0; i < 4; i++)
        #pragma unroll
        for (int j = 0; j < 4; j++)
            #pragma unroll
            for (int q = 0; q < 4; q++) acc[i][j][q] = 0.f;

    auto load_tile = [&](int kt, int buf) {
        int k0 = kt << 5;
        int ksl = 0, h0 = k0, shift = 0;
        if (MODE == 1) {
            ksl = k0 >> 10;
            h0 = k0 & (HDIM - 1);
            shift = (ksl - 1) * dil;
        }
        float* Ad = As + buf * 128 * TFPAD;
        float* Bd = Bs + buf * 128 * TFPAD;
        #pragma unroll
        for (int i = 0; i < 4; i++) {
            int idx = tid + i * 256;
            int r = idx >> 3;
            int c4 = (idx & 7) << 2;
            const float* srcA;
            bool pred = true;
            if (MODE == 1) {
                int n = row0 + r;
                int s2 = (n & (SDIM - 1)) + shift;
                pred = ((unsigned)s2 < (unsigned)SDIM);
                srcA = pred ? (A + (size_t)(n + shift) * HDIM + h0 + c4) : A;
            } else {
                srcA = A + (size_t)(row0 + r) * K + k0 + c4;
            }
            cp16(Ad + r * TFPAD + c4, srcA, pred);
            const float* srcB;
            if (MODE == 1)
                srcB = W + ((size_t)ksl * HDIM + col0 + r) * HDIM + h0 + c4;
            else
                srcB = W + (size_t)(col0 + r) * K + k0 + c4;
            cp16(Bd + r * TFPAD + c4, srcB, true);
        }
    };

    load_tile(0, 0); CP_COMMIT();
    if (KT > 1) load_tile(1, 1);
    CP_COMMIT();

    int buf = 0;
    for (int kt = 0; kt < KT; kt++) {
        CP_WAIT1();
        __syncthreads();
        if (kt + 2 < KT) load_tile(kt + 2, (buf + 2 >= 3) ? buf - 1 : buf + 2);
        CP_COMMIT();

        const unsigned aB = aBase + buf * BUFO;
        const unsigned bB = bBase + buf * BUFO;
        #pragma unroll
        for (int kk = 0; kk < 4; kk++) {
            unsigned af[4][4], bf[4][2];
            #pragma unroll
            for (int p = 0; p < 2; p++)
                ldsm_x4(bB + p * (16 * TFPAD * 4) + kk * 32,
                        bf[2 * p][0], bf[2 * p][1], bf[2 * p + 1][0], bf[2 * p + 1][1]);
            #pragma unroll
            for (int mt = 0; mt < 4; mt++)
                ldsm_x4(aB + mt * (16 * TFPAD * 4) + kk * 32,
                        af[mt][0], af[mt][1], af[mt][2], af[mt][3]);
            #pragma unroll
            for (int mt = 0; mt < 4; mt++)
                #pragma unroll
                for (int nt = 0; nt < 4; nt++)
                    mma_tf32(acc[mt][nt], af[mt], bf[nt]);
        }
        buf = (buf + 1 == 3) ? 0 : buf + 1;
    }

    #pragma unroll
    for (int mt = 0; mt < 4; mt++) {
        int r0 = row0 + wm * 64 + mt * 16 + g;
        int r1 = r0 + 8;
        float g0 = 0.f, g1 = 0.f;
        if (MODE == 3) { g0 = gates[r0]; g1 = gates[r1]; }
        #pragma unroll
        for (int nt = 0; nt < 4; nt++) {
            int c = col0 + wn * 32 + nt * 8 + 2 * t;
            float b0v = bias ? bias[c] : 0.f;
            float b1v = bias ? bias[c + 1] : 0.f;
            float v[4] = {acc[mt][nt][0] + b0v, acc[mt][nt][1] + b1v,
                          acc[mt][nt][2] + b0v, acc[mt][nt][3] + b1v};
            if (act == 2) {
                #pragma unroll
                for (int q = 0; q < 4; q++)
                    v[q] = 0.5f * v[q] * (1.f + erff(v[q] * 0.70710678118654752f));
            } else if (act == 1) {
                #pragma unroll
                for (int q = 0; q < 4; q++) v[q] = fmaxf(v[q], 0.f);
            }
            if (roundC) {
                #pragma unroll
                for (int q = 0; q < 4; q++) v[q] = round_tf32f(v[q]);
            }
            if (MODE == 3) {
                float2 l0 = *reinterpret_cast<const float2*>(locl + (size_t)r0 * ldc + c);
                float2 l1 = *reinterpret_cast<const float2*>(locl + (size_t)r1 * ldc + c);
                v[0] = g0 * l0.x + (1.f - g0) * v[0];
                v[1] = g0 * l0.y + (1.f - g0) * v[1];
                v[2] = g1 * l1.x + (1.f - g1) * v[2];
                v[3] = g1 * l1.y + (1.f - g1) * v[3];
            }
            *reinterpret_cast<float2*>(C + (size_t)r0 * ldc + coff + c) = make_float2(v[0], v[1]);
            *reinterpret_cast<float2*>(C + (size_t)r1 * ldc + coff + c) = make_float2(v[2], v[3]);
        }
    }
}

// =====================================================================
// BF16 GEMM (router). BK=64 halves, HPAD=72 (R12 winner, unchanged).
// MODE 0: plain. MODE 2: 3xBF16 virtual K=3072.
// =====================================================================
#define HPAD 72

template<int MODE>
__global__ void __launch_bounds__(256, 2) gemm_bf16k(
    const __nv_bfloat16* __restrict__ A, const __nv_bfloat16* __restrict__ Alo,
    const __nv_bfloat16* __restrict__ W, const __nv_bfloat16* __restrict__ Wlo,
    const float* __restrict__ bias, float* __restrict__ C, __nv_bfloat16* __restrict__ C2,
    int K, int ldc, int act)
{
    extern __shared__ __nv_bfloat16 hsm[];
    __nv_bfloat16* As = hsm;                   // [3][128][HPAD]
    __nv_bfloat16* Bs = hsm + 3 * 128 * HPAD;

    const int tid = threadIdx.x;
    const int lane = tid & 31;
    const int wid = tid >> 5;
    const int wm = wid >> 2;
    const int wn = wid & 3;
    const int g = lane >> 2;
    const int t = lane & 3;
    const int row0 = blockIdx.y * 128;
    const int col0 = blockIdx.x * 128;
    const int KT = K >> 6;

    const unsigned sA = (unsigned)__cvta_generic_to_shared(As);
    const unsigned sB = (unsigned)__cvta_generic_to_shared(Bs);
    const unsigned aBase = sA + (wm * 64 + (lane & 15)) * (HPAD * 2) + ((lane >> 4) & 1) * 16;
    const unsigned bBase = sB + (wn * 32 + (lane & 7) + ((lane >> 4) & 1) * 8) * (HPAD * 2)
                              + ((lane >> 3) & 1) * 16;
    const unsigned BUFO = 128 * HPAD * 2;

    float acc[4][4][4];
    #pragma unroll
    for (int i = 0; i < 4; i++)
        #pragma unroll
        for (int j = 0; j < 4; j++)
            #pragma unroll
            for (int q = 0; q < 4; q++) acc[i][j][q] = 0.f;

    auto load_tile = [&](int kt, int buf) {
        int k0 = kt << 6;
        int ksl = 0, h0 = k0;
        if (MODE == 2) { ksl = k0 >> 10; h0 = k0 & (HDIM - 1); }
        __nv_bfloat16* Ad = As + buf * 128 * HPAD;
        __nv_bfloat16* Bd = Bs + buf * 128 * HPAD;
        #pragma unroll
        for (int i = 0; i < 4; i++) {
            int idx = tid + i * 256;
            int r = idx >> 3;
            int c8 = (idx & 7) << 3;
            const __nv_bfloat16* srcA;
            if (MODE == 2) {
                const __nv_bfloat16* Ab = (ksl == 2) ? Alo : A;
                srcA = Ab + (size_t)(row0 + r) * HDIM + h0 + c8;
            } else {
                srcA = A + (size_t)(row0 + r) * K + k0 + c8;
            }
            cp16(Ad + r * HPAD + c8, srcA, true);
            const __nv_bfloat16* srcB;
            if (MODE == 2) {
                const __nv_bfloat16* Wb = (ksl == 1) ? Wlo : W;
                srcB = Wb + (size_t)(col0 + r) * HDIM + h0 + c8;
            } else {
                srcB = W + (size_t)(col0 + r) * K + k0 + c8;
            }
            cp16(Bd + r * HPAD + c8, srcB, true);
        }
    };

    load_tile(0, 0); CP_COMMIT();
    if (KT > 1) load_tile(1, 1);
    CP_COMMIT();

    int buf = 0;
    for (int kt = 0; kt < KT; kt++) {
        CP_WAIT1();
        __syncthreads();
        if (kt + 2 < KT) load_tile(kt + 2, (buf + 2 >= 3) ? buf - 1 : buf + 2);
        CP_COMMIT();

        const unsigned aB = aBase + buf * BUFO;
        const unsigned bB = bBase + buf * BUFO;
        #pragma unroll
        for (int kk = 0; kk < 4; kk++) {
            unsigned af[4][4], bf[4][2];
            #pragma unroll
            for (int p = 0; p < 2; p++)
                ldsm_x4(bB + p * (16 * HPAD * 2) + kk * 32,
                        bf[2 * p][0], bf[2 * p][1], bf[2 * p + 1][0], bf[2 * p + 1][1]);
            #pragma unroll
            for (int mt = 0; mt < 4; mt++)
                ldsm_x4(aB + mt * (16 * HPAD * 2) + kk * 32,
                        af[mt][0], af[mt][1], af[mt][2], af[mt][3]);
            #pragma unroll
            for (int mt = 0; mt < 4; mt++)
                #pragma unroll
                for (int nt = 0; nt < 4; nt++)
                    mma_bf16(acc[mt][nt], af[mt], bf[nt]);
        }
        buf = (buf + 1 == 3) ? 0 : buf + 1;
    }

    #pragma unroll
    for (int mt = 0; mt < 4; mt++) {
        int r0 = row0 + wm * 64 + mt * 16 + g;
        int r1 = r0 + 8;
        #pragma unroll
        for (int nt = 0; nt < 4; nt++) {
            int c = col0 + wn * 32 + nt * 8 + 2 * t;
            float b0v = bias ? bias[c] : 0.f;
            float b1v = bias ? bias[c + 1] : 0.f;
            float v[4] = {acc[mt][nt][0] + b0v, acc[mt][nt][1] + b1v,
                          acc[mt][nt][2] + b0v, acc[mt][nt][3] + b1v};
            if (act == 1) {
                #pragma unroll
                for (int q = 0; q < 4; q++) v[q] = fmaxf(v[q], 0.f);
            }
            if (C) {
                *reinterpret_cast<float2*>(C + (size_t)r0 * ldc + c) = make_float2(v[0], v[1]);
                *reinterpret_cast<float2*>(C + (size_t)r1 * ldc + c) = make_float2(v[2], v[3]);
            }
            if (C2) {
                __nv_bfloat162 p0, p1;
                p0.x = __float2bfloat16_rn(v[0]); p0.y = __float2bfloat16_rn(v[1]);
                p1.x = __float2bfloat16_rn(v[2]); p1.y = __float2bfloat16_rn(v[3]);
                *reinterpret_cast<__nv_bfloat162*>(C2 + (size_t)r0 * ldc + c) = p0;
                *reinterpret_cast<__nv_bfloat162*>(C2 + (size_t)r1 * ldc + c) = p1;
            }
        }
    }
}

// =====================================================================
// prep_x_gate: block per row. xt/xhb/xlb elementwise + gate dot fused.
// =====================================================================
__global__ void __launch_bounds__(256) prep_x_gate(
    const float* __restrict__ x, const float* __restrict__ wg,
    const float* __restrict__ bg, float* __restrict__ xt,
    __nv_bfloat16* __restrict__ hi, __nv_bfloat16* __restrict__ lo,
    float* __restrict__ gates)
{
    __shared__ float sh[33];
    int n = blockIdx.x;
    int i = n * (HDIM / 4) + threadIdx.x;   // float4 index
    float4 v = reinterpret_cast<const float4*>(x)[i];
    float4 w = reinterpret_cast<const float4*>(wg)[threadIdx.x];
    float4 r;
    r.x = round_tf32f(v.x); r.y = round_tf32f(v.y);
    r.z = round_tf32f(v.z); r.w = round_tf32f(v.w);
    reinterpret_cast<float4*>(xt)[i] = r;
    __nv_bfloat162 h0, h1, l0, l1;
    h0.x = __float2bfloat16_rn(v.x); l0.x = __float2bfloat16_rn(v.x - __bfloat162float(h0.x));
    h0.y = __float2bfloat16_rn(v.y); l0.y = __float2bfloat16_rn(v.y - __bfloat162float(h0.y));
    h1.x = __float2bfloat16_rn(v.z); l1.x = __float2bfloat16_rn(v.z - __bfloat162float(h1.x));
    h1.y = __float2bfloat16_rn(v.w); l1.y = __float2bfloat16_rn(v.w - __bfloat162float(h1.y));
    reinterpret_cast<__nv_bfloat162*>(hi)[2 * i] = h0;
    reinterpret_cast<__nv_bfloat162*>(hi)[2 * i + 1] = h1;
    reinterpret_cast<__nv_bfloat162*>(lo)[2 * i] = l0;
    reinterpret_cast<__nv_bfloat162*>(lo)[2 * i + 1] = l1;
    float s = v.x * w.x + v.y * w.y + v.z * w.z + v.w * w.w;
    float dot = block_reduce_sum(s, sh);
    if (threadIdx.x == 0) gates[n] = 1.f / (1.f + expf(-(dot + bg[0])));
}

// =====================================================================
// mega prep: flat grid, compile-time segment dispatch.
// seg0 repack conv weights (1 float/thread), seg1-4 tf32 weight rounds
// (1 float4/thread), seg5 w1 bf16 split (f4), seg6 w2 bf16 round (f4),
// seg7 zero usage.
// =====================================================================
#define PSEG0 36864                // repack: 9,437,184 floats
#define PSEG1 (PSEG0 + 512)        // wproj: 131072 f4
#define PSEG2 (PSEG1 + 3072)       // wout: 786432 f4
#define PSEG3 (PSEG2 + 512)        // wmap: 131072 f4
#define PSEG4 (PSEG3 + 512)        // wrp: 131072 f4
#define PSEG5 (PSEG4 + 1024)       // w1 split: 262144 f4
#define PSEG6 (PSEG5 + 4096)       // w2 round: 1,048,576 f4
#define PSEG7 (PSEG6 + 16)         // usage zero: 4096 floats

__global__ void __launch_bounds__(256) mega_prep(
    const float* __restrict__ conv_w, float* __restrict__ convwt,
    const float* __restrict__ wproj, float* __restrict__ wprojt,
    const float* __restrict__ wout, float* __restrict__ woutt,
    const float* __restrict__ wmap, float* __restrict__ wmapt,
    const float* __restrict__ wrp, float* __restrict__ wrpt,
    const float* __restrict__ w1, __nv_bfloat16* __restrict__ w1hb,
    __nv_bfloat16* __restrict__ w1lb,
    const float* __restrict__ w2, __nv_bfloat16* __restrict__ w2b,
    float* __restrict__ usage)
{
    int b = blockIdx.x;
    if (b < PSEG0) {
        int idx = b * 256 + threadIdx.x;
        int hi = idx & (HDIM - 1);
        int t = idx >> 10;
        int ho = t & (HDIM - 1);
        int t2 = t >> 10;
        int k = t2 % 3;
        int d = t2 / 3;
        convwt[idx] = round_tf32f(conv_w[(((size_t)d * HDIM + ho) * HDIM + hi) * 3 + k]);
    } else if (b < PSEG4) {
        const float* src; float* dst; int i;
        if (b < PSEG1)      { src = wproj; dst = wprojt; i = (b - PSEG0) * 256 + threadIdx.x; }
        else if (b < PSEG2) { src = wout;  dst = woutt;  i = (b - PSEG1) * 256 + threadIdx.x; }
        else if (b < PSEG3) { src = wmap;  dst = wmapt;  i = (b - PSEG2) * 256 + threadIdx.x; }
        else                { src = wrp;   dst = wrpt;   i = (b - PSEG3) * 256 + threadIdx.x; }
        float4 v = reinterpret_cast<const float4*>(src)[i];
        v.x = round_tf32f(v.x); v.y = round_tf32f(v.y);
        v.z = round_tf32f(v.z); v.w = round_tf32f(v.w);
        reinterpret_cast<float4*>(dst)[i] = v;
    } else if (b < PSEG5) {
        int i = (b - PSEG4) * 256 + threadIdx.x;
        float4 v = reinterpret_cast<const float4*>(w1)[i];
        __nv_bfloat162 h0, h1, l0, l1;
        h0.x = __float2bfloat16_rn(v.x); l0.x = __float2bfloat16_rn(v.x - __bfloat162float(h0.x));
        h0.y = __float2bfloat16_rn(v.y); l0.y = __float2bfloat16_rn(v.y - __bfloat162float(h0.y));
        h1.x = __float2bfloat16_rn(v.z); l1.x = __float2bfloat16_rn(v.z - __bfloat162float(h1.x));
        h1.y = __float2bfloat16_rn(v.w); l1.y = __float2bfloat16_rn(v.w - __bfloat162float(h1.y));
        reinterpret_cast<__nv_bfloat162*>(w1hb)[2 * i] = h0;
        reinterpret_cast<__nv_bfloat162*>(w1hb)[2 * i + 1] = h1;
        reinterpret_cast<__nv_bfloat162*>(w1lb)[2 * i] = l0;
        reinterpret_cast<__nv_bfloat162*>(w1lb)[2 * i + 1] = l1;
    } else if (b < PSEG6) {
        int i = (b - PSEG5) * 256 + threadIdx.x;
        float4 v = reinterpret_cast<const float4*>(w2)[i];
        __nv_bfloat162 p0, p1;
        p0.x = __float2bfloat16_rn(v.x); p0.y = __float2bfloat16_rn(v.y);
        p1.x = __float2bfloat16_rn(v.z); p1.y = __float2bfloat16_rn(v.w);
        reinterpret_cast<__nv_bfloat162*>(w2b)[2 * i] = p0;
        reinterpret_cast<__nv_bfloat162*>(w2b)[2 * i + 1] = p1;
    } else {
        int i = (b - PSEG6) * 256 + threadIdx.x;
        if (i < PDIM) usage[i] = 0.f;
    }
}

// ---------------- top-8 (bf16 logits) + fp32 rescore + exact top-2 ----------------
__device__ __forceinline__ bool better(float va, int ia, float vb, int ib) {
    return (va > vb) || (va == vb && ia < ib);
}
__device__ __forceinline__ void ins2(float& v1, int& i1, float& v2, int& i2, float v, int i) {
    if (better(v, i, v1, i1)) { v2 = v1; i2 = i1; v1 = v; i1 = i; }
    else if (better(v, i, v2, i2)) { v2 = v; i2 = i; }
}

__global__ void __launch_bounds__(256) topk_rescore_kernel(
    const __nv_bfloat16* __restrict__ logits, const float* __restrict__ inter,
    const float* __restrict__ w2, const float* __restrict__ b2,
    const float* __restrict__ tpool, const float* __restrict__ temp_p,
    float* __restrict__ combined, float* __restrict__ usage)
{
    int gw = (blockIdx.x * blockDim.x + threadIdx.x) >> 5;
    int lane = threadIdx.x & 31;
    if (gw >= NTOK) return;
    float temp = fminf(fmaxf(*temp_p, 0.1f), 5.0f);
    float invt = 1.f / temp;

    const __nv_bfloat16* lrow = logits + (size_t)gw * PDIM;
    float tv[8]; int ti[8];
    #pragma unroll
    for (int k = 0; k < 8; k++) { tv[k] = -FLT_MAX; ti[k] = 0x3fffffff; }
    auto push = [&](float v, int j) {
        if (better(v, j, tv[7], ti[7])) {
            tv[7] = v; ti[7] = j;
            #pragma unroll
            for (int k = 7; k > 0; k--) {
                bool sw = better(tv[k], ti[k], tv[k - 1], ti[k - 1]);
                float av = sw ? tv[k] : tv[k - 1];
                float bv2 = sw ? tv[k - 1] : tv[k];
                int ai = sw ? ti[k] : ti[k - 1];
                int bi = sw ? ti[k - 1] : ti[k];
                tv[k - 1] = av; tv[k] = bv2; ti[k - 1] = ai; ti[k] = bi;
            }
        }
    };
    for (int j = lane * 2; j < PDIM; j += 64) {
        __nv_bfloat162 p = *reinterpret_cast<const __nv_bfloat162*>(lrow + j);
        push(fminf(fmaxf(__bfloat162float(p.x) * invt, -10.f), 10.f), j);
        push(fminf(fmaxf(__bfloat162float(p.y) * invt, -10.f), 10.f), j + 1);
    }

    int cand[8];
    #pragma unroll
    for (int r = 0; r < 8; r++) {
        float bvv = tv[0]; int bii = ti[0];
        #pragma unroll
        for (int off = 16; off; off >>= 1) {
            float ov = __shfl_xor_sync(0xffffffffu, bvv, off);
            int oi = __shfl_xor_sync(0xffffffffu, bii, off);
            if (better(ov, oi, bvv, bii)) { bvv = ov; bii = oi; }
        }
        cand[r] = bii;
        if (ti[0] == bii) {
            #pragma unroll
            for (int k = 0; k < 7; k++) { tv[k] = tv[k + 1]; ti[k] = ti[k + 1]; }
            tv[7] = -FLT_MAX; ti[7] = 0x3fffffff;
        }
    }

    const float* irow = inter + (size_t)gw * INTER_DIM;
    float xv[32];
    #pragma unroll
    for (int q = 0; q < 32; q++) xv[q] = irow[lane + q * 32];

    float v1 = -FLT_MAX, v2 = -FLT_MAX;
    int i1 = 0x3fffffff, i2 = 0x3fffffff;
    #pragma unroll
    for (int r = 0; r < 8; r++) {
        const float* wrow = w2 + (size_t)cand[r] * INTER_DIM;
        float s = 0.f;
        #pragma unroll
        for (int q = 0; q < 32; q++) s = fmaf(xv[q], wrow[lane + q * 32], s);
        #pragma unroll
        for (int off = 16; off; off >>= 1) s += __shfl_xor_sync(0xffffffffu, s, off);
        float v = fminf(fmaxf((s + b2[cand[r]]) * invt, -10.f), 10.f);
        ins2(v1, i1, v2, i2, v, cand[r]);
    }

    float e = expf(v2 - v1);
    float w1 = 1.f / (1.f + e);
    float w2s = e / (1.f + e);
    if (lane == 0) {
        atomicAdd(&usage[i1], w1);
        atomicAdd(&usage[i2], w2s);
    }
    const float* p1 = tpool + (size_t)i1 * DDIM;
    const float* p2 = tpool + (size_t)i2 * DDIM;
    float* dst = combined + (size_t)gw * (2 * DDIM) + DDIM;
    for (int d = lane; d < DDIM; d += 32)
        dst[d] = round_tf32f(w1 * p1[d] + w2s * p2[d]);
}

// ---------------- layernorm over D=512, writes rounded combined[:, :512] ----------------
__global__ void ln_kernel(const float* __restrict__ proj, const float* __restrict__ g,
                          const float* __restrict__ b, float* __restrict__ combined)
{
    __shared__ float sh[33];
    int n = blockIdx.x;
    const float* row = proj + (size_t)n * DDIM;
    float v[4];
    float s = 0.f;
    #pragma unroll
    for (int j = 0; j < 4; j++) { v[j] = row[threadIdx.x + j * 128]; s += v[j]; }
    float mean = block_reduce_sum(s, sh) * (1.f / DDIM);
    float q = 0.f;
    #pragma unroll
    for (int j = 0; j < 4; j++) { float d = v[j] - mean; q += d * d; }
    float var = block_reduce_sum(q, sh) * (1.f / DDIM);
    float rstd = rsqrtf(var + 1e-5f);
    float* dst = combined + (size_t)n * (2 * DDIM);
    #pragma unroll
    for (int j = 0; j < 4; j++) {
        int idx = threadIdx.x + j * 128;
        dst[idx] = round_tf32f((v[j] - mean) * rstd * g[idx] + b[idx]);
    }
}

// ---------------- diversity loss ----------------
__global__ void divloss_kernel(const float* __restrict__ usage, float* __restrict__ out) {
    __shared__ float sh[33];
    float s = 0.f;
    for (int j = threadIdx.x; j < PDIM; j += 1024) s += usage[j];
    float total = block_reduce_sum(s, sh);
    float inv = 1.f / (total + 1e-8f);
    float q = 0.f;
    const float ip = 1.f / (float)PDIM;
    for (int j = threadIdx.x; j < PDIM; j += 1024) {
        float f = usage[j] * inv - ip;
        q += f * f;
    }
    float qt = block_reduce_sum(q, sh);
    if (threadIdx.x == 0) out[0] = (qt / (float)PDIM) * 0.01f;
}

// ---------------- host launcher ----------------
extern "C" void kernel_launch(void* const* d_in, const int* in_sizes, int n_in,
                              void* d_out, int out_size)
{
    const float* x      = (const float*)d_in[0];
    const float* tpool  = (const float*)d_in[1];
    const float* w1     = (const float*)d_in[2];
    const float* b1     = (const float*)d_in[3];
    const float* w2     = (const float*)d_in[4];
    const float* b2     = (const float*)d_in[5];
    const float* temp   = (const float*)d_in[6];
    const float* wproj  = (const float*)d_in[7];
    const float* bproj  = (const float*)d_in[8];
    const float* ln_g   = (const float*)d_in[9];
    const float* ln_b   = (const float*)d_in[10];
    const float* wmap   = (const float*)d_in[11];
    const float* bmap   = (const float*)d_in[12];
    const float* conv_w = (const float*)d_in[13];
    const float* conv_b = (const float*)d_in[14];
    const float* wout   = (const float*)d_in[15];
    const float* bout   = (const float*)d_in[16];
    const float* wrp    = (const float*)d_in[17];
    const float* brp    = (const float*)d_in[18];
    const float* wg     = (const float*)d_in[19];
    const float* bg     = (const float*)d_in[20];
    float* out = (float*)d_out;

    float *inter, *concat, *local, *combined, *transf, *proj;
    float *convwt, *usage, *gates, *xt, *wprojt, *woutt, *wmapt, *wrpt;
    __nv_bfloat16 *logitsb, *xhb, *xlb, *w1hb, *w1lb, *w2b, *interb;
    cudaGetSymbolAddress((void**)&inter,    g_inter);
    cudaGetSymbolAddress((void**)&logitsb,  g_logitsb);
    cudaGetSymbolAddress((void**)&concat,   g_concat);
    cudaGetSymbolAddress((void**)&local,    g_local);
    cudaGetSymbolAddress((void**)&combined, g_combined);
    cudaGetSymbolAddress((void**)&transf,   g_transf);
    cudaGetSymbolAddress((void**)&proj,     g_proj);
    cudaGetSymbolAddress((void**)&convwt,   g_convwt);
    cudaGetSymbolAddress((void**)&usage,    g_usage);
    cudaGetSymbolAddress((void**)&gates,    g_gates);
    cudaGetSymbolAddress((void**)&xt,       g_xt);
    cudaGetSymbolAddress((void**)&wprojt,   g_wprojt);
    cudaGetSymbolAddress((void**)&woutt,    g_woutt);
    cudaGetSymbolAddress((void**)&wmapt,    g_wmapt);
    cudaGetSymbolAddress((void**)&wrpt,     g_wrpt);
    cudaGetSymbolAddress((void**)&xhb,      g_xhb);
    cudaGetSymbolAddress((void**)&xlb,      g_xlb);
    cudaGetSymbolAddress((void**)&w1hb,     g_w1hb);
    cudaGetSymbolAddress((void**)&w1lb,     g_w1lb);
    cudaGetSymbolAddress((void**)&w2b,      g_w2b);
    cudaGetSymbolAddress((void**)&interb,   g_interb);

    const int TF_SMEM = 6 * 128 * TFPAD * sizeof(float);          // 110592 B
    const int BF_SMEM = 6 * 128 * HPAD * sizeof(__nv_bfloat16);   // 110592 B
    cudaFuncSetAttribute(gemm_tf32<0>, cudaFuncAttributeMaxDynamicSharedMemorySize, TF_SMEM);
    cudaFuncSetAttribute(gemm_tf32<1>, cudaFuncAttributeMaxDynamicSharedMemorySize, TF_SMEM);
    cudaFuncSetAttribute(gemm_tf32<3>, cudaFuncAttributeMaxDynamicSharedMemorySize, TF_SMEM);
    cudaFuncSetAttribute(gemm_bf16k<0>, cudaFuncAttributeMaxDynamicSharedMemorySize, BF_SMEM);
    cudaFuncSetAttribute(gemm_bf16k<2>, cudaFuncAttributeMaxDynamicSharedMemorySize, BF_SMEM);

    // ---- prep: ONE fused weight-prep launch + fused x-prep/gate ----
    mega_prep<<<PSEG7, 256>>>(conv_w, convwt, wproj, wprojt, wout, woutt,
                              wmap, wmapt, wrp, wrpt, w1, w1hb, w1lb,
                              w2, w2b, usage);
    prep_x_gate<<<NTOK, 256>>>(x, wg, bg, xt, xhb, xlb, gates);

    // ---- router inter: 3xBF16 split, relu; dual write fp32 + bf16 ----
    gemm_bf16k<2><<<dim3(INTER_DIM / 128, NTOK / 128), 256, BF_SMEM>>>(
        xhb, xlb, w1hb, w1lb, b1, inter, interb, 3 * HDIM, INTER_DIM, 1);

    // ---- logits: single bf16, bf16 output (top-8 screen only) ----
    gemm_bf16k<0><<<dim3(PDIM / 128, NTOK / 128), 256, BF_SMEM>>>(
        interb, nullptr, w2b, nullptr, b2, nullptr, logitsb, INTER_DIM, PDIM, 0);

    topk_rescore_kernel<<<(NTOK * 32 + 255) / 256, 256>>>(
        logitsb, inter, w2, b2, tpool, temp, combined, usage);

    // ---- projected_x (tf32) -> LN -> combined[:, :512] ----
    gemm_tf32<0><<<dim3(DDIM / 128, NTOK / 128), 256, TF_SMEM>>>(
        xt, wprojt, bproj, proj, HDIM, DDIM, 0, 0, 0, nullptr, nullptr);
    ln_kernel<<<NTOK, 128>>>(proj, ln_g, ln_b, combined);

    // ---- dilated convs: single fused launch over blockIdx.z (dil = 1<<z) ----
    gemm_tf32<1><<<dim3(HDIM / 128, NTOK / 128, NDIL), 256, TF_SMEM>>>(
        xt, convwt, conv_b, concat, 3 * HDIM, 3 * HDIM, 0, 2, 1, nullptr, nullptr);

    // ---- local out (tf32) ----
    gemm_tf32<0><<<dim3(HDIM / 128, NTOK / 128), 256, TF_SMEM>>>(
        concat, woutt, bout, local, 3 * HDIM, HDIM, 0, 0, 0, nullptr, nullptr);

    // ---- transformation (rounded out) ----
    gemm_tf32<0><<<dim3(DDIM / 128, NTOK / 128), 256, TF_SMEM>>>(
        combined, wmapt, bmap, transf, 2 * DDIM, DDIM, 0, 0, 1, nullptr, nullptr);

    // ---- global out + gate mix fused: out = g*local + (1-g)*(transf@wrp^T + brp) ----
    gemm_tf32<3><<<dim3(HDIM / 128, NTOK / 128), 256, TF_SMEM>>>(
        transf, wrpt, brp, out, DDIM, HDIM, 0, 0, 0, gates, local);

    // diversity loss -> last output element
    if (out_size > NTOK * HDIM)
        divloss_kernel<<<1, 1024>>>(usage, out + (size_t)NTOK * HDIM);
}

// round 17
// speedup vs baseline: 1.1624x; 1.0050x over previous
#include <cuda_runtime.h>
#include <cuda_bf16.h>
#include <cstdint>
#include <float.h>

// ---------------- problem constants ----------------
#define BDIM 4
#define SDIM 4096
#define HDIM 1024
#define PDIM 4096
#define DDIM 512
#define NTOK (BDIM * SDIM)          // 16384
#define INTER_DIM 1024
#define NDIL 3

// ---------------- scratch (device globals; no allocs allowed) ----------------
__device__ float g_inter[NTOK * INTER_DIM];         // near-exact fp32 (rescore)
__device__ __nv_bfloat16 g_logitsb[(size_t)NTOK * PDIM]; // bf16 screen logits
__device__ float g_concat[(size_t)NTOK * 3 * HDIM]; // tf32-rounded GELU out
__device__ float g_local[NTOK * HDIM];
__device__ float g_combined[NTOK * 2 * DDIM];       // tf32-rounded
__device__ float g_transf[NTOK * DDIM];             // tf32-rounded
__device__ float g_proj[NTOK * DDIM];
__device__ float g_convwt[NDIL * 3 * HDIM * HDIM];  // repacked + tf32-rounded
__device__ float g_usage[PDIM];
__device__ float g_gates[NTOK];                     // sigmoid(x.wg + bg)
// pre-rounded tf32 operands (continuous paths)
__device__ float g_xt[NTOK * HDIM];                 // tf32(x)
__device__ float g_wprojt[DDIM * HDIM];
__device__ float g_woutt[HDIM * 3 * HDIM];
__device__ float g_wmapt[DDIM * 2 * DDIM];
__device__ float g_wrpt[HDIM * DDIM];
// bf16 router operands
__device__ __nv_bfloat16 g_xhb[NTOK * HDIM];        // hi(x) bf16
__device__ __nv_bfloat16 g_xlb[NTOK * HDIM];        // lo(x) bf16
__device__ __nv_bfloat16 g_w1hb[INTER_DIM * HDIM];
__device__ __nv_bfloat16 g_w1lb[INTER_DIM * HDIM];
__device__ __nv_bfloat16 g_w2b[(size_t)PDIM * INTER_DIM];
__device__ __nv_bfloat16 g_interb[NTOK * INTER_DIM];// bf16(inter) (logits A)

// ---------------- helpers ----------------
__device__ __forceinline__ float block_reduce_sum(float v, float* sh) {
    int tid = threadIdx.x;
    #pragma unroll
    for (int o = 16; o; o >>= 1) v += __shfl_xor_sync(0xffffffffu, v, o);
    if ((tid & 31) == 0) sh[tid >> 5] = v;
    __syncthreads();
    int nw = blockDim.x >> 5;
    float r = (tid < nw) ? sh[tid] : 0.f;
    if (tid < 32) {
        #pragma unroll
        for (int o = 16; o; o >>= 1) r += __shfl_xor_sync(0xffffffffu, r, o);
        if (tid == 0) sh[32] = r;
    }
    __syncthreads();
    float total = sh[32];
    __syncthreads();
    return total;
}

__device__ __forceinline__ unsigned cvt_tf32(float x) {
    unsigned r;
    asm("cvt.rna.tf32.f32 %0, %1;" : "=r"(r) : "f"(x));
    return r;
}
__device__ __forceinline__ float round_tf32f(float x) {
    return __uint_as_float(cvt_tf32(x));
}

__device__ __forceinline__ void mma_tf32(float* c, const unsigned* a, const unsigned* b) {
    asm volatile(
        "mma.sync.aligned.m16n8k8.row.col.f32.tf32.tf32.f32 "
        "{%0,%1,%2,%3}, {%4,%5,%6,%7}, {%8,%9}, {%0,%1,%2,%3};\n"
        : "+f"(c[0]), "+f"(c[1]), "+f"(c[2]), "+f"(c[3])
        : "r"(a[0]), "r"(a[1]), "r"(a[2]), "r"(a[3]), "r"(b[0]), "r"(b[1]));
}

__device__ __forceinline__ void mma_bf16(float* c, const unsigned* a, const unsigned* b) {
    asm volatile(
        "mma.sync.aligned.m16n8k16.row.col.f32.bf16.bf16.f32 "
        "{%0,%1,%2,%3}, {%4,%5,%6,%7}, {%8,%9}, {%0,%1,%2,%3};\n"
        : "+f"(c[0]), "+f"(c[1]), "+f"(c[2]), "+f"(c[3])
        : "r"(a[0]), "r"(a[1]), "r"(a[2]), "r"(a[3]), "r"(b[0]), "r"(b[1]));
}

__device__ __forceinline__ void ldsm_x4(unsigned addr, unsigned& r0, unsigned& r1,
                                        unsigned& r2, unsigned& r3) {
    asm volatile("ldmatrix.sync.aligned.m8n8.x4.shared.b16 {%0,%1,%2,%3}, [%4];"
                 : "=r"(r0), "=r"(r1), "=r"(r2), "=r"(r3) : "r"(addr));
}

__device__ __forceinline__ void cp16(void* dst_smem, const void* src, bool pred) {
    unsigned d = (unsigned)__cvta_generic_to_shared(dst_smem);
    int sz = pred ? 16 : 0;
    asm volatile("cp.async.cg.shared.global [%0], [%1], 16, %2;\n"
                 :: "r"(d), "l"(src), "r"(sz));
}
#define CP_COMMIT() asm volatile("cp.async.commit_group;\n" ::)
#define CP_WAIT1()  asm volatile("cp.async.wait_group 1;\n" ::)

// =====================================================================
// TF32 GEMM (R8 core: BM=BN=128, BK=32, 256 threads, 8 warps,
// warp 64x32, cp.async 3-stage, one __syncthreads per chunk, 2 CTAs/SM).
// MODE 0: plain  C = act(A @ W^T + b)
// MODE 1: conv   A = virtual im2col of x; dil = 1 << blockIdx.z.
// MODE 3: gated epilogue: C = g*local + (1-g)*(A @ W^T + b)
// =====================================================================
#define TFPAD 36

template<int MODE>
__global__ void __launch_bounds__(256, 2) gemm_tf32(
    const float* __restrict__ A, const float* __restrict__ W,
    const float* __restrict__ bias, float* __restrict__ C,
    int K, int ldc, int coff, int act, int roundC,
    const float* __restrict__ gates, const float* __restrict__ locl)
{
    extern __shared__ float smem[];
    float* As = smem;                      // [3][128][TFPAD]
    float* Bs = smem + 3 * 128 * TFPAD;    // [3][128][TFPAD]

    int dil = 0;
    if (MODE == 1) {
        int z = blockIdx.z;
        dil = 1 << z;
        W += (size_t)z * 3 * HDIM * HDIM;
        bias += z * HDIM;
        coff += z * HDIM;
    }

    const int tid = threadIdx.x;
    const int lane = tid & 31;
    const int wid = tid >> 5;
    const int wm = wid >> 2;
    const int wn = wid & 3;
    const int g = lane >> 2;
    const int t = lane & 3;
    const int row0 = blockIdx.y * 128;
    const int col0 = blockIdx.x * 128;
    const int KT = K >> 5;

    const unsigned sA = (unsigned)__cvta_generic_to_shared(As);
    const unsigned sB = (unsigned)__cvta_generic_to_shared(Bs);
    const unsigned aBase = sA + (((wm * 64 + (lane & 15)) * TFPAD + ((lane >> 4) & 1) * 4) << 2);
    const unsigned bBase = sB + (((wn * 32 + (lane & 7) + ((lane >> 4) & 1) * 8) * TFPAD
                                  + ((lane >> 3) & 1) * 4) << 2);
    const unsigned BUFO = 128 * TFPAD * 4;

    float acc[4][4][4];
    #pragma unroll
    for (int i = 0; i < 4; i++)
        #pragma unroll
        for (int j = 0; j < 4; j++)
            #pragma unroll
            for (int q = 0; q < 4; q++) acc[i][j][q] = 0.f;

    auto load_tile = [&](int kt, int buf) {
        int k0 = kt << 5;
        int ksl = 0, h0 = k0, shift = 0;
        if (MODE == 1) {
            ksl = k0 >> 10;
            h0 = k0 & (HDIM - 1);
            shift = (ksl - 1) * dil;
        }
        float* Ad = As + buf * 128 * TFPAD;
        float* Bd = Bs + buf * 128 * TFPAD;
        #pragma unroll
        for (int i = 0; i < 4; i++) {
            int idx = tid + i * 256;
            int r = idx >> 3;
            int c4 = (idx & 7) << 2;
            const float* srcA;
            bool pred = true;
            if (MODE == 1) {
                int n = row0 + r;
                int s2 = (n & (SDIM - 1)) + shift;
                pred = ((unsigned)s2 < (unsigned)SDIM);
                srcA = pred ? (A + (size_t)(n + shift) * HDIM + h0 + c4) : A;
            } else {
                srcA = A + (size_t)(row0 + r) * K + k0 + c4;
            }
            cp16(Ad + r * TFPAD + c4, srcA, pred);
            const float* srcB;
            if (MODE == 1)
                srcB = W + ((size_t)ksl * HDIM + col0 + r) * HDIM + h0 + c4;
            else
                srcB = W + (size_t)(col0 + r) * K + k0 + c4;
            cp16(Bd + r * TFPAD + c4, srcB, true);
        }
    };

    load_tile(0, 0); CP_COMMIT();
    if (KT > 1) load_tile(1, 1);
    CP_COMMIT();

    int buf = 0;
    for (int kt = 0; kt < KT; kt++) {
        CP_WAIT1();
        __syncthreads();
        if (kt + 2 < KT) load_tile(kt + 2, (buf + 2 >= 3) ? buf - 1 : buf + 2);
        CP_COMMIT();

        const unsigned aB = aBase + buf * BUFO;
        const unsigned bB = bBase + buf * BUFO;
        #pragma unroll
        for (int kk = 0; kk < 4; kk++) {
            unsigned af[4][4], bf[4][2];
            #pragma unroll
            for (int p = 0; p < 2; p++)
                ldsm_x4(bB + p * (16 * TFPAD * 4) + kk * 32,
                        bf[2 * p][0], bf[2 * p][1], bf[2 * p + 1][0], bf[2 * p + 1][1]);
            #pragma unroll
            for (int mt = 0; mt < 4; mt++)
                ldsm_x4(aB + mt * (16 * TFPAD * 4) + kk * 32,
                        af[mt][0], af[mt][1], af[mt][2], af[mt][3]);
            #pragma unroll
            for (int mt = 0; mt < 4; mt++)
                #pragma unroll
                for (int nt = 0; nt < 4; nt++)
                    mma_tf32(acc[mt][nt], af[mt], bf[nt]);
        }
        buf = (buf + 1 == 3) ? 0 : buf + 1;
    }

    #pragma unroll
    for (int mt = 0; mt < 4; mt++) {
        int r0 = row0 + wm * 64 + mt * 16 + g;
        int r1 = r0 + 8;
        float g0 = 0.f, g1 = 0.f;
        if (MODE == 3) { g0 = gates[r0]; g1 = gates[r1]; }
        #pragma unroll
        for (int nt = 0; nt < 4; nt++) {
            int c = col0 + wn * 32 + nt * 8 + 2 * t;
            float b0v = bias ? bias[c] : 0.f;
            float b1v = bias ? bias[c + 1] : 0.f;
            float v[4] = {acc[mt][nt][0] + b0v, acc[mt][nt][1] + b1v,
                          acc[mt][nt][2] + b0v, acc[mt][nt][3] + b1v};
            if (act == 2) {
                #pragma unroll
                for (int q = 0; q < 4; q++)
                    v[q] = 0.5f * v[q] * (1.f + erff(v[q] * 0.70710678118654752f));
            } else if (act == 1) {
                #pragma unroll
                for (int q = 0; q < 4; q++) v[q] = fmaxf(v[q], 0.f);
            }
            if (roundC) {
                #pragma unroll
                for (int q = 0; q < 4; q++) v[q] = round_tf32f(v[q]);
            }
            if (MODE == 3) {
                float2 l0 = *reinterpret_cast<const float2*>(locl + (size_t)r0 * ldc + c);
                float2 l1 = *reinterpret_cast<const float2*>(locl + (size_t)r1 * ldc + c);
                v[0] = g0 * l0.x + (1.f - g0) * v[0];
                v[1] = g0 * l0.y + (1.f - g0) * v[1];
                v[2] = g1 * l1.x + (1.f - g1) * v[2];
                v[3] = g1 * l1.y + (1.f - g1) * v[3];
            }
            *reinterpret_cast<float2*>(C + (size_t)r0 * ldc + coff + c) = make_float2(v[0], v[1]);
            *reinterpret_cast<float2*>(C + (size_t)r1 * ldc + coff + c) = make_float2(v[2], v[3]);
        }
    }
}

// =====================================================================
// BF16 GEMM (router). BK=64 halves, HPAD=72 (R12 winner, unchanged).
// MODE 0: plain. MODE 2: 3xBF16 virtual K=3072.
// =====================================================================
#define HPAD 72

template<int MODE>
__global__ void __launch_bounds__(256, 2) gemm_bf16k(
    const __nv_bfloat16* __restrict__ A, const __nv_bfloat16* __restrict__ Alo,
    const __nv_bfloat16* __restrict__ W, const __nv_bfloat16* __restrict__ Wlo,
    const float* __restrict__ bias, float* __restrict__ C, __nv_bfloat16* __restrict__ C2,
    int K, int ldc, int act)
{
    extern __shared__ __nv_bfloat16 hsm[];
    __nv_bfloat16* As = hsm;                   // [3][128][HPAD]
    __nv_bfloat16* Bs = hsm + 3 * 128 * HPAD;

    const int tid = threadIdx.x;
    const int lane = tid & 31;
    const int wid = tid >> 5;
    const int wm = wid >> 2;
    const int wn = wid & 3;
    const int g = lane >> 2;
    const int t = lane & 3;
    const int row0 = blockIdx.y * 128;
    const int col0 = blockIdx.x * 128;
    const int KT = K >> 6;

    const unsigned sA = (unsigned)__cvta_generic_to_shared(As);
    const unsigned sB = (unsigned)__cvta_generic_to_shared(Bs);
    const unsigned aBase = sA + (wm * 64 + (lane & 15)) * (HPAD * 2) + ((lane >> 4) & 1) * 16;
    const unsigned bBase = sB + (wn * 32 + (lane & 7) + ((lane >> 4) & 1) * 8) * (HPAD * 2)
                              + ((lane >> 3) & 1) * 16;
    const unsigned BUFO = 128 * HPAD * 2;

    float acc[4][4][4];
    #pragma unroll
    for (int i = 0; i < 4; i++)
        #pragma unroll
        for (int j = 0; j < 4; j++)
            #pragma unroll
            for (int q = 0; q < 4; q++) acc[i][j][q] = 0.f;

    auto load_tile = [&](int kt, int buf) {
        int k0 = kt << 6;
        int ksl = 0, h0 = k0;
        if (MODE == 2) { ksl = k0 >> 10; h0 = k0 & (HDIM - 1); }
        __nv_bfloat16* Ad = As + buf * 128 * HPAD;
        __nv_bfloat16* Bd = Bs + buf * 128 * HPAD;
        #pragma unroll
        for (int i = 0; i < 4; i++) {
            int idx = tid + i * 256;
            int r = idx >> 3;
            int c8 = (idx & 7) << 3;
            const __nv_bfloat16* srcA;
            if (MODE == 2) {
                const __nv_bfloat16* Ab = (ksl == 2) ? Alo : A;
                srcA = Ab + (size_t)(row0 + r) * HDIM + h0 + c8;
            } else {
                srcA = A + (size_t)(row0 + r) * K + k0 + c8;
            }
            cp16(Ad + r * HPAD + c8, srcA, true);
            const __nv_bfloat16* srcB;
            if (MODE == 2) {
                const __nv_bfloat16* Wb = (ksl == 1) ? Wlo : W;
                srcB = Wb + (size_t)(col0 + r) * HDIM + h0 + c8;
            } else {
                srcB = W + (size_t)(col0 + r) * K + k0 + c8;
            }
            cp16(Bd + r * HPAD + c8, srcB, true);
        }
    };

    load_tile(0, 0); CP_COMMIT();
    if (KT > 1) load_tile(1, 1);
    CP_COMMIT();

    int buf = 0;
    for (int kt = 0; kt < KT; kt++) {
        CP_WAIT1();
        __syncthreads();
        if (kt + 2 < KT) load_tile(kt + 2, (buf + 2 >= 3) ? buf - 1 : buf + 2);
        CP_COMMIT();

        const unsigned aB = aBase + buf * BUFO;
        const unsigned bB = bBase + buf * BUFO;
        #pragma unroll
        for (int kk = 0; kk < 4; kk++) {
            unsigned af[4][4], bf[4][2];
            #pragma unroll
            for (int p = 0; p < 2; p++)
                ldsm_x4(bB + p * (16 * HPAD * 2) + kk * 32,
                        bf[2 * p][0], bf[2 * p][1], bf[2 * p + 1][0], bf[2 * p + 1][1]);
            #pragma unroll
            for (int mt = 0; mt < 4; mt++)
                ldsm_x4(aB + mt * (16 * HPAD * 2) + kk * 32,
                        af[mt][0], af[mt][1], af[mt][2], af[mt][3]);
            #pragma unroll
            for (int mt = 0; mt < 4; mt++)
                #pragma unroll
                for (int nt = 0; nt < 4; nt++)
                    mma_bf16(acc[mt][nt], af[mt], bf[nt]);
        }
        buf = (buf + 1 == 3) ? 0 : buf + 1;
    }

    #pragma unroll
    for (int mt = 0; mt < 4; mt++) {
        int r0 = row0 + wm * 64 + mt * 16 + g;
        int r1 = r0 + 8;
        #pragma unroll
        for (int nt = 0; nt < 4; nt++) {
            int c = col0 + wn * 32 + nt * 8 + 2 * t;
            float b0v = bias ? bias[c] : 0.f;
            float b1v = bias ? bias[c + 1] : 0.f;
            float v[4] = {acc[mt][nt][0] + b0v, acc[mt][nt][1] + b1v,
                          acc[mt][nt][2] + b0v, acc[mt][nt][3] + b1v};
            if (act == 1) {
                #pragma unroll
                for (int q = 0; q < 4; q++) v[q] = fmaxf(v[q], 0.f);
            }
            if (C) {
                *reinterpret_cast<float2*>(C + (size_t)r0 * ldc + c) = make_float2(v[0], v[1]);
                *reinterpret_cast<float2*>(C + (size_t)r1 * ldc + c) = make_float2(v[2], v[3]);
            }
            if (C2) {
                __nv_bfloat162 p0, p1;
                p0.x = __float2bfloat16_rn(v[0]); p0.y = __float2bfloat16_rn(v[1]);
                p1.x = __float2bfloat16_rn(v[2]); p1.y = __float2bfloat16_rn(v[3]);
                *reinterpret_cast<__nv_bfloat162*>(C2 + (size_t)r0 * ldc + c) = p0;
                *reinterpret_cast<__nv_bfloat162*>(C2 + (size_t)r1 * ldc + c) = p1;
            }
        }
    }
}

// =====================================================================
// mega prep: ONE launch. Flat grid, compile-time segment dispatch.
// segA: conv repack, block per (d, ho), smem-staged transpose (coalesced)
// segB-E: tf32 weight rounds; segF: w1 bf16 split; segG: w2 bf16 round;
// segH: zero usage; segI: prep_x + gate (block per token row).
// =====================================================================
#define Q0 3072                    // repack: block per (d, ho)
#define Q1 (Q0 + 512)              // wproj: 131072 f4
#define Q2 (Q1 + 3072)             // wout: 786432 f4
#define Q3 (Q2 + 512)              // wmap: 131072 f4
#define Q4 (Q3 + 512)              // wrp: 131072 f4
#define Q5 (Q4 + 1024)             // w1 split: 262144 f4
#define Q6 (Q5 + 4096)             // w2 round: 1,048,576 f4
#define Q7 (Q6 + 16)               // usage zero: 4096 floats
#define Q8 (Q7 + NTOK)             // prep_x_gate: block per token

__global__ void __launch_bounds__(256) mega_prep(
    const float* __restrict__ conv_w, float* __restrict__ convwt,
    const float* __restrict__ wproj, float* __restrict__ wprojt,
    const float* __restrict__ wout, float* __restrict__ woutt,
    const float* __restrict__ wmap, float* __restrict__ wmapt,
    const float* __restrict__ wrp, float* __restrict__ wrpt,
    const float* __restrict__ w1, __nv_bfloat16* __restrict__ w1hb,
    __nv_bfloat16* __restrict__ w1lb,
    const float* __restrict__ w2, __nv_bfloat16* __restrict__ w2b,
    float* __restrict__ usage,
    const float* __restrict__ x, const float* __restrict__ wg,
    const float* __restrict__ bg, float* __restrict__ xt,
    __nv_bfloat16* __restrict__ xhb, __nv_bfloat16* __restrict__ xlb,
    float* __restrict__ gates)
{
    __shared__ float stage[3 * HDIM];   // 12 KB: repack staging / reduce scratch
    int b = blockIdx.x;
    int tid = threadIdx.x;
    if (b < Q0) {
        // conv repack: src [d][ho][hi][k] row (3072 contiguous) -> dst [d][k][ho][hi]
        int d = b >> 10;
        int ho = b & (HDIM - 1);
        const float* src = conv_w + (size_t)b * 3 * HDIM;   // (d*1024+ho)*3072
        #pragma unroll
        for (int i = 0; i < 12; i++)
            stage[tid + i * 256] = src[tid + i * 256];
        __syncthreads();
        #pragma unroll
        for (int k = 0; k < 3; k++) {
            float* dst = convwt + (((size_t)(d * 3 + k)) * HDIM + ho) * HDIM;
            #pragma unroll
            for (int i = 0; i < 4; i++) {
                int hi = tid + i * 256;
                dst[hi] = round_tf32f(stage[hi * 3 + k]);   // stride-3 smem: conflict-free
            }
        }
    } else if (b < Q4) {
        const float* src; float* dst; int i;
        if (b < Q1)      { src = wproj; dst = wprojt; i = (b - Q0) * 256 + tid; }
        else if (b < Q2) { src = wout;  dst = woutt;  i = (b - Q1) * 256 + tid; }
        else if (b < Q3) { src = wmap;  dst = wmapt;  i = (b - Q2) * 256 + tid; }
        else             { src = wrp;   dst = wrpt;   i = (b - Q3) * 256 + tid; }
        float4 v = reinterpret_cast<const float4*>(src)[i];
        v.x = round_tf32f(v.x); v.y = round_tf32f(v.y);
        v.z = round_tf32f(v.z); v.w = round_tf32f(v.w);
        reinterpret_cast<float4*>(dst)[i] = v;
    } else if (b < Q5) {
        int i = (b - Q4) * 256 + tid;
        float4 v = reinterpret_cast<const float4*>(w1)[i];
        __nv_bfloat162 h0, h1, l0, l1;
        h0.x = __float2bfloat16_rn(v.x); l0.x = __float2bfloat16_rn(v.x - __bfloat162float(h0.x));
        h0.y = __float2bfloat16_rn(v.y); l0.y = __float2bfloat16_rn(v.y - __bfloat162float(h0.y));
        h1.x = __float2bfloat16_rn(v.z); l1.x = __float2bfloat16_rn(v.z - __bfloat162float(h1.x));
        h1.y = __float2bfloat16_rn(v.w); l1.y = __float2bfloat16_rn(v.w - __bfloat162float(h1.y));
        reinterpret_cast<__nv_bfloat162*>(w1hb)[2 * i] = h0;
        reinterpret_cast<__nv_bfloat162*>(w1hb)[2 * i + 1] = h1;
        reinterpret_cast<__nv_bfloat162*>(w1lb)[2 * i] = l0;
        reinterpret_cast<__nv_bfloat162*>(w1lb)[2 * i + 1] = l1;
    } else if (b < Q6) {
        int i = (b - Q5) * 256 + tid;
        float4 v = reinterpret_cast<const float4*>(w2)[i];
        __nv_bfloat162 p0, p1;
        p0.x = __float2bfloat16_rn(v.x); p0.y = __float2bfloat16_rn(v.y);
        p1.x = __float2bfloat16_rn(v.z); p1.y = __float2bfloat16_rn(v.w);
        reinterpret_cast<__nv_bfloat162*>(w2b)[2 * i] = p0;
        reinterpret_cast<__nv_bfloat162*>(w2b)[2 * i + 1] = p1;
    } else if (b < Q7) {
        int i = (b - Q6) * 256 + tid;
        if (i < PDIM) usage[i] = 0.f;
    } else {
        // prep_x + gate: block per token row
        int n = b - Q7;
        int i = n * (HDIM / 4) + tid;   // float4 index
        float4 v = reinterpret_cast<const float4*>(x)[i];
        float4 w = reinterpret_cast<const float4*>(wg)[tid];
        float4 r;
        r.x = round_tf32f(v.x); r.y = round_tf32f(v.y);
        r.z = round_tf32f(v.z); r.w = round_tf32f(v.w);
        reinterpret_cast<float4*>(xt)[i] = r;
        __nv_bfloat162 h0, h1, l0, l1;
        h0.x = __float2bfloat16_rn(v.x); l0.x = __float2bfloat16_rn(v.x - __bfloat162float(h0.x));
        h0.y = __float2bfloat16_rn(v.y); l0.y = __float2bfloat16_rn(v.y - __bfloat162float(h0.y));
        h1.x = __float2bfloat16_rn(v.z); l1.x = __float2bfloat16_rn(v.z - __bfloat162float(h1.x));
        h1.y = __float2bfloat16_rn(v.w); l1.y = __float2bfloat16_rn(v.w - __bfloat162float(h1.y));
        reinterpret_cast<__nv_bfloat162*>(xhb)[2 * i] = h0;
        reinterpret_cast<__nv_bfloat162*>(xhb)[2 * i + 1] = h1;
        reinterpret_cast<__nv_bfloat162*>(xlb)[2 * i] = l0;
        reinterpret_cast<__nv_bfloat162*>(xlb)[2 * i + 1] = l1;
        float s = v.x * w.x + v.y * w.y + v.z * w.z + v.w * w.w;
        float dot = block_reduce_sum(s, stage);
        if (tid == 0) gates[n] = 1.f / (1.f + expf(-(dot + bg[0])));
    }
}

// ---------------- top-8 (bf16 logits) + fp32 rescore + exact top-2 ----------------
__device__ __forceinline__ bool better(float va, int ia, float vb, int ib) {
    return (va > vb) || (va == vb && ia < ib);
}
__device__ __forceinline__ void ins2(float& v1, int& i1, float& v2, int& i2, float v, int i) {
    if (better(v, i, v1, i1)) { v2 = v1; i2 = i1; v1 = v; i1 = i; }
    else if (better(v, i, v2, i2)) { v2 = v; i2 = i; }
}

__global__ void __launch_bounds__(256) topk_rescore_kernel(
    const __nv_bfloat16* __restrict__ logits, const float* __restrict__ inter,
    const float* __restrict__ w2, const float* __restrict__ b2,
    const float* __restrict__ tpool, const float* __restrict__ temp_p,
    float* __restrict__ combined, float* __restrict__ usage)
{
    int gw = (blockIdx.x * blockDim.x + threadIdx.x) >> 5;
    int lane = threadIdx.x & 31;
    if (gw >= NTOK) return;
    float temp = fminf(fmaxf(*temp_p, 0.1f), 5.0f);
    float invt = 1.f / temp;

    const __nv_bfloat16* lrow = logits + (size_t)gw * PDIM;
    float tv[8]; int ti[8];
    #pragma unroll
    for (int k = 0; k < 8; k++) { tv[k] = -FLT_MAX; ti[k] = 0x3fffffff; }
    auto push = [&](float v, int j) {
        if (better(v, j, tv[7], ti[7])) {
            tv[7] = v; ti[7] = j;
            #pragma unroll
            for (int k = 7; k > 0; k--) {
                bool sw = better(tv[k], ti[k], tv[k - 1], ti[k - 1]);
                float av = sw ? tv[k] : tv[k - 1];
                float bv2 = sw ? tv[k - 1] : tv[k];
                int ai = sw ? ti[k] : ti[k - 1];
                int bi = sw ? ti[k - 1] : ti[k];
                tv[k - 1] = av; tv[k] = bv2; ti[k - 1] = ai; ti[k] = bi;
            }
        }
    };
    for (int j = lane * 2; j < PDIM; j += 64) {
        __nv_bfloat162 p = *reinterpret_cast<const __nv_bfloat162*>(lrow + j);
        push(fminf(fmaxf(__bfloat162float(p.x) * invt, -10.f), 10.f), j);
        push(fminf(fmaxf(__bfloat162float(p.y) * invt, -10.f), 10.f), j + 1);
    }

    int cand[8];
    #pragma unroll
    for (int r = 0; r < 8; r++) {
        float bvv = tv[0]; int bii = ti[0];
        #pragma unroll
        for (int off = 16; off; off >>= 1) {
            float ov = __shfl_xor_sync(0xffffffffu, bvv, off);
            int oi = __shfl_xor_sync(0xffffffffu, bii, off);
            if (better(ov, oi, bvv, bii)) { bvv = ov; bii = oi; }
        }
        cand[r] = bii;
        if (ti[0] == bii) {
            #pragma unroll
            for (int k = 0; k < 7; k++) { tv[k] = tv[k + 1]; ti[k] = ti[k + 1]; }
            tv[7] = -FLT_MAX; ti[7] = 0x3fffffff;
        }
    }

    const float* irow = inter + (size_t)gw * INTER_DIM;
    float xv[32];
    #pragma unroll
    for (int q = 0; q < 32; q++) xv[q] = irow[lane + q * 32];

    float v1 = -FLT_MAX, v2 = -FLT_MAX;
    int i1 = 0x3fffffff, i2 = 0x3fffffff;
    #pragma unroll
    for (int r = 0; r < 8; r++) {
        const float* wrow = w2 + (size_t)cand[r] * INTER_DIM;
        float s = 0.f;
        #pragma unroll
        for (int q = 0; q < 32; q++) s = fmaf(xv[q], wrow[lane + q * 32], s);
        #pragma unroll
        for (int off = 16; off; off >>= 1) s += __shfl_xor_sync(0xffffffffu, s, off);
        float v = fminf(fmaxf((s + b2[cand[r]]) * invt, -10.f), 10.f);
        ins2(v1, i1, v2, i2, v, cand[r]);
    }

    float e = expf(v2 - v1);
    float w1 = 1.f / (1.f + e);
    float w2s = e / (1.f + e);
    if (lane == 0) {
        atomicAdd(&usage[i1], w1);
        atomicAdd(&usage[i2], w2s);
    }
    const float* p1 = tpool + (size_t)i1 * DDIM;
    const float* p2 = tpool + (size_t)i2 * DDIM;
    float* dst = combined + (size_t)gw * (2 * DDIM) + DDIM;
    for (int d = lane; d < DDIM; d += 32)
        dst[d] = round_tf32f(w1 * p1[d] + w2s * p2[d]);
}

// ---------------- layernorm over D=512, writes rounded combined[:, :512] ----------------
__global__ void ln_kernel(const float* __restrict__ proj, const float* __restrict__ g,
                          const float* __restrict__ b, float* __restrict__ combined)
{
    __shared__ float sh[33];
    int n = blockIdx.x;
    const float* row = proj + (size_t)n * DDIM;
    float v[4];
    float s = 0.f;
    #pragma unroll
    for (int j = 0; j < 4; j++) { v[j] = row[threadIdx.x + j * 128]; s += v[j]; }
    float mean = block_reduce_sum(s, sh) * (1.f / DDIM);
    float q = 0.f;
    #pragma unroll
    for (int j = 0; j < 4; j++) { float d = v[j] - mean; q += d * d; }
    float var = block_reduce_sum(q, sh) * (1.f / DDIM);
    float rstd = rsqrtf(var + 1e-5f);
    float* dst = combined + (size_t)n * (2 * DDIM);
    #pragma unroll
    for (int j = 0; j < 4; j++) {
        int idx = threadIdx.x + j * 128;
        dst[idx] = round_tf32f((v[j] - mean) * rstd * g[idx] + b[idx]);
    }
}

// ---------------- diversity loss ----------------
__global__ void divloss_kernel(const float* __restrict__ usage, float* __restrict__ out) {
    __shared__ float sh[33];
    float s = 0.f;
    for (int j = threadIdx.x; j < PDIM; j += 1024) s += usage[j];
    float total = block_reduce_sum(s, sh);
    float inv = 1.f / (total + 1e-8f);
    float q = 0.f;
    const float ip = 1.f / (float)PDIM;
    for (int j = threadIdx.x; j < PDIM; j += 1024) {
        float f = usage[j] * inv - ip;
        q += f * f;
    }
    float qt = block_reduce_sum(q, sh);
    if (threadIdx.x == 0) out[0] = (qt / (float)PDIM) * 0.01f;
}

// ---------------- host launcher ----------------
extern "C" void kernel_launch(void* const* d_in, const int* in_sizes, int n_in,
                              void* d_out, int out_size)
{
    const float* x      = (const float*)d_in[0];
    const float* tpool  = (const float*)d_in[1];
    const float* w1     = (const float*)d_in[2];
    const float* b1     = (const float*)d_in[3];
    const float* w2     = (const float*)d_in[4];
    const float* b2     = (const float*)d_in[5];
    const float* temp   = (const float*)d_in[6];
    const float* wproj  = (const float*)d_in[7];
    const float* bproj  = (const float*)d_in[8];
    const float* ln_g   = (const float*)d_in[9];
    const float* ln_b   = (const float*)d_in[10];
    const float* wmap   = (const float*)d_in[11];
    const float* bmap   = (const float*)d_in[12];
    const float* conv_w = (const float*)d_in[13];
    const float* conv_b = (const float*)d_in[14];
    const float* wout   = (const float*)d_in[15];
    const float* bout   = (const float*)d_in[16];
    const float* wrp    = (const float*)d_in[17];
    const float* brp    = (const float*)d_in[18];
    const float* wg     = (const float*)d_in[19];
    const float* bg     = (const float*)d_in[20];
    float* out = (float*)d_out;

    float *inter, *concat, *local, *combined, *transf, *proj;
    float *convwt, *usage, *gates, *xt, *wprojt, *woutt, *wmapt, *wrpt;
    __nv_bfloat16 *logitsb, *xhb, *xlb, *w1hb, *w1lb, *w2b, *interb;
    cudaGetSymbolAddress((void**)&inter,    g_inter);
    cudaGetSymbolAddress((void**)&logitsb,  g_logitsb);
    cudaGetSymbolAddress((void**)&concat,   g_concat);
    cudaGetSymbolAddress((void**)&local,    g_local);
    cudaGetSymbolAddress((void**)&combined, g_combined);
    cudaGetSymbolAddress((void**)&transf,   g_transf);
    cudaGetSymbolAddress((void**)&proj,     g_proj);
    cudaGetSymbolAddress((void**)&convwt,   g_convwt);
    cudaGetSymbolAddress((void**)&usage,    g_usage);
    cudaGetSymbolAddress((void**)&gates,    g_gates);
    cudaGetSymbolAddress((void**)&xt,       g_xt);
    cudaGetSymbolAddress((void**)&wprojt,   g_wprojt);
    cudaGetSymbolAddress((void**)&woutt,    g_woutt);
    cudaGetSymbolAddress((void**)&wmapt,    g_wmapt);
    cudaGetSymbolAddress((void**)&wrpt,     g_wrpt);
    cudaGetSymbolAddress((void**)&xhb,      g_xhb);
    cudaGetSymbolAddress((void**)&xlb,      g_xlb);
    cudaGetSymbolAddress((void**)&w1hb,     g_w1hb);
    cudaGetSymbolAddress((void**)&w1lb,     g_w1lb);
    cudaGetSymbolAddress((void**)&w2b,      g_w2b);
    cudaGetSymbolAddress((void**)&interb,   g_interb);

    const int TF_SMEM = 6 * 128 * TFPAD * sizeof(float);          // 110592 B
    const int BF_SMEM = 6 * 128 * HPAD * sizeof(__nv_bfloat16);   // 110592 B
    cudaFuncSetAttribute(gemm_tf32<0>, cudaFuncAttributeMaxDynamicSharedMemorySize, TF_SMEM);
    cudaFuncSetAttribute(gemm_tf32<1>, cudaFuncAttributeMaxDynamicSharedMemorySize, TF_SMEM);
    cudaFuncSetAttribute(gemm_tf32<3>, cudaFuncAttributeMaxDynamicSharedMemorySize, TF_SMEM);
    cudaFuncSetAttribute(gemm_bf16k<0>, cudaFuncAttributeMaxDynamicSharedMemorySize, BF_SMEM);
    cudaFuncSetAttribute(gemm_bf16k<2>, cudaFuncAttributeMaxDynamicSharedMemorySize, BF_SMEM);

    // ---- prep: ONE launch (weights + x prep + gate + usage zero) ----
    mega_prep<<<Q8, 256>>>(conv_w, convwt, wproj, wprojt, wout, woutt,
                           wmap, wmapt, wrp, wrpt, w1, w1hb, w1lb,
                           w2, w2b, usage, x, wg, bg, xt, xhb, xlb, gates);

    // ---- router inter: 3xBF16 split, relu; dual write fp32 + bf16 ----
    gemm_bf16k<2><<<dim3(INTER_DIM / 128, NTOK / 128), 256, BF_SMEM>>>(
        xhb, xlb, w1hb, w1lb, b1, inter, interb, 3 * HDIM, INTER_DIM, 1);

    // ---- logits: single bf16, bf16 output (top-8 screen only) ----
    gemm_bf16k<0><<<dim3(PDIM / 128, NTOK / 128), 256, BF_SMEM>>>(
        interb, nullptr, w2b, nullptr, b2, nullptr, logitsb, INTER_DIM, PDIM, 0);

    topk_rescore_kernel<<<(NTOK * 32 + 255) / 256, 256>>>(
        logitsb, inter, w2, b2, tpool, temp, combined, usage);

    // ---- projected_x (tf32) -> LN -> combined[:, :512] ----
    gemm_tf32<0><<<dim3(DDIM / 128, NTOK / 128), 256, TF_SMEM>>>(
        xt, wprojt, bproj, proj, HDIM, DDIM, 0, 0, 0, nullptr, nullptr);
    ln_kernel<<<NTOK, 128>>>(proj, ln_g, ln_b, combined);

    // ---- dilated convs: single fused launch over blockIdx.z (dil = 1<<z) ----
    gemm_tf32<1><<<dim3(HDIM / 128, NTOK / 128, NDIL), 256, TF_SMEM>>>(
        xt, convwt, conv_b, concat, 3 * HDIM, 3 * HDIM, 0, 2, 1, nullptr, nullptr);

    // ---- local out (tf32) ----
    gemm_tf32<0><<<dim3(HDIM / 128, NTOK / 128), 256, TF_SMEM>>>(
        concat, woutt, bout, local, 3 * HDIM, HDIM, 0, 0, 0, nullptr, nullptr);

    // ---- transformation (rounded out) ----
    gemm_tf32<0><<<dim3(DDIM / 128, NTOK / 128), 256, TF_SMEM>>>(
        combined, wmapt, bmap, transf, 2 * DDIM, DDIM, 0, 0, 1, nullptr, nullptr);

    // ---- global out + gate mix fused: out = g*local + (1-g)*(transf@wrp^T + brp) ----
    gemm_tf32<3><<<dim3(HDIM / 128, NTOK / 128), 256, TF_SMEM>>>(
        transf, wrpt, brp, out, DDIM, HDIM, 0, 0, 0, gates, local);

    // diversity loss -> last output element
    if (out_size > NTOK * HDIM)
        divloss_kernel<<<1, 1024>>>(usage, out + (size_t)NTOK * HDIM);
}